// round 1
// baseline (speedup 1.0000x reference)
#include <cuda_runtime.h>
#include <math.h>

// Problem constants
#define HH     224
#define C_     192
#define WS     7
#define NPIX   49          // 7*7
#define HEADS  6
#define DH     32
#define NWIN   8192        // 8 * 32 * 32
#define STRIDE 196         // padded row stride (floats) for 192-wide tiles
#define ATT_W  14406       // 6*49*49 per window

// Shared memory layout (float offsets)
#define OFF_XW    0            // 49*196 = 9604   (aliased by att later)
#define OFF_YW    9604         // 49*196 = 9604
#define OFF_Q     19208        // 49*196          (aliased by ctx later)
#define OFF_K     28812        // 49*196          (aliased by final later)
#define OFF_V     38416        // 52*196 = 10192  (3 zero pad rows)
#define OFF_WT    48608        // 16*192 = 3072
#define OFF_LOGMW 51680        // 49
#define OFF_GOFF  51730        // 49 ints
#define SMEM_FLOATS 51792
// att alias: 6*49*52 = 15288 floats at offset 0 (fits in xw+yw = 19208)

__global__ __launch_bounds__(256, 1)
void fused_winattn(const float* __restrict__ x, const float* __restrict__ y,
                   const float* __restrict__ Wq, const float* __restrict__ Wk,
                   const float* __restrict__ Wv, const float* __restrict__ Wo,
                   float* __restrict__ out, float* __restrict__ att_out)
{
    extern __shared__ float sm[];
    float* s_xw    = sm + OFF_XW;
    float* s_yw    = sm + OFF_YW;
    float* s_att   = sm + OFF_XW;   // alias (valid after q,k,v GEMMs)
    float* s_q     = sm + OFF_Q;
    float* s_k     = sm + OFF_K;
    float* s_v     = sm + OFF_V;
    float* s_w     = sm + OFF_WT;
    float* s_logmw = sm + OFF_LOGMW;
    int*   s_goff  = (int*)(sm + OFF_GOFF);
    float* s_ctx   = s_q;           // alias after attention
    float* s_fin   = s_k;           // alias after attention

    const int tx = threadIdx.x;
    const int w  = blockIdx.x;
    const int b  = w >> 10;
    const int wr = (w >> 5) & 31;
    const int wc = w & 31;

    // ---------------- Phase 0: gather (with roll), mask, stage xw/yw ----------------
    {
        const int warp = tx >> 5, lane = tx & 31;
        for (int p = warp; p < NPIX; p += 8) {
            int i = p / 7, j = p - i * 7;
            int hs = wr * 7 + i + 3;  if (hs  >= HH) hs  -= HH;
            int ws2 = wc * 7 + j + 3; if (ws2 >= HH) ws2 -= HH;
            int goff = ((b * HH + hs) * HH + ws2) * C_;
            float xv[6];
            int cnt = 0;
            #pragma unroll
            for (int u = 0; u < 6; u++) {
                xv[u] = x[goff + lane + 32 * u];
                cnt += (xv[u] > 0.95f) ? 0 : 1;
            }
            #pragma unroll
            for (int o = 16; o; o >>= 1) cnt += __shfl_xor_sync(0xffffffffu, cnt, o);
            float mask = (float)cnt * (1.0f / 192.0f);
            #pragma unroll
            for (int u = 0; u < 6; u++) {
                s_xw[p * STRIDE + lane + 32 * u] = xv[u] * mask;
                s_yw[p * STRIDE + lane + 32 * u] = y[goff + lane + 32 * u];
            }
            if (lane == 0) {
                s_logmw[p] = logf(mask + 1e-6f);
                s_goff[p]  = goff;
            }
        }
    }
    __syncthreads();

    // ---------------- GEMM helper: out[49,192] = in[49,192] @ W[192,192] ----------------
    auto gemm = [&](const float* __restrict__ in, const float* __restrict__ Wg,
                    float* __restrict__ outp) {
        const int rt = tx >> 6;   // 0..3  (row group)
        const int ct = tx & 63;   // 0..63 (col thread)
        float acc[13][3];
        #pragma unroll
        for (int u = 0; u < 13; u++)
            #pragma unroll
            for (int jj = 0; jj < 3; jj++) acc[u][jj] = 0.0f;

        for (int k0 = 0; k0 < 192; k0 += 16) {
            __syncthreads();   // previous wtile fully consumed
            #pragma unroll
            for (int t = 0; t < 12; t++) {
                int e   = tx + t * 256;
                int row = e / 192;
                int col = e - row * 192;
                s_w[e] = Wg[(k0 + row) * 192 + col];
            }
            __syncthreads();
            #pragma unroll
            for (int kk = 0; kk < 16; kk++) {
                float a[13];
                #pragma unroll
                for (int u = 0; u < 13; u++)
                    a[u] = in[(rt + 4 * u) * STRIDE + k0 + kk];
                float wv[3];
                #pragma unroll
                for (int jj = 0; jj < 3; jj++)
                    wv[jj] = s_w[kk * 192 + ct + 64 * jj];
                #pragma unroll
                for (int u = 0; u < 13; u++)
                    #pragma unroll
                    for (int jj = 0; jj < 3; jj++)
                        acc[u][jj] = fmaf(a[u], wv[jj], acc[u][jj]);
            }
        }
        #pragma unroll
        for (int u = 0; u < 13; u++) {
            int r = rt + 4 * u;
            if (r < NPIX) {
                #pragma unroll
                for (int jj = 0; jj < 3; jj++)
                    outp[r * STRIDE + ct + 64 * jj] = acc[u][jj];
            }
        }
        __syncthreads();
    };

    // ---------------- Phase 1: projections ----------------
    gemm(s_xw, Wq, s_q);
    gemm(s_yw, Wk, s_k);
    gemm(s_yw, Wv, s_v);

    // zero v pad rows 49..51 (needed for padded att@v)
    for (int e = tx; e < 3 * STRIDE; e += 256) s_v[NPIX * STRIDE + e] = 0.0f;

    // ---------------- Phase 2: logits + softmax (one thread per (h,n) row) ----------------
    // NOTE: writes s_att which aliases s_xw/s_yw (both dead now)
    for (int idx = tx; idx < HEADS * NPIX; idx += 256) {
        int h = idx / NPIX;
        int n = idx - h * NPIX;
        const float4* q4p = (const float4*)(s_q + n * STRIDE + h * DH);
        float4 q4[8];
        #pragma unroll
        for (int u = 0; u < 8; u++) q4[u] = q4p[u];

        float* arow = s_att + (h * NPIX + n) * 52;
        float mx = -1e30f;
        for (int m = 0; m < NPIX; m++) {
            const float4* k4 = (const float4*)(s_k + m * STRIDE + h * DH);
            float acc = 0.0f;
            #pragma unroll
            for (int u = 0; u < 8; u++) {
                float4 kv = k4[u];
                acc = fmaf(q4[u].x, kv.x, acc);
                acc = fmaf(q4[u].y, kv.y, acc);
                acc = fmaf(q4[u].z, kv.z, acc);
                acc = fmaf(q4[u].w, kv.w, acc);
            }
            float l = acc * 0.17677669529663687f + s_logmw[m];
            arow[m] = l;
            mx = fmaxf(mx, l);
        }
        float sum = 0.0f;
        for (int m = 0; m < NPIX; m++) {
            float e = __expf(arow[m] - mx);
            arow[m] = e;
            sum += e;
        }
        float inv = 1.0f / sum;
        for (int m = 0; m < NPIX; m++) arow[m] *= inv;
        arow[49] = 0.0f; arow[50] = 0.0f; arow[51] = 0.0f;  // pad for float4 att@v
    }
    __syncthreads();

    // ---------------- Phase 2.5: write att to gmem (coalesced) ----------------
    {
        float* attg = att_out + (size_t)w * ATT_W;
        for (int e = tx; e < ATT_W; e += 256) {
            int t = e / NPIX;           // t = h*49 + n
            int m = e - t * NPIX;
            attg[e] = s_att[t * 52 + m];
        }
    }

    // ---------------- Phase 3: ctx[n, c] = sum_m att[h,n,m] * v[m,c]  (h = c/32) ----------------
    if (tx < C_) {
        const int c = tx;
        const int h = c >> 5;
        float acc[NPIX];
        #pragma unroll
        for (int n = 0; n < NPIX; n++) acc[n] = 0.0f;
        for (int m0 = 0; m0 < 52; m0 += 4) {
            float v0 = s_v[(m0 + 0) * STRIDE + c];
            float v1 = s_v[(m0 + 1) * STRIDE + c];
            float v2 = s_v[(m0 + 2) * STRIDE + c];
            float v3 = s_v[(m0 + 3) * STRIDE + c];
            const float* ab = s_att + h * NPIX * 52 + m0;
            #pragma unroll 7
            for (int n = 0; n < NPIX; n++) {
                float4 a4 = *(const float4*)(ab + n * 52);
                acc[n] = fmaf(a4.x, v0, acc[n]);
                acc[n] = fmaf(a4.y, v1, acc[n]);
                acc[n] = fmaf(a4.z, v2, acc[n]);
                acc[n] = fmaf(a4.w, v3, acc[n]);
            }
        }
        #pragma unroll
        for (int n = 0; n < NPIX; n++) s_ctx[n * STRIDE + c] = acc[n];
    }
    __syncthreads();

    // ---------------- Phase 4: final = ctx @ Wo ----------------
    gemm(s_ctx, Wo, s_fin);

    // ---------------- Phase 5: scatter to out (roll-back == same index map) ----------------
    for (int e = tx; e < NPIX * C_; e += 256) {
        int p = e / C_;
        int c = e - p * C_;
        out[s_goff[p] + c] = s_fin[p * STRIDE + c];
    }
}

extern "C" void kernel_launch(void* const* d_in, const int* in_sizes, int n_in,
                              void* d_out, int out_size)
{
    const float* x  = (const float*)d_in[0];
    const float* y  = (const float*)d_in[1];
    const float* Wq = (const float*)d_in[2];
    const float* Wk = (const float*)d_in[3];
    const float* Wv = (const float*)d_in[4];
    const float* Wo = (const float*)d_in[5];

    float* out = (float*)d_out;                       // [8,224,224,192]
    float* att = out + (size_t)8 * 224 * 224 * 192;   // [8192,6,49,49]

    size_t smem = (size_t)SMEM_FLOATS * sizeof(float);
    cudaFuncSetAttribute(fused_winattn,
                         cudaFuncAttributeMaxDynamicSharedMemorySize, (int)smem);
    fused_winattn<<<NWIN, 256, smem>>>(x, y, Wq, Wk, Wv, Wo, out, att);
}

// round 2
// speedup vs baseline: 1.4492x; 1.4492x over previous
#include <cuda_runtime.h>
#include <math.h>

// Problem constants
#define HH     224
#define C_     192
#define NPIX   49          // 7*7
#define HEADS  6
#define DH     32
#define NWIN   8192        // 8 * 32 * 32
#define STRIDE 196         // padded row stride (floats)
#define ATT_W  14406       // 6*49*49 per window

// Shared memory layout (float offsets)
#define OFF_XW    0            // 49*196 = 9604   (aliased by att later)
#define OFF_YW    9604         // 49*196
#define OFF_Q     19208        // 49*196          (aliased by ctx later)
#define OFF_K     28812        // 49*196          (aliased by final later)
#define OFF_V     38416        // 52*196 = 10192  (3 zero pad rows)
#define OFF_WT    48608        // 2*16*192 = 6144 (double buffered)
#define OFF_LOGMW 54752        // 49 (+pad)
#define OFF_GOFF  54816        // 49 ints
#define SMEM_FLOATS 54880
// att alias: 6*49*52 = 15288 floats at offset 0 (fits under OFF_Q)

typedef unsigned long long ull;

__device__ __forceinline__ ull pack2(float a, float b) {
    ull r; asm("mov.b64 %0, {%1,%2};" : "=l"(r) : "f"(a), "f"(b)); return r;
}
__device__ __forceinline__ float2 unpack2(ull v) {
    float2 r; asm("mov.b64 {%0,%1}, %2;" : "=f"(r.x), "=f"(r.y) : "l"(v)); return r;
}
// packed fp32x2 FMA (SASS FFMA2) — only reachable via PTX
__device__ __forceinline__ void fma2(ull &d, ull a, ull b) {
    asm("fma.rn.f32x2 %0, %1, %2, %0;" : "+l"(d) : "l"(a), "l"(b));
}

__global__ __launch_bounds__(256, 1)
void fused_winattn(const float* __restrict__ x, const float* __restrict__ y,
                   const float* __restrict__ Wq, const float* __restrict__ Wk,
                   const float* __restrict__ Wv, const float* __restrict__ Wo,
                   float* __restrict__ out, float* __restrict__ att_out)
{
    extern __shared__ float sm[];
    float* s_xw    = sm + OFF_XW;
    float* s_yw    = sm + OFF_YW;
    float* s_att   = sm + OFF_XW;   // alias (valid after q,k,v GEMMs)
    float* s_q     = sm + OFF_Q;
    float* s_k     = sm + OFF_K;
    float* s_v     = sm + OFF_V;
    float* s_w     = sm + OFF_WT;
    float* s_logmw = sm + OFF_LOGMW;
    int*   s_goff  = (int*)(sm + OFF_GOFF);
    float* s_ctx   = s_q;           // alias after attention
    float* s_fin   = s_k;           // alias after attention

    const int tx = threadIdx.x;
    const int w  = blockIdx.x;
    const int b  = w >> 10;
    const int wr = (w >> 5) & 31;
    const int wc = w & 31;

    // ---------------- Phase 0: gather (with roll), mask, stage xw/yw ----------------
    {
        const int warp = tx >> 5, lane = tx & 31;
        for (int p = warp; p < NPIX; p += 8) {
            int i = p / 7, j = p - i * 7;
            int hs = wr * 7 + i + 3;  if (hs  >= HH) hs  -= HH;
            int ws2 = wc * 7 + j + 3; if (ws2 >= HH) ws2 -= HH;
            int goff = ((b * HH + hs) * HH + ws2) * C_;
            float xv[6];
            int cnt = 0;
            #pragma unroll
            for (int u = 0; u < 6; u++) {
                xv[u] = x[goff + lane + 32 * u];
                cnt += (xv[u] > 0.95f) ? 0 : 1;
            }
            #pragma unroll
            for (int o = 16; o; o >>= 1) cnt += __shfl_xor_sync(0xffffffffu, cnt, o);
            float mask = (float)cnt * (1.0f / 192.0f);
            #pragma unroll
            for (int u = 0; u < 6; u++) {
                s_xw[p * STRIDE + lane + 32 * u] = xv[u] * mask;
                s_yw[p * STRIDE + lane + 32 * u] = y[goff + lane + 32 * u];
            }
            if (lane == 0) {
                s_logmw[p] = logf(mask + 1e-6f);
                s_goff[p]  = goff;
            }
        }
    }
    __syncthreads();

    // ---------------- GEMM: out[49,192] = in[49,192] @ W[192,192], FFMA2 ----------------
    // 256 threads: rt = tx>>5 (8 row groups), ct = tx&31 (32 col-pair threads),
    // each thread: rows rt+8u (u<7), column pairs 2*ct + 64*jj (jj<3).
    auto gemm = [&](const float* __restrict__ in, const float* __restrict__ Wg,
                    float* __restrict__ outp) {
        const int rt = tx >> 5;
        const int ct = tx & 31;
        ull acc[7][3];
        #pragma unroll
        for (int u = 0; u < 7; u++)
            #pragma unroll
            for (int jj = 0; jj < 3; jj++) acc[u][jj] = 0ull;

        // prefetch weight tile 0 (16 rows x 192 cols = 3072 floats, flat copy)
        float4 wreg[3];
        #pragma unroll
        for (int i = 0; i < 3; i++)
            wreg[i] = *(const float4*)(Wg + (tx + 256 * i) * 4);
        #pragma unroll
        for (int i = 0; i < 3; i++)
            *(float4*)(s_w + (tx + 256 * i) * 4) = wreg[i];
        __syncthreads();

        for (int t = 0; t < 12; t++) {
            const float* wb = s_w + (t & 1) * 3072;
            if (t < 11) {   // prefetch next tile into regs (overlaps compute)
                #pragma unroll
                for (int i = 0; i < 3; i++)
                    wreg[i] = *(const float4*)(Wg + (t + 1) * 3072 + (tx + 256 * i) * 4);
            }
            const int k0 = t * 16;
            #pragma unroll
            for (int kb = 0; kb < 4; kb++) {
                float4 a4[7];
                #pragma unroll
                for (int u = 0; u < 7; u++)
                    a4[u] = *(const float4*)(in + (rt + 8 * u) * STRIDE + k0 + 4 * kb);
                #pragma unroll
                for (int kk = 0; kk < 4; kk++) {
                    ull wv[3];
                    #pragma unroll
                    for (int jj = 0; jj < 3; jj++)
                        wv[jj] = *(const ull*)(wb + (4 * kb + kk) * 192 + 2 * ct + 64 * jj);
                    #pragma unroll
                    for (int u = 0; u < 7; u++) {
                        float av = (kk == 0) ? a4[u].x : (kk == 1) ? a4[u].y
                                 : (kk == 2) ? a4[u].z : a4[u].w;
                        ull ad = pack2(av, av);
                        #pragma unroll
                        for (int jj = 0; jj < 3; jj++)
                            fma2(acc[u][jj], ad, wv[jj]);
                    }
                }
            }
            if (t < 11) {
                #pragma unroll
                for (int i = 0; i < 3; i++)
                    *(float4*)(s_w + ((t + 1) & 1) * 3072 + (tx + 256 * i) * 4) = wreg[i];
            }
            __syncthreads();
        }
        #pragma unroll
        for (int u = 0; u < 7; u++) {
            int r = rt + 8 * u;
            if (r < NPIX) {
                #pragma unroll
                for (int jj = 0; jj < 3; jj++)
                    *(float2*)(outp + r * STRIDE + 2 * ct + 64 * jj) = unpack2(acc[u][jj]);
            }
        }
        __syncthreads();
    };

    // ---------------- Phase 1: projections ----------------
    gemm(s_xw, Wq, s_q);
    gemm(s_yw, Wk, s_k);
    gemm(s_yw, Wv, s_v);

    // zero v pad rows 49..51 (for padded att@v)
    for (int e = tx; e < 3 * STRIDE; e += 256) s_v[NPIX * STRIDE + e] = 0.0f;

    // ---------------- Phase 2: logits + softmax (one thread per (h,n) row) ----------------
    for (int idx = tx; idx < HEADS * NPIX; idx += 256) {
        int h = idx / NPIX;
        int n = idx - h * NPIX;
        const ull* q2 = (const ull*)(s_q + n * STRIDE + h * DH);
        ull qr[16];
        #pragma unroll
        for (int u = 0; u < 16; u++) qr[u] = q2[u];

        float* arow = s_att + (h * NPIX + n) * 52;
        float mx = -1e30f;
        for (int m = 0; m < NPIX; m++) {
            const ull* k2 = (const ull*)(s_k + m * STRIDE + h * DH);
            ull acc = 0ull;
            #pragma unroll
            for (int u = 0; u < 16; u++) fma2(acc, qr[u], k2[u]);
            float2 p = unpack2(acc);
            float l = (p.x + p.y) * 0.17677669529663687f + s_logmw[m];
            arow[m] = l;
            mx = fmaxf(mx, l);
        }
        float sum = 0.0f;
        for (int m = 0; m < NPIX; m++) {
            float e = __expf(arow[m] - mx);
            arow[m] = e;
            sum += e;
        }
        float inv = 1.0f / sum;
        for (int m = 0; m < NPIX; m++) arow[m] *= inv;
        arow[49] = 0.0f; arow[50] = 0.0f; arow[51] = 0.0f;  // pad
    }
    __syncthreads();

    // ---------------- Phase 2.5: write att to gmem (coalesced) ----------------
    {
        float* attg = att_out + (size_t)w * ATT_W;
        for (int e = tx; e < ATT_W; e += 256) {
            int t = e / NPIX;           // t = h*49 + n
            int m = e - t * NPIX;
            attg[e] = s_att[t * 52 + m];
        }
    }

    // ---------------- Phase 3: ctx[n,c] = sum_m att[h,n,m] * v[m,c]  (packed pairs) ----------------
    if (tx < 192) {
        const int cp  = tx % 96;           // column pair index, cols 2cp, 2cp+1
        const int seg = tx / 96;
        const int n0  = seg * 25;
        const int nn  = seg ? 24 : 25;
        const int h   = cp >> 4;           // (2cp)/32
        ull acc[25];
        #pragma unroll
        for (int n = 0; n < 25; n++) acc[n] = 0ull;
        for (int m0 = 0; m0 < 52; m0 += 4) {
            ull v2[4];
            #pragma unroll
            for (int i = 0; i < 4; i++)
                v2[i] = *(const ull*)(s_v + (m0 + i) * STRIDE + 2 * cp);
            #pragma unroll
            for (int n = 0; n < 25; n++) {
                if (n < nn) {
                    float4 a4 = *(const float4*)(s_att + (h * NPIX + n0 + n) * 52 + m0);
                    fma2(acc[n], pack2(a4.x, a4.x), v2[0]);
                    fma2(acc[n], pack2(a4.y, a4.y), v2[1]);
                    fma2(acc[n], pack2(a4.z, a4.z), v2[2]);
                    fma2(acc[n], pack2(a4.w, a4.w), v2[3]);
                }
            }
        }
        #pragma unroll
        for (int n = 0; n < 25; n++)
            if (n < nn)
                *(float2*)(s_ctx + (n0 + n) * STRIDE + 2 * cp) = unpack2(acc[n]);
    }
    __syncthreads();

    // ---------------- Phase 4: final = ctx @ Wo ----------------
    gemm(s_ctx, Wo, s_fin);

    // ---------------- Phase 5: scatter to out (roll-back == same index map) ----------------
    for (int idx = tx; idx < NPIX * 48; idx += 256) {
        int p  = idx / 48;
        int c4 = idx - p * 48;
        *(float4*)(out + s_goff[p] + 4 * c4) = *(const float4*)(s_fin + p * STRIDE + 4 * c4);
    }
}

extern "C" void kernel_launch(void* const* d_in, const int* in_sizes, int n_in,
                              void* d_out, int out_size)
{
    const float* x  = (const float*)d_in[0];
    const float* y  = (const float*)d_in[1];
    const float* Wq = (const float*)d_in[2];
    const float* Wk = (const float*)d_in[3];
    const float* Wv = (const float*)d_in[4];
    const float* Wo = (const float*)d_in[5];

    float* out = (float*)d_out;                       // [8,224,224,192]
    float* att = out + (size_t)8 * 224 * 224 * 192;   // [8192,6,49,49]

    size_t smem = (size_t)SMEM_FLOATS * sizeof(float);
    cudaFuncSetAttribute(fused_winattn,
                         cudaFuncAttributeMaxDynamicSharedMemorySize, (int)smem);
    fused_winattn<<<NWIN, 256, smem>>>(x, y, Wq, Wk, Wv, Wo, out, att);
}

// round 3
// speedup vs baseline: 1.4498x; 1.0004x over previous
#include <cuda_runtime.h>
#include <math.h>

// Problem constants
#define HH     224
#define C_     192
#define NPIX   49          // 7*7
#define HEADS  6
#define DH     32
#define NWIN   8192        // 8 * 32 * 32
#define STRIDE 196         // padded row stride (floats)
#define ATT_W  14406       // 6*49*49 per window

// Shared memory layout (float offsets)
#define OFF_XW    0            // 49*196 = 9604   (aliased by att later)
#define OFF_YW    9604         // 49*196
#define OFF_Q     19208        // 49*196          (aliased by ctx later)
#define OFF_K     28812        // 49*196          (aliased by final later)
#define OFF_V     38416        // 52*196 = 10192  (3 zero pad rows)
#define OFF_WT    48608        // 2*16*192 = 6144 (double buffered)
#define OFF_LOGMW 54752        // 49 (+pad)
#define OFF_GOFF  54816        // 49 ints
#define SMEM_FLOATS 54880
// att alias: 6*49*52 = 15288 floats at offset 0 (fits under OFF_Q)

typedef unsigned long long ull;

__device__ __forceinline__ ull pack2(float a, float b) {
    ull r; asm("mov.b64 %0, {%1,%2};" : "=l"(r) : "f"(a), "f"(b)); return r;
}
__device__ __forceinline__ float2 unpack2(ull v) {
    float2 r; asm("mov.b64 {%0,%1}, %2;" : "=f"(r.x), "=f"(r.y) : "l"(v)); return r;
}
// packed fp32x2 FMA (SASS FFMA2) — only reachable via PTX
__device__ __forceinline__ void fma2(ull &d, ull a, ull b) {
    asm("fma.rn.f32x2 %0, %1, %2, %0;" : "+l"(d) : "l"(a), "l"(b));
}

__global__ __launch_bounds__(256, 1)
void fused_winattn(const float* __restrict__ x, const float* __restrict__ y,
                   const float* __restrict__ Wq, const float* __restrict__ Wk,
                   const float* __restrict__ Wv, const float* __restrict__ Wo,
                   float* __restrict__ out, float* __restrict__ att_out)
{
    extern __shared__ float sm[];
    float* s_xw    = sm + OFF_XW;
    float* s_yw    = sm + OFF_YW;
    float* s_att   = sm + OFF_XW;   // alias (valid after q,k,v GEMMs)
    float* s_q     = sm + OFF_Q;
    float* s_k     = sm + OFF_K;
    float* s_v     = sm + OFF_V;
    float* s_w     = sm + OFF_WT;
    float* s_logmw = sm + OFF_LOGMW;
    int*   s_goff  = (int*)(sm + OFF_GOFF);
    float* s_ctx   = s_q;           // alias after attention
    float* s_fin   = s_k;           // alias after attention

    const int tx = threadIdx.x;
    const int w  = blockIdx.x;
    const int b  = w >> 10;
    const int wr = (w >> 5) & 31;
    const int wc = w & 31;

    // ---------------- Phase 0: gather (with roll), mask, stage xw/yw ----------------
    {
        const int warp = tx >> 5, lane = tx & 31;
        for (int p = warp; p < NPIX; p += 8) {
            int i = p / 7, j = p - i * 7;
            int hs = wr * 7 + i + 3;  if (hs  >= HH) hs  -= HH;
            int ws2 = wc * 7 + j + 3; if (ws2 >= HH) ws2 -= HH;
            int goff = ((b * HH + hs) * HH + ws2) * C_;
            float xv[6];
            int cnt = 0;
            #pragma unroll
            for (int u = 0; u < 6; u++) {
                xv[u] = x[goff + lane + 32 * u];
                cnt += (xv[u] > 0.95f) ? 0 : 1;
            }
            #pragma unroll
            for (int o = 16; o; o >>= 1) cnt += __shfl_xor_sync(0xffffffffu, cnt, o);
            float mask = (float)cnt * (1.0f / 192.0f);
            #pragma unroll
            for (int u = 0; u < 6; u++) {
                s_xw[p * STRIDE + lane + 32 * u] = xv[u] * mask;
                s_yw[p * STRIDE + lane + 32 * u] = y[goff + lane + 32 * u];
            }
            if (lane == 0) {
                s_logmw[p] = logf(mask + 1e-6f);
                s_goff[p]  = goff;
            }
        }
    }
    __syncthreads();

    // ---------------- GEMM: out[49,192] = in[49,192] @ W[192,192], FFMA2 ----------------
    // 256 threads: rt = tx>>5 (8 row groups), ct = tx&31 (32 col-pair threads),
    // each thread: rows rt+8u (u<7), column pairs 2*ct + 64*jj (jj<3).
    auto gemm = [&](const float* __restrict__ in, const float* __restrict__ Wg,
                    float* __restrict__ outp) {
        const int rt = tx >> 5;
        const int ct = tx & 31;
        ull acc[7][3];
        #pragma unroll
        for (int u = 0; u < 7; u++)
            #pragma unroll
            for (int jj = 0; jj < 3; jj++) acc[u][jj] = 0ull;

        // prefetch weight tile 0 (16 rows x 192 cols = 3072 floats, flat copy)
        float4 wreg[3];
        #pragma unroll
        for (int i = 0; i < 3; i++)
            wreg[i] = *(const float4*)(Wg + (tx + 256 * i) * 4);
        #pragma unroll
        for (int i = 0; i < 3; i++)
            *(float4*)(s_w + (tx + 256 * i) * 4) = wreg[i];
        __syncthreads();

        for (int t = 0; t < 12; t++) {
            const float* wb = s_w + (t & 1) * 3072;
            if (t < 11) {   // prefetch next tile into regs (overlaps compute)
                #pragma unroll
                for (int i = 0; i < 3; i++)
                    wreg[i] = *(const float4*)(Wg + (t + 1) * 3072 + (tx + 256 * i) * 4);
            }
            const int k0 = t * 16;
            #pragma unroll
            for (int kb = 0; kb < 4; kb++) {
                float4 a4[7];
                #pragma unroll
                for (int u = 0; u < 7; u++)
                    a4[u] = *(const float4*)(in + (rt + 8 * u) * STRIDE + k0 + 4 * kb);
                #pragma unroll
                for (int kk = 0; kk < 4; kk++) {
                    ull wv[3];
                    #pragma unroll
                    for (int jj = 0; jj < 3; jj++)
                        wv[jj] = *(const ull*)(wb + (4 * kb + kk) * 192 + 2 * ct + 64 * jj);
                    #pragma unroll
                    for (int u = 0; u < 7; u++) {
                        float av = (kk == 0) ? a4[u].x : (kk == 1) ? a4[u].y
                                 : (kk == 2) ? a4[u].z : a4[u].w;
                        ull ad = pack2(av, av);
                        #pragma unroll
                        for (int jj = 0; jj < 3; jj++)
                            fma2(acc[u][jj], ad, wv[jj]);
                    }
                }
            }
            if (t < 11) {
                #pragma unroll
                for (int i = 0; i < 3; i++)
                    *(float4*)(s_w + ((t + 1) & 1) * 3072 + (tx + 256 * i) * 4) = wreg[i];
            }
            __syncthreads();
        }
        #pragma unroll
        for (int u = 0; u < 7; u++) {
            int r = rt + 8 * u;
            if (r < NPIX) {
                #pragma unroll
                for (int jj = 0; jj < 3; jj++)
                    *(float2*)(outp + r * STRIDE + 2 * ct + 64 * jj) = unpack2(acc[u][jj]);
            }
        }
        __syncthreads();
    };

    // ---------------- Phase 1: projections ----------------
    gemm(s_xw, Wq, s_q);
    gemm(s_yw, Wk, s_k);
    gemm(s_yw, Wv, s_v);

    // zero v pad rows 49..51 (for padded att@v)
    for (int e = tx; e < 3 * STRIDE; e += 256) s_v[NPIX * STRIDE + e] = 0.0f;

    // ---------------- Phase 2: logits + softmax (one thread per (h,n) row) ----------------
    for (int idx = tx; idx < HEADS * NPIX; idx += 256) {
        int h = idx / NPIX;
        int n = idx - h * NPIX;
        const ull* q2 = (const ull*)(s_q + n * STRIDE + h * DH);
        ull qr[16];
        #pragma unroll
        for (int u = 0; u < 16; u++) qr[u] = q2[u];

        float* arow = s_att + (h * NPIX + n) * 52;
        float mx = -1e30f;
        for (int m = 0; m < NPIX; m++) {
            const ull* k2 = (const ull*)(s_k + m * STRIDE + h * DH);
            ull acc = 0ull;
            #pragma unroll
            for (int u = 0; u < 16; u++) fma2(acc, qr[u], k2[u]);
            float2 p = unpack2(acc);
            float l = (p.x + p.y) * 0.17677669529663687f + s_logmw[m];
            arow[m] = l;
            mx = fmaxf(mx, l);
        }
        float sum = 0.0f;
        for (int m = 0; m < NPIX; m++) {
            float e = __expf(arow[m] - mx);
            arow[m] = e;
            sum += e;
        }
        float inv = 1.0f / sum;
        for (int m = 0; m < NPIX; m++) arow[m] *= inv;
        arow[49] = 0.0f; arow[50] = 0.0f; arow[51] = 0.0f;  // pad
    }
    __syncthreads();

    // ---------------- Phase 2.5: write att to gmem (coalesced) ----------------
    {
        float* attg = att_out + (size_t)w * ATT_W;
        for (int e = tx; e < ATT_W; e += 256) {
            int t = e / NPIX;           // t = h*49 + n
            int m = e - t * NPIX;
            attg[e] = s_att[t * 52 + m];
        }
    }

    // ---------------- Phase 3: ctx[n,c] = sum_m att[h,n,m] * v[m,c]  (packed pairs) ----------------
    if (tx < 192) {
        const int cp  = tx % 96;           // column pair index, cols 2cp, 2cp+1
        const int seg = tx / 96;
        const int n0  = seg * 25;
        const int nn  = seg ? 24 : 25;
        const int h   = cp >> 4;           // (2cp)/32
        ull acc[25];
        #pragma unroll
        for (int n = 0; n < 25; n++) acc[n] = 0ull;
        for (int m0 = 0; m0 < 52; m0 += 4) {
            ull v2[4];
            #pragma unroll
            for (int i = 0; i < 4; i++)
                v2[i] = *(const ull*)(s_v + (m0 + i) * STRIDE + 2 * cp);
            #pragma unroll
            for (int n = 0; n < 25; n++) {
                if (n < nn) {
                    float4 a4 = *(const float4*)(s_att + (h * NPIX + n0 + n) * 52 + m0);
                    fma2(acc[n], pack2(a4.x, a4.x), v2[0]);
                    fma2(acc[n], pack2(a4.y, a4.y), v2[1]);
                    fma2(acc[n], pack2(a4.z, a4.z), v2[2]);
                    fma2(acc[n], pack2(a4.w, a4.w), v2[3]);
                }
            }
        }
        #pragma unroll
        for (int n = 0; n < 25; n++)
            if (n < nn)
                *(float2*)(s_ctx + (n0 + n) * STRIDE + 2 * cp) = unpack2(acc[n]);
    }
    __syncthreads();

    // ---------------- Phase 4: final = ctx @ Wo ----------------
    gemm(s_ctx, Wo, s_fin);

    // ---------------- Phase 5: scatter to out (roll-back == same index map) ----------------
    for (int idx = tx; idx < NPIX * 48; idx += 256) {
        int p  = idx / 48;
        int c4 = idx - p * 48;
        *(float4*)(out + s_goff[p] + 4 * c4) = *(const float4*)(s_fin + p * STRIDE + 4 * c4);
    }
}

extern "C" void kernel_launch(void* const* d_in, const int* in_sizes, int n_in,
                              void* d_out, int out_size)
{
    const float* x  = (const float*)d_in[0];
    const float* y  = (const float*)d_in[1];
    const float* Wq = (const float*)d_in[2];
    const float* Wk = (const float*)d_in[3];
    const float* Wv = (const float*)d_in[4];
    const float* Wo = (const float*)d_in[5];

    float* out = (float*)d_out;                       // [8,224,224,192]
    float* att = out + (size_t)8 * 224 * 224 * 192;   // [8192,6,49,49]

    size_t smem = (size_t)SMEM_FLOATS * sizeof(float);
    cudaFuncSetAttribute(fused_winattn,
                         cudaFuncAttributeMaxDynamicSharedMemorySize, (int)smem);
    fused_winattn<<<NWIN, 256, smem>>>(x, y, Wq, Wk, Wv, Wo, out, att);
}

// round 4
// speedup vs baseline: 1.4511x; 1.0009x over previous
#include <cuda_runtime.h>
#include <math.h>

// Problem constants
#define HH     224
#define C_     192
#define NPIX   49          // 7*7
#define HEADS  6
#define DH     32
#define NWIN   8192        // 8 * 32 * 32
#define STRIDE 196         // padded row stride (floats)
#define ATT_W  14406       // 6*49*49 per window

// Shared memory layout (float offsets)
#define OFF_XW    0            // 49*196 = 9604   (aliased by att later)
#define OFF_YW    9604         // 49*196
#define OFF_Q     19208        // 49*196          (aliased by ctx later)
#define OFF_K     28812        // 49*196          (aliased by final later)
#define OFF_V     38416        // 52*196 = 10192  (3 zero pad rows)
#define OFF_WT    48608        // 2*16*192 = 6144 (double buffered)
#define OFF_LOGMW 54752        // 49 (+pad)
#define OFF_GOFF  54816        // 49 ints
#define SMEM_FLOATS 54880
// att alias: 6*49*52 = 15288 floats at offset 0 (fits under OFF_Q)

typedef unsigned long long ull;

__device__ __forceinline__ ull pack2(float a, float b) {
    ull r; asm("mov.b64 %0, {%1,%2};" : "=l"(r) : "f"(a), "f"(b)); return r;
}
__device__ __forceinline__ float2 unpack2(ull v) {
    float2 r; asm("mov.b64 {%0,%1}, %2;" : "=f"(r.x), "=f"(r.y) : "l"(v)); return r;
}
// packed fp32x2 FMA (SASS FFMA2) — only reachable via PTX
__device__ __forceinline__ void fma2(ull &d, ull a, ull b) {
    asm("fma.rn.f32x2 %0, %1, %2, %0;" : "+l"(d) : "l"(a), "l"(b));
}

__global__ __launch_bounds__(256, 1)
void fused_winattn(const float* __restrict__ x, const float* __restrict__ y,
                   const float* __restrict__ Wq, const float* __restrict__ Wk,
                   const float* __restrict__ Wv, const float* __restrict__ Wo,
                   float* __restrict__ out, float* __restrict__ att_out)
{
    extern __shared__ float sm[];
    float* s_xw    = sm + OFF_XW;
    float* s_yw    = sm + OFF_YW;
    float* s_att   = sm + OFF_XW;   // alias (valid after q,k,v GEMMs)
    float* s_q     = sm + OFF_Q;
    float* s_k     = sm + OFF_K;
    float* s_v     = sm + OFF_V;
    float* s_w     = sm + OFF_WT;
    float* s_logmw = sm + OFF_LOGMW;
    int*   s_goff  = (int*)(sm + OFF_GOFF);
    float* s_ctx   = s_q;           // alias after attention
    float* s_fin   = s_k;           // alias after attention

    const int tx = threadIdx.x;
    const int w  = blockIdx.x;
    const int b  = w >> 10;
    const int wr = (w >> 5) & 31;
    const int wc = w & 31;

    // ---------------- Phase 0: gather (with roll), mask, stage xw/yw ----------------
    {
        const int warp = tx >> 5, lane = tx & 31;
        for (int p = warp; p < NPIX; p += 8) {
            int i = p / 7, j = p - i * 7;
            int hs = wr * 7 + i + 3;  if (hs  >= HH) hs  -= HH;
            int ws2 = wc * 7 + j + 3; if (ws2 >= HH) ws2 -= HH;
            int goff = ((b * HH + hs) * HH + ws2) * C_;
            float xv[6];
            int cnt = 0;
            #pragma unroll
            for (int u = 0; u < 6; u++) {
                xv[u] = x[goff + lane + 32 * u];
                cnt += (xv[u] > 0.95f) ? 0 : 1;
            }
            #pragma unroll
            for (int o = 16; o; o >>= 1) cnt += __shfl_xor_sync(0xffffffffu, cnt, o);
            float mask = (float)cnt * (1.0f / 192.0f);
            #pragma unroll
            for (int u = 0; u < 6; u++) {
                s_xw[p * STRIDE + lane + 32 * u] = xv[u] * mask;
                s_yw[p * STRIDE + lane + 32 * u] = y[goff + lane + 32 * u];
            }
            if (lane == 0) {
                s_logmw[p] = logf(mask + 1e-6f);
                s_goff[p]  = goff;
            }
        }
    }
    __syncthreads();

    // ---------------- GEMM: out[49,192] = in[49,192] @ W[192,192], FFMA2 ----------------
    // 256 threads: rt = tx>>5 (8 row groups), ct = tx&31 (32 col-pair threads),
    // each thread: rows rt+8u (u<7), column pairs 2*ct + 64*jj (jj<3).
    auto gemm = [&](const float* __restrict__ in, const float* __restrict__ Wg,
                    float* __restrict__ outp) {
        const int rt = tx >> 5;
        const int ct = tx & 31;
        ull acc[7][3];
        #pragma unroll
        for (int u = 0; u < 7; u++)
            #pragma unroll
            for (int jj = 0; jj < 3; jj++) acc[u][jj] = 0ull;

        // prefetch weight tile 0 (16 rows x 192 cols = 3072 floats, flat copy)
        float4 wreg[3];
        #pragma unroll
        for (int i = 0; i < 3; i++)
            wreg[i] = *(const float4*)(Wg + (tx + 256 * i) * 4);
        #pragma unroll
        for (int i = 0; i < 3; i++)
            *(float4*)(s_w + (tx + 256 * i) * 4) = wreg[i];
        __syncthreads();

        for (int t = 0; t < 12; t++) {
            const float* wb = s_w + (t & 1) * 3072;
            if (t < 11) {   // prefetch next tile into regs (overlaps compute)
                #pragma unroll
                for (int i = 0; i < 3; i++)
                    wreg[i] = *(const float4*)(Wg + (t + 1) * 3072 + (tx + 256 * i) * 4);
            }
            const int k0 = t * 16;
            #pragma unroll
            for (int kb = 0; kb < 4; kb++) {
                float4 a4[7];
                #pragma unroll
                for (int u = 0; u < 7; u++)
                    a4[u] = *(const float4*)(in + (rt + 8 * u) * STRIDE + k0 + 4 * kb);
                #pragma unroll
                for (int kk = 0; kk < 4; kk++) {
                    ull wv[3];
                    #pragma unroll
                    for (int jj = 0; jj < 3; jj++)
                        wv[jj] = *(const ull*)(wb + (4 * kb + kk) * 192 + 2 * ct + 64 * jj);
                    #pragma unroll
                    for (int u = 0; u < 7; u++) {
                        float av = (kk == 0) ? a4[u].x : (kk == 1) ? a4[u].y
                                 : (kk == 2) ? a4[u].z : a4[u].w;
                        ull ad = pack2(av, av);
                        #pragma unroll
                        for (int jj = 0; jj < 3; jj++)
                            fma2(acc[u][jj], ad, wv[jj]);
                    }
                }
            }
            if (t < 11) {
                #pragma unroll
                for (int i = 0; i < 3; i++)
                    *(float4*)(s_w + ((t + 1) & 1) * 3072 + (tx + 256 * i) * 4) = wreg[i];
            }
            __syncthreads();
        }
        #pragma unroll
        for (int u = 0; u < 7; u++) {
            int r = rt + 8 * u;
            if (r < NPIX) {
                #pragma unroll
                for (int jj = 0; jj < 3; jj++)
                    *(float2*)(outp + r * STRIDE + 2 * ct + 64 * jj) = unpack2(acc[u][jj]);
            }
        }
        __syncthreads();
    };

    // ---------------- Phase 1: projections ----------------
    gemm(s_xw, Wq, s_q);
    gemm(s_yw, Wk, s_k);
    gemm(s_yw, Wv, s_v);

    // zero v pad rows 49..51 (for padded att@v)
    for (int e = tx; e < 3 * STRIDE; e += 256) s_v[NPIX * STRIDE + e] = 0.0f;

    // ---------------- Phase 2: logits + softmax (one thread per (h,n) row) ----------------
    for (int idx = tx; idx < HEADS * NPIX; idx += 256) {
        int h = idx / NPIX;
        int n = idx - h * NPIX;
        const ull* q2 = (const ull*)(s_q + n * STRIDE + h * DH);
        ull qr[16];
        #pragma unroll
        for (int u = 0; u < 16; u++) qr[u] = q2[u];

        float* arow = s_att + (h * NPIX + n) * 52;
        float mx = -1e30f;
        for (int m = 0; m < NPIX; m++) {
            const ull* k2 = (const ull*)(s_k + m * STRIDE + h * DH);
            ull acc = 0ull;
            #pragma unroll
            for (int u = 0; u < 16; u++) fma2(acc, qr[u], k2[u]);
            float2 p = unpack2(acc);
            float l = (p.x + p.y) * 0.17677669529663687f + s_logmw[m];
            arow[m] = l;
            mx = fmaxf(mx, l);
        }
        float sum = 0.0f;
        for (int m = 0; m < NPIX; m++) {
            float e = __expf(arow[m] - mx);
            arow[m] = e;
            sum += e;
        }
        float inv = 1.0f / sum;
        for (int m = 0; m < NPIX; m++) arow[m] *= inv;
        arow[49] = 0.0f; arow[50] = 0.0f; arow[51] = 0.0f;  // pad
    }
    __syncthreads();

    // ---------------- Phase 2.5: write att to gmem (coalesced) ----------------
    {
        float* attg = att_out + (size_t)w * ATT_W;
        for (int e = tx; e < ATT_W; e += 256) {
            int t = e / NPIX;           // t = h*49 + n
            int m = e - t * NPIX;
            attg[e] = s_att[t * 52 + m];
        }
    }

    // ---------------- Phase 3: ctx[n,c] = sum_m att[h,n,m] * v[m,c]  (packed pairs) ----------------
    if (tx < 192) {
        const int cp  = tx % 96;           // column pair index, cols 2cp, 2cp+1
        const int seg = tx / 96;
        const int n0  = seg * 25;
        const int nn  = seg ? 24 : 25;
        const int h   = cp >> 4;           // (2cp)/32
        ull acc[25];
        #pragma unroll
        for (int n = 0; n < 25; n++) acc[n] = 0ull;
        for (int m0 = 0; m0 < 52; m0 += 4) {
            ull v2[4];
            #pragma unroll
            for (int i = 0; i < 4; i++)
                v2[i] = *(const ull*)(s_v + (m0 + i) * STRIDE + 2 * cp);
            #pragma unroll
            for (int n = 0; n < 25; n++) {
                if (n < nn) {
                    float4 a4 = *(const float4*)(s_att + (h * NPIX + n0 + n) * 52 + m0);
                    fma2(acc[n], pack2(a4.x, a4.x), v2[0]);
                    fma2(acc[n], pack2(a4.y, a4.y), v2[1]);
                    fma2(acc[n], pack2(a4.z, a4.z), v2[2]);
                    fma2(acc[n], pack2(a4.w, a4.w), v2[3]);
                }
            }
        }
        #pragma unroll
        for (int n = 0; n < 25; n++)
            if (n < nn)
                *(float2*)(s_ctx + (n0 + n) * STRIDE + 2 * cp) = unpack2(acc[n]);
    }
    __syncthreads();

    // ---------------- Phase 4: final = ctx @ Wo ----------------
    gemm(s_ctx, Wo, s_fin);

    // ---------------- Phase 5: scatter to out (roll-back == same index map) ----------------
    for (int idx = tx; idx < NPIX * 48; idx += 256) {
        int p  = idx / 48;
        int c4 = idx - p * 48;
        *(float4*)(out + s_goff[p] + 4 * c4) = *(const float4*)(s_fin + p * STRIDE + 4 * c4);
    }
}

extern "C" void kernel_launch(void* const* d_in, const int* in_sizes, int n_in,
                              void* d_out, int out_size)
{
    const float* x  = (const float*)d_in[0];
    const float* y  = (const float*)d_in[1];
    const float* Wq = (const float*)d_in[2];
    const float* Wk = (const float*)d_in[3];
    const float* Wv = (const float*)d_in[4];
    const float* Wo = (const float*)d_in[5];

    float* out = (float*)d_out;                       // [8,224,224,192]
    float* att = out + (size_t)8 * 224 * 224 * 192;   // [8192,6,49,49]

    size_t smem = (size_t)SMEM_FLOATS * sizeof(float);
    cudaFuncSetAttribute(fused_winattn,
                         cudaFuncAttributeMaxDynamicSharedMemorySize, (int)smem);
    fused_winattn<<<NWIN, 256, smem>>>(x, y, Wq, Wk, Wv, Wo, out, att);
}

// round 6
// speedup vs baseline: 1.8835x; 1.2980x over previous
#include <cuda_runtime.h>
#include <cuda_fp16.h>
#include <math.h>
#include <stdint.h>

#define HH      224
#define C_      192
#define NPIX    49
#define HEADS   6
#define NWIN    8192
#define QSTRIDE 196
#define ATT_W   14406

// ---- smem byte layout (no alignment constraints beyond 16B) ----
#define A_HI    0          // A image hi: 12kt x 4mt x 32lane x 16B = 24576
#define A_LO    24576      // A image lo: 24576
#define B_OFF   49152      // single B chunk buffer: 24576
#define Q_OFF   73728      // 49*196*4 = 38416
#define K_OFF   112144     // 38416
#define ATT_OFF 150560     // 6*49*52*4 = 61152 (exclusive)
#define LOGMW_O 211712     // 49 floats
#define GOFF_O  211908     // 49 ints
#define SMEM_BYTES 212112
#define V_OFF   0          // alias A region after GEMMs (52*196*4 = 40768 < 49152)

typedef unsigned long long ull;

// weight images in mma-B-fragment order:
// [w][hi/lo][chunk64][ (kt*24 + ntile)*32*4 + lane*4 + khi*2 + half ]  (halves)
__device__ __align__(16) __half g_Bimg[4][2][3][12288];

// ---------------- helpers ----------------
__device__ __forceinline__ ull pack2(float a, float b) {
    ull r; asm("mov.b64 %0, {%1,%2};" : "=l"(r) : "f"(a), "f"(b)); return r;
}
__device__ __forceinline__ float2 unpack2(ull v) {
    float2 r; asm("mov.b64 {%0,%1}, %2;" : "=f"(r.x), "=f"(r.y) : "l"(v)); return r;
}
__device__ __forceinline__ void fma2(ull &d, ull a, ull b) {
    asm("fma.rn.f32x2 %0, %1, %2, %0;" : "+l"(d) : "l"(a), "l"(b));
}
__device__ __forceinline__ void mma16816(float* c, const uint32_t* a, uint32_t b0, uint32_t b1) {
    asm volatile("mma.sync.aligned.m16n8k16.row.col.f32.f16.f16.f32 "
        "{%0,%1,%2,%3}, {%4,%5,%6,%7}, {%8,%9}, {%0,%1,%2,%3};"
        : "+f"(c[0]), "+f"(c[1]), "+f"(c[2]), "+f"(c[3])
        : "r"(a[0]), "r"(a[1]), "r"(a[2]), "r"(a[3]), "r"(b0), "r"(b1));
}

// ---------------- prep: weights -> f16 hi/lo fragment-order images ----------------
__global__ void prep_w(const float* __restrict__ Wq, const float* __restrict__ Wk,
                       const float* __restrict__ Wv, const float* __restrict__ Wo)
{
    int e = blockIdx.x * 256 + threadIdx.x;
    if (e >= 4 * 36864) return;
    int wsel = e / 36864, r = e % 36864;
    int k = r / 192, n = r % 192;
    const float* W = (wsel == 0) ? Wq : (wsel == 1) ? Wk : (wsel == 2) ? Wv : Wo;
    float v = W[k * 192 + n];
    __half h = __float2half_rn(v);
    __half l = __float2half_rn(v - __half2float(h));
    // mma B fragment (16x8 col-major): b0 = B[2t+half][g], b1 = B[2t+8+half][g]
    int chunk = k >> 6, kk = k & 63;
    int kt = kk >> 4, kc = kk & 15;
    int khi = kc >> 3, t = (kc & 7) >> 1, half = kc & 1;
    int ntile = n >> 3, g = n & 7;
    int lane = g * 4 + t;
    int off = ((kt * 24 + ntile) * 32 + lane) * 4 + khi * 2 + half;
    g_Bimg[wsel][0][chunk][off] = h;
    g_Bimg[wsel][1][chunk][off] = l;
}

// stage A element pair (row p, cols c,c+1 with c even) into fragment-order hi/lo images
// mma A frag (16x16 row-major): a0=A[g][2t+.], a1=A[g+8][2t+.], a2=A[g][2t+8+.], a3=A[g+8][2t+8+.]
__device__ __forceinline__ void stage_pair(char* smem, int p, int c, float a0, float a1)
{
    __half h0 = __float2half_rn(a0), h1 = __float2half_rn(a1);
    __half l0 = __float2half_rn(a0 - __half2float(h0));
    __half l1 = __float2half_rn(a1 - __half2float(h1));
    int mt = p >> 4, rr = p & 15;
    int g = rr & 7, hi8 = rr >> 3;
    int kt = c >> 4, cc = c & 15;
    int khi = cc >> 3, t = (cc & 7) >> 1;
    int reg = hi8 + 2 * khi;
    int off = (((kt * 4 + mt) * 32 + g * 4 + t) * 8 + reg * 2) * 2;  // bytes
    *(__half2*)(smem + A_HI + off) = __halves2half2(h0, h1);
    *(__half2*)(smem + A_LO + off) = __halves2half2(l0, l1);
}

// ---- GEMM: dst[49,192] (stride 196 fp32) = A(split f16) @ W ; HMMA, reg accum ----
__device__ void run_gemm(char* smem, const __half* img, float* __restrict__ dst, int tx)
{
    const int wid = tx >> 5, lane = tx & 31;
    const int mt = wid >> 1, nh = wid & 1;
    const int g = lane >> 2, t = lane & 3;

    float c[12][4];
    #pragma unroll
    for (int j = 0; j < 12; j++)
        #pragma unroll
        for (int i = 0; i < 4; i++) c[j][i] = 0.0f;

    uint4 wreg[6];
    const uint4* src0 = (const uint4*)img;
    #pragma unroll
    for (int i = 0; i < 6; i++) wreg[i] = src0[tx + 256 * i];

    for (int s = 0; s < 6; s++) {
        const int hl = (s < 3) ? 0 : 1;
        const int chunk = (s < 3) ? s : s - 3;
        __syncthreads();                       // previous consumers of B buffer done
        uint4* bb = (uint4*)(smem + B_OFF);
        #pragma unroll
        for (int i = 0; i < 6; i++) bb[tx + 256 * i] = wreg[i];
        __syncthreads();
        if (s < 5) {                            // prefetch next chunk (hidden by compute)
            const int s2 = s + 1;
            const int hl2 = (s2 < 3) ? 0 : 1, ch2 = (s2 < 3) ? s2 : s2 - 3;
            const uint4* nsrc = (const uint4*)(img + (hl2 * 3 + ch2) * 12288);
            #pragma unroll
            for (int i = 0; i < 6; i++) wreg[i] = nsrc[tx + 256 * i];
        }
        #pragma unroll
        for (int ktl = 0; ktl < 4; ktl++) {
            const int kt = chunk * 4 + ktl;
            uint4 ah = *(const uint4*)(smem + A_HI + ((kt * 4 + mt) * 32 + lane) * 16);
            uint4 al;
            if (hl == 0)
                al = *(const uint4*)(smem + A_LO + ((kt * 4 + mt) * 32 + lane) * 16);
            #pragma unroll
            for (int j = 0; j < 12; j++) {
                uint2 b = *(const uint2*)(smem + B_OFF + ((ktl * 24 + nh * 12 + j) * 32 + lane) * 8);
                mma16816(c[j], (const uint32_t*)&ah, b.x, b.y);
                if (hl == 0) mma16816(c[j], (const uint32_t*)&al, b.x, b.y);
            }
        }
    }
    __syncthreads();
    // epilogue: reg -> dst (fp32, stride QSTRIDE), skip rows >= 49
    const int r0 = mt * 16 + g, r1 = r0 + 8;
    #pragma unroll
    for (int j = 0; j < 12; j++) {
        int col = nh * 96 + j * 8 + 2 * t;
        if (r0 < NPIX) *(float2*)(dst + r0 * QSTRIDE + col) = make_float2(c[j][0], c[j][1]);
        if (r1 < NPIX) *(float2*)(dst + r1 * QSTRIDE + col) = make_float2(c[j][2], c[j][3]);
    }
}

__global__ __launch_bounds__(256, 1)
void fused_winattn(const float* __restrict__ x, const float* __restrict__ y,
                   float* __restrict__ out, float* __restrict__ att_out)
{
    extern __shared__ __align__(16) char smem[];
    float* s_q     = (float*)(smem + Q_OFF);
    float* s_k     = (float*)(smem + K_OFF);
    float* s_v     = (float*)(smem + V_OFF);
    float* s_att   = (float*)(smem + ATT_OFF);
    float* s_ctx   = s_q;
    float* s_fin   = s_k;
    float* s_logmw = (float*)(smem + LOGMW_O);
    int*   s_goff  = (int*)(smem + GOFF_O);

    const int tx = threadIdx.x;
    const int wid = tx >> 5, lane = tx & 31;
    const int w  = blockIdx.x;
    const int b  = w >> 10;
    const int wr = (w >> 5) & 31;
    const int wc = w & 31;

    // ---- gather x (roll + mask) -> A images; logmw, goff ----
    for (int p = wid; p < NPIX; p += 8) {
        int i = p / 7, j = p - i * 7;
        int hs = wr * 7 + i + 3;  if (hs >= HH) hs -= HH;
        int vs = wc * 7 + j + 3;  if (vs >= HH) vs -= HH;
        int goff = ((b * HH + hs) * HH + vs) * C_;
        float2 xv[3];
        int cnt = 0;
        #pragma unroll
        for (int u = 0; u < 3; u++) {
            xv[u] = *(const float2*)(x + goff + 2 * lane + 64 * u);
            cnt += (xv[u].x > 0.95f ? 0 : 1) + (xv[u].y > 0.95f ? 0 : 1);
        }
        #pragma unroll
        for (int o = 16; o; o >>= 1) cnt += __shfl_xor_sync(0xffffffffu, cnt, o);
        float mask = (float)cnt * (1.0f / 192.0f);
        #pragma unroll
        for (int u = 0; u < 3; u++)
            stage_pair(smem, p, 2 * lane + 64 * u, xv[u].x * mask, xv[u].y * mask);
        if (lane == 0) { s_logmw[p] = logf(mask + 1e-6f); s_goff[p] = goff; }
    }
    __syncthreads();

    // ---- GEMM q ----
    run_gemm(smem, &g_Bimg[0][0][0][0], s_q, tx);
    __syncthreads();

    // ---- gather y -> A images ----
    for (int p = wid; p < NPIX; p += 8) {
        int goff = s_goff[p];
        #pragma unroll
        for (int u = 0; u < 3; u++) {
            float2 yv = *(const float2*)(y + goff + 2 * lane + 64 * u);
            stage_pair(smem, p, 2 * lane + 64 * u, yv.x, yv.y);
        }
    }
    __syncthreads();

    // ---- GEMM k, GEMM v (shared A=y image) ----
    run_gemm(smem, &g_Bimg[1][0][0][0], s_k, tx);
    run_gemm(smem, &g_Bimg[2][0][0][0], s_v, tx);   // writes V region (aliases A; A dead)
    __syncthreads();
    for (int e = tx; e < 3 * QSTRIDE; e += 256) s_v[NPIX * QSTRIDE + e] = 0.0f;  // v pad rows
    __syncthreads();

    // ---- logits + softmax (FFMA2; one thread per (h,n) row) ----
    for (int idx = tx; idx < HEADS * NPIX; idx += 256) {
        int h = idx / NPIX;
        int n = idx - h * NPIX;
        const ull* q2 = (const ull*)(s_q + n * QSTRIDE + h * 32);
        ull qr[16];
        #pragma unroll
        for (int u = 0; u < 16; u++) qr[u] = q2[u];
        float* arow = s_att + (h * NPIX + n) * 52;
        float mx = -1e30f;
        for (int m = 0; m < NPIX; m++) {
            const ull* k2 = (const ull*)(s_k + m * QSTRIDE + h * 32);
            ull acc = 0ull;
            #pragma unroll
            for (int u = 0; u < 16; u++) fma2(acc, qr[u], k2[u]);
            float2 pr = unpack2(acc);
            float l = (pr.x + pr.y) * 0.17677669529663687f + s_logmw[m];
            arow[m] = l;
            mx = fmaxf(mx, l);
        }
        float sum = 0.0f;
        for (int m = 0; m < NPIX; m++) { float e = __expf(arow[m] - mx); arow[m] = e; sum += e; }
        float inv = 1.0f / sum;
        for (int m = 0; m < NPIX; m++) arow[m] *= inv;
        arow[49] = 0.0f; arow[50] = 0.0f; arow[51] = 0.0f;
    }
    __syncthreads();

    // ---- att -> gmem (coalesced) ----
    {
        float* attg = att_out + (size_t)w * ATT_W;
        for (int e = tx; e < ATT_W; e += 256) {
            int t = e / NPIX;
            int m = e - t * NPIX;
            attg[e] = s_att[t * 52 + m];
        }
    }

    // ---- ctx = att @ v (FFMA2 packed pairs) ----
    if (tx < 192) {
        const int cp  = tx % 96;
        const int seg = tx / 96;
        const int n0  = seg * 25;
        const int nn  = seg ? 24 : 25;
        const int h   = cp >> 4;
        ull acc[25];
        #pragma unroll
        for (int n = 0; n < 25; n++) acc[n] = 0ull;
        for (int m0 = 0; m0 < 52; m0 += 4) {
            ull v2[4];
            #pragma unroll
            for (int i = 0; i < 4; i++)
                v2[i] = *(const ull*)(s_v + (m0 + i) * QSTRIDE + 2 * cp);
            #pragma unroll
            for (int n = 0; n < 25; n++) {
                if (n < nn) {
                    float4 a4 = *(const float4*)(s_att + (h * NPIX + n0 + n) * 52 + m0);
                    fma2(acc[n], pack2(a4.x, a4.x), v2[0]);
                    fma2(acc[n], pack2(a4.y, a4.y), v2[1]);
                    fma2(acc[n], pack2(a4.z, a4.z), v2[2]);
                    fma2(acc[n], pack2(a4.w, a4.w), v2[3]);
                }
            }
        }
        #pragma unroll
        for (int n = 0; n < 25; n++)
            if (n < nn)
                *(float2*)(s_ctx + (n0 + n) * QSTRIDE + 2 * cp) = unpack2(acc[n]);
    }
    __syncthreads();

    // ---- ctx -> A images (V/A region dead) ----
    for (int e = tx; e < NPIX * 96; e += 256) {
        int p  = e / 96;
        int cp = e - p * 96;
        float2 cv = *(const float2*)(s_ctx + p * QSTRIDE + 2 * cp);
        stage_pair(smem, p, 2 * cp, cv.x, cv.y);
    }
    __syncthreads();

    // ---- GEMM o ----
    run_gemm(smem, &g_Bimg[3][0][0][0], s_fin, tx);   // k region (dead)
    __syncthreads();

    // ---- scatter out (roll-back == same index map) ----
    for (int idx = tx; idx < NPIX * 48; idx += 256) {
        int p  = idx / 48;
        int c4 = idx - p * 48;
        *(float4*)(out + s_goff[p] + 4 * c4) = *(const float4*)(s_fin + p * QSTRIDE + 4 * c4);
    }
}

extern "C" void kernel_launch(void* const* d_in, const int* in_sizes, int n_in,
                              void* d_out, int out_size)
{
    const float* x  = (const float*)d_in[0];
    const float* y  = (const float*)d_in[1];
    const float* Wq = (const float*)d_in[2];
    const float* Wk = (const float*)d_in[3];
    const float* Wv = (const float*)d_in[4];
    const float* Wo = (const float*)d_in[5];

    float* out = (float*)d_out;                       // [8,224,224,192]
    float* att = out + (size_t)8 * 224 * 224 * 192;   // [8192,6,49,49]

    prep_w<<<576, 256>>>(Wq, Wk, Wv, Wo);

    cudaFuncSetAttribute(fused_winattn,
                         cudaFuncAttributeMaxDynamicSharedMemorySize, SMEM_BYTES);
    fused_winattn<<<NWIN, 256, SMEM_BYTES>>>(x, y, out, att);
}

// round 7
// speedup vs baseline: 2.8275x; 1.5012x over previous
#include <cuda_runtime.h>
#include <cuda_fp16.h>
#include <math.h>
#include <stdint.h>

#define HH      224
#define C_      192
#define NPIX    49
#define HEADS   6
#define NWIN    8192
#define QSTRIDE 196
#define ATT_W   14406

// ---- smem byte layout ----
#define A_HI    0          // A image hi: 12kt x 4mt x 32lane x 16B = 24576
#define A_LO    24576
#define B_OFF   49152      // single B chunk buffer: 24576
#define Q_OFF   73728      // 49*196*4 = 38416
#define K_OFF   112144     // 38416
#define ATT_OFF 150560     // 6*49*52*4 = 61152 (exclusive)
#define LOGMW_O 211712     // 49 floats
#define GOFF_O  211908     // 49 ints
#define SMEM_BYTES 212112
#define V_OFF   0          // alias A region after GEMMs

typedef unsigned long long ull;

// weight images in mma-B-fragment order (hi/lo; lo kept for easy revert, unused)
__device__ __align__(16) __half g_Bimg[4][2][3][12288];

// ---------------- helpers ----------------
__device__ __forceinline__ ull pack2(float a, float b) {
    ull r; asm("mov.b64 %0, {%1,%2};" : "=l"(r) : "f"(a), "f"(b)); return r;
}
__device__ __forceinline__ float2 unpack2(ull v) {
    float2 r; asm("mov.b64 {%0,%1}, %2;" : "=f"(r.x), "=f"(r.y) : "l"(v)); return r;
}
__device__ __forceinline__ void fma2(ull &d, ull a, ull b) {
    asm("fma.rn.f32x2 %0, %1, %2, %0;" : "+l"(d) : "l"(a), "l"(b));
}
__device__ __forceinline__ void mma16816(float* c, const uint32_t* a, uint32_t b0, uint32_t b1) {
    asm volatile("mma.sync.aligned.m16n8k16.row.col.f32.f16.f16.f32 "
        "{%0,%1,%2,%3}, {%4,%5,%6,%7}, {%8,%9}, {%0,%1,%2,%3};"
        : "+f"(c[0]), "+f"(c[1]), "+f"(c[2]), "+f"(c[3])
        : "r"(a[0]), "r"(a[1]), "r"(a[2]), "r"(a[3]), "r"(b0), "r"(b1));
}
// split a float2 into f16 hi + f16 residual-lo packed half2 words
__device__ __forceinline__ void split2(float2 v, uint32_t& hi, uint32_t& lo) {
    __half2 h2 = __float22half2_rn(v);
    float2 hf = __half22float2(h2);
    __half2 l2 = __float22half2_rn(make_float2(v.x - hf.x, v.y - hf.y));
    hi = *(uint32_t*)&h2;
    lo = *(uint32_t*)&l2;
}

// ---------------- prep: weights -> f16 hi/lo fragment-order images ----------------
__global__ void prep_w(const float* __restrict__ Wq, const float* __restrict__ Wk,
                       const float* __restrict__ Wv, const float* __restrict__ Wo)
{
    int e = blockIdx.x * 256 + threadIdx.x;
    if (e >= 4 * 36864) return;
    int wsel = e / 36864, r = e % 36864;
    int k = r / 192, n = r % 192;
    const float* W = (wsel == 0) ? Wq : (wsel == 1) ? Wk : (wsel == 2) ? Wv : Wo;
    float v = W[k * 192 + n];
    __half h = __float2half_rn(v);
    __half l = __float2half_rn(v - __half2float(h));
    int chunk = k >> 6, kk = k & 63;
    int kt = kk >> 4, kc = kk & 15;
    int khi = kc >> 3, t = (kc & 7) >> 1, half = kc & 1;
    int ntile = n >> 3, g = n & 7;
    int lane = g * 4 + t;
    int off = ((kt * 24 + ntile) * 32 + lane) * 4 + khi * 2 + half;
    g_Bimg[wsel][0][chunk][off] = h;
    g_Bimg[wsel][1][chunk][off] = l;
}

// stage A element pair into fragment-order hi/lo images
__device__ __forceinline__ void stage_pair(char* smem, int p, int c, float a0, float a1)
{
    uint32_t hi, lo;
    split2(make_float2(a0, a1), hi, lo);
    int mt = p >> 4, rr = p & 15;
    int g = rr & 7, hi8 = rr >> 3;
    int kt = c >> 4, cc = c & 15;
    int khi = cc >> 3, t = (cc & 7) >> 1;
    int reg = hi8 + 2 * khi;
    int off = (((kt * 4 + mt) * 32 + g * 4 + t) * 8 + reg * 2) * 2;  // bytes
    *(uint32_t*)(smem + A_HI + off) = hi;
    *(uint32_t*)(smem + A_LO + off) = lo;
}

// ---- projection GEMM (2-pass: Ah*Bh + Al*Bh): dst[49,192] = A(split) @ W ----
__device__ void run_gemm(char* smem, const __half* img, float* __restrict__ dst, int tx)
{
    const int wid = tx >> 5, lane = tx & 31;
    const int mt = wid >> 1, nh = wid & 1;
    const int g = lane >> 2, t = lane & 3;

    float c[12][4];
    #pragma unroll
    for (int j = 0; j < 12; j++)
        #pragma unroll
        for (int i = 0; i < 4; i++) c[j][i] = 0.0f;

    uint4 wreg[6];
    const uint4* src0 = (const uint4*)img;
    #pragma unroll
    for (int i = 0; i < 6; i++) wreg[i] = src0[tx + 256 * i];

    for (int s = 0; s < 3; s++) {
        __syncthreads();
        uint4* bb = (uint4*)(smem + B_OFF);
        #pragma unroll
        for (int i = 0; i < 6; i++) bb[tx + 256 * i] = wreg[i];
        __syncthreads();
        if (s < 2) {
            const uint4* nsrc = (const uint4*)(img + (s + 1) * 12288);
            #pragma unroll
            for (int i = 0; i < 6; i++) wreg[i] = nsrc[tx + 256 * i];
        }
        #pragma unroll
        for (int ktl = 0; ktl < 4; ktl++) {
            const int kt = s * 4 + ktl;
            uint4 ah = *(const uint4*)(smem + A_HI + ((kt * 4 + mt) * 32 + lane) * 16);
            uint4 al = *(const uint4*)(smem + A_LO + ((kt * 4 + mt) * 32 + lane) * 16);
            #pragma unroll
            for (int j = 0; j < 12; j++) {
                uint2 b = *(const uint2*)(smem + B_OFF + ((ktl * 24 + nh * 12 + j) * 32 + lane) * 8);
                mma16816(c[j], (const uint32_t*)&ah, b.x, b.y);
                mma16816(c[j], (const uint32_t*)&al, b.x, b.y);
            }
        }
    }
    __syncthreads();
    const int r0 = mt * 16 + g, r1 = r0 + 8;
    #pragma unroll
    for (int j = 0; j < 12; j++) {
        int col = nh * 96 + j * 8 + 2 * t;
        if (r0 < NPIX) *(float2*)(dst + r0 * QSTRIDE + col) = make_float2(c[j][0], c[j][1]);
        if (r1 < NPIX) *(float2*)(dst + r1 * QSTRIDE + col) = make_float2(c[j][2], c[j][3]);
    }
}

__global__ __launch_bounds__(256, 1)
void fused_winattn(const float* __restrict__ x, const float* __restrict__ y,
                   float* __restrict__ out, float* __restrict__ att_out)
{
    extern __shared__ __align__(16) char smem[];
    float* s_q     = (float*)(smem + Q_OFF);
    float* s_k     = (float*)(smem + K_OFF);
    float* s_v     = (float*)(smem + V_OFF);
    float* s_att   = (float*)(smem + ATT_OFF);
    float* s_ctx   = s_q;
    float* s_fin   = s_k;
    float* s_logmw = (float*)(smem + LOGMW_O);
    int*   s_goff  = (int*)(smem + GOFF_O);

    const int tx = threadIdx.x;
    const int wid = tx >> 5, lane = tx & 31;
    const int w  = blockIdx.x;
    const int b  = w >> 10;
    const int wr = (w >> 5) & 31;
    const int wc = w & 31;

    // ---- gather x (roll + mask) -> A images; logmw, goff ----
    for (int p = wid; p < NPIX; p += 8) {
        int i = p / 7, j = p - i * 7;
        int hs = wr * 7 + i + 3;  if (hs >= HH) hs -= HH;
        int vs = wc * 7 + j + 3;  if (vs >= HH) vs -= HH;
        int goff = ((b * HH + hs) * HH + vs) * C_;
        float2 xv[3];
        int cnt = 0;
        #pragma unroll
        for (int u = 0; u < 3; u++) {
            xv[u] = *(const float2*)(x + goff + 2 * lane + 64 * u);
            cnt += (xv[u].x > 0.95f ? 0 : 1) + (xv[u].y > 0.95f ? 0 : 1);
        }
        #pragma unroll
        for (int o = 16; o; o >>= 1) cnt += __shfl_xor_sync(0xffffffffu, cnt, o);
        float mask = (float)cnt * (1.0f / 192.0f);
        #pragma unroll
        for (int u = 0; u < 3; u++)
            stage_pair(smem, p, 2 * lane + 64 * u, xv[u].x * mask, xv[u].y * mask);
        if (lane == 0) { s_logmw[p] = logf(mask + 1e-6f); s_goff[p] = goff; }
    }
    __syncthreads();

    // ---- GEMM q ----
    run_gemm(smem, &g_Bimg[0][0][0][0], s_q, tx);
    __syncthreads();

    // ---- gather y -> A images ----
    for (int p = wid; p < NPIX; p += 8) {
        int goff = s_goff[p];
        #pragma unroll
        for (int u = 0; u < 3; u++) {
            float2 yv = *(const float2*)(y + goff + 2 * lane + 64 * u);
            stage_pair(smem, p, 2 * lane + 64 * u, yv.x, yv.y);
        }
    }
    __syncthreads();

    // ---- GEMM k, GEMM v ----
    run_gemm(smem, &g_Bimg[1][0][0][0], s_k, tx);
    run_gemm(smem, &g_Bimg[2][0][0][0], s_v, tx);   // writes V region (aliases A; A dead)
    __syncthreads();
    for (int e = tx; e < 3 * QSTRIDE; e += 256) s_v[NPIX * QSTRIDE + e] = 0.0f;
    __syncthreads();

    // ---- logits via mma: per head logits[49,49] = (q*scale) @ k^T, f16 3-pass split ----
    {
        const float SCALE = 0.17677669529663687f;
        const int g = lane >> 2, t = lane & 3;
        for (int u = wid; u < 24; u += 8) {
            const int h = u >> 2, mt = u & 3;
            uint32_t ah[2][4], al[2][4];
            #pragma unroll
            for (int kb = 0; kb < 2; kb++)
                #pragma unroll
                for (int r = 0; r < 4; r++) {
                    int row = mt * 16 + g + (r & 1) * 8;
                    int col = h * 32 + kb * 16 + (r >> 1) * 8 + 2 * t;
                    float2 qv = *(const float2*)(s_q + row * QSTRIDE + col);
                    qv.x *= SCALE; qv.y *= SCALE;
                    split2(qv, ah[kb][r], al[kb][r]);
                }
            for (int nt = 0; nt < 7; nt++) {
                float c[4] = {0.f, 0.f, 0.f, 0.f};
                #pragma unroll
                for (int kb = 0; kb < 2; kb++) {
                    int krow = nt * 8 + g;
                    int kcol = h * 32 + kb * 16 + 2 * t;
                    float2 k0 = *(const float2*)(s_k + krow * QSTRIDE + kcol);
                    float2 k1 = *(const float2*)(s_k + krow * QSTRIDE + kcol + 8);
                    uint32_t bh0, bl0, bh1, bl1;
                    split2(k0, bh0, bl0);
                    split2(k1, bh1, bl1);
                    mma16816(c, ah[kb], bh0, bh1);
                    mma16816(c, al[kb], bh0, bh1);
                    mma16816(c, ah[kb], bl0, bl1);
                }
                int n0 = mt * 16 + g;
                int m0 = nt * 8 + 2 * t;
                float* hb = s_att + h * (NPIX * 52);
                if (n0 < NPIX) {
                    if (m0     < NPIX) hb[n0 * 52 + m0]     = c[0];
                    if (m0 + 1 < NPIX) hb[n0 * 52 + m0 + 1] = c[1];
                }
                if (n0 + 8 < NPIX) {
                    if (m0     < NPIX) hb[(n0 + 8) * 52 + m0]     = c[2];
                    if (m0 + 1 < NPIX) hb[(n0 + 8) * 52 + m0 + 1] = c[3];
                }
            }
        }
    }
    __syncthreads();

    // ---- softmax rows (add log-mask here) ----
    for (int idx = tx; idx < HEADS * NPIX; idx += 256) {
        float* arow = s_att + idx * 52;
        float mx = -1e30f;
        for (int m = 0; m < NPIX; m++) {
            float l = arow[m] + s_logmw[m];
            arow[m] = l;
            mx = fmaxf(mx, l);
        }
        float sum = 0.0f;
        for (int m = 0; m < NPIX; m++) { float e = __expf(arow[m] - mx); arow[m] = e; sum += e; }
        float inv = 1.0f / sum;
        for (int m = 0; m < NPIX; m++) arow[m] *= inv;
        arow[49] = 0.0f; arow[50] = 0.0f; arow[51] = 0.0f;
    }
    __syncthreads();

    // ---- att -> gmem (coalesced) ----
    {
        float* attg = att_out + (size_t)w * ATT_W;
        for (int e = tx; e < ATT_W; e += 256) {
            int t = e / NPIX;
            int m = e - t * NPIX;
            attg[e] = s_att[t * 52 + m];
        }
    }

    // ---- ctx = att @ v (FFMA2 packed pairs) ----
    if (tx < 192) {
        const int cp  = tx % 96;
        const int seg = tx / 96;
        const int n0  = seg * 25;
        const int nn  = seg ? 24 : 25;
        const int h   = cp >> 4;
        ull acc[25];
        #pragma unroll
        for (int n = 0; n < 25; n++) acc[n] = 0ull;
        for (int m0 = 0; m0 < 52; m0 += 4) {
            ull v2[4];
            #pragma unroll
            for (int i = 0; i < 4; i++)
                v2[i] = *(const ull*)(s_v + (m0 + i) * QSTRIDE + 2 * cp);
            #pragma unroll
            for (int n = 0; n < 25; n++) {
                if (n < nn) {
                    float4 a4 = *(const float4*)(s_att + (h * NPIX + n0 + n) * 52 + m0);
                    fma2(acc[n], pack2(a4.x, a4.x), v2[0]);
                    fma2(acc[n], pack2(a4.y, a4.y), v2[1]);
                    fma2(acc[n], pack2(a4.z, a4.z), v2[2]);
                    fma2(acc[n], pack2(a4.w, a4.w), v2[3]);
                }
            }
        }
        #pragma unroll
        for (int n = 0; n < 25; n++)
            if (n < nn)
                *(float2*)(s_ctx + (n0 + n) * QSTRIDE + 2 * cp) = unpack2(acc[n]);
    }
    __syncthreads();

    // ---- ctx -> A images ----
    for (int e = tx; e < NPIX * 96; e += 256) {
        int p  = e / 96;
        int cp = e - p * 96;
        float2 cv = *(const float2*)(s_ctx + p * QSTRIDE + 2 * cp);
        stage_pair(smem, p, 2 * cp, cv.x, cv.y);
    }
    __syncthreads();

    // ---- GEMM o ----
    run_gemm(smem, &g_Bimg[3][0][0][0], s_fin, tx);
    __syncthreads();

    // ---- scatter out (roll-back == same index map) ----
    for (int idx = tx; idx < NPIX * 48; idx += 256) {
        int p  = idx / 48;
        int c4 = idx - p * 48;
        *(float4*)(out + s_goff[p] + 4 * c4) = *(const float4*)(s_fin + p * QSTRIDE + 4 * c4);
    }
}

extern "C" void kernel_launch(void* const* d_in, const int* in_sizes, int n_in,
                              void* d_out, int out_size)
{
    const float* x  = (const float*)d_in[0];
    const float* y  = (const float*)d_in[1];
    const float* Wq = (const float*)d_in[2];
    const float* Wk = (const float*)d_in[3];
    const float* Wv = (const float*)d_in[4];
    const float* Wo = (const float*)d_in[5];

    float* out = (float*)d_out;                       // [8,224,224,192]
    float* att = out + (size_t)8 * 224 * 224 * 192;   // [8192,6,49,49]

    prep_w<<<576, 256>>>(Wq, Wk, Wv, Wo);

    cudaFuncSetAttribute(fused_winattn,
                         cudaFuncAttributeMaxDynamicSharedMemorySize, SMEM_BYTES);
    fused_winattn<<<NWIN, 256, SMEM_BYTES>>>(x, y, out, att);
}

// round 8
// speedup vs baseline: 2.9796x; 1.0538x over previous
#include <cuda_runtime.h>
#include <cuda_fp16.h>
#include <math.h>
#include <stdint.h>

#define HH      224
#define C_      192
#define NPIX    49
#define HEADS   6
#define NWIN    8192
#define QSTRIDE 196
#define ATT_W   14406

// ---- smem byte layout ----
#define A_HI    0          // A frag image hi: 24576
#define A_LO    24576
#define B_OFF   49152      // B chunk buffer: 24576
#define QF_HI   73728      // Q frag image hi: 24576
#define QF_LO   98304
#define KF_HI   122880     // K frag image hi: 21504
#define KF_LO   144384
#define ATT_OFF 165888     // 294*52*4 = 61152
#define LOGMW_O 227040
#define GOFF_O  227236
#define SMEM_BYTES 227456
#define V_OFF   0          // fp32 v, alias A (52*196*4 = 40768)
#define CTX_OFF 73728      // alias QF (dead after logits)
#define FIN_OFF 122880     // alias KF (dead after logits)

typedef unsigned long long ull;

// weight images in mma-B-fragment order
__device__ __align__(16) __half g_Bimg[4][2][3][12288];

// ---------------- helpers ----------------
__device__ __forceinline__ ull pack2(float a, float b) {
    ull r; asm("mov.b64 %0, {%1,%2};" : "=l"(r) : "f"(a), "f"(b)); return r;
}
__device__ __forceinline__ float2 unpack2(ull v) {
    float2 r; asm("mov.b64 {%0,%1}, %2;" : "=f"(r.x), "=f"(r.y) : "l"(v)); return r;
}
__device__ __forceinline__ void fma2(ull &d, ull a, ull b) {
    asm("fma.rn.f32x2 %0, %1, %2, %0;" : "+l"(d) : "l"(a), "l"(b));
}
__device__ __forceinline__ void mma16816(float* c, const uint32_t* a, uint32_t b0, uint32_t b1) {
    asm volatile("mma.sync.aligned.m16n8k16.row.col.f32.f16.f16.f32 "
        "{%0,%1,%2,%3}, {%4,%5,%6,%7}, {%8,%9}, {%0,%1,%2,%3};"
        : "+f"(c[0]), "+f"(c[1]), "+f"(c[2]), "+f"(c[3])
        : "r"(a[0]), "r"(a[1]), "r"(a[2]), "r"(a[3]), "r"(b0), "r"(b1));
}
__device__ __forceinline__ void split2(float2 v, uint32_t& hi, uint32_t& lo) {
    __half2 h2 = __float22half2_rn(v);
    float2 hf = __half22float2(h2);
    __half2 l2 = __float22half2_rn(make_float2(v.x - hf.x, v.y - hf.y));
    hi = *(uint32_t*)&h2;
    lo = *(uint32_t*)&l2;
}

// ---------------- prep: weights -> f16 hi/lo fragment-order images ----------------
__global__ void prep_w(const float* __restrict__ Wq, const float* __restrict__ Wk,
                       const float* __restrict__ Wv, const float* __restrict__ Wo)
{
    int e = blockIdx.x * 256 + threadIdx.x;
    if (e >= 4 * 36864) return;
    int wsel = e / 36864, r = e % 36864;
    int k = r / 192, n = r % 192;
    const float* W = (wsel == 0) ? Wq : (wsel == 1) ? Wk : (wsel == 2) ? Wv : Wo;
    float v = W[k * 192 + n];
    __half h = __float2half_rn(v);
    __half l = __float2half_rn(v - __half2float(h));
    int chunk = k >> 6, kk = k & 63;
    int kt = kk >> 4, kc = kk & 15;
    int khi = kc >> 3, t = (kc & 7) >> 1, half = kc & 1;
    int ntile = n >> 3, g = n & 7;
    int lane = g * 4 + t;
    int off = ((kt * 24 + ntile) * 32 + lane) * 4 + khi * 2 + half;
    g_Bimg[wsel][0][chunk][off] = h;
    g_Bimg[wsel][1][chunk][off] = l;
}

// stage A element pair into fragment-order hi/lo images
__device__ __forceinline__ void stage_pair(char* smem, int p, int c, float a0, float a1)
{
    uint32_t hi, lo;
    split2(make_float2(a0, a1), hi, lo);
    int mt = p >> 4, rr = p & 15;
    int g = rr & 7, hi8 = rr >> 3;
    int kt = c >> 4, cc = c & 15;
    int khi = cc >> 3, t = (cc & 7) >> 1;
    int reg = hi8 + 2 * khi;
    int off = (((kt * 4 + mt) * 32 + g * 4 + t) * 8 + reg * 2) * 2;
    *(uint32_t*)(smem + A_HI + off) = hi;
    *(uint32_t*)(smem + A_LO + off) = lo;
}

// ---- projection GEMM (2-pass Ah*Bh + Al*Bh). mode: 0=fp32 dst, 1=Q frags, 2=K frags
__device__ void run_gemm(char* smem, const __half* img, float* __restrict__ dst,
                         int tx, int mode)
{
    const int wid = tx >> 5, lane = tx & 31;
    const int mt = wid >> 1, nh = wid & 1;
    const int g = lane >> 2, t = lane & 3;

    float c[12][4];
    #pragma unroll
    for (int j = 0; j < 12; j++)
        #pragma unroll
        for (int i = 0; i < 4; i++) c[j][i] = 0.0f;

    uint4 wreg[6];
    const uint4* src0 = (const uint4*)img;
    #pragma unroll
    for (int i = 0; i < 6; i++) wreg[i] = src0[tx + 256 * i];

    for (int s = 0; s < 3; s++) {
        __syncthreads();
        uint4* bb = (uint4*)(smem + B_OFF);
        #pragma unroll
        for (int i = 0; i < 6; i++) bb[tx + 256 * i] = wreg[i];
        __syncthreads();
        if (s < 2) {
            const uint4* nsrc = (const uint4*)(img + (s + 1) * 12288);
            #pragma unroll
            for (int i = 0; i < 6; i++) wreg[i] = nsrc[tx + 256 * i];
        }
        #pragma unroll
        for (int ktl = 0; ktl < 4; ktl++) {
            const int kt = s * 4 + ktl;
            uint4 ah = *(const uint4*)(smem + A_HI + ((kt * 4 + mt) * 32 + lane) * 16);
            uint4 al = *(const uint4*)(smem + A_LO + ((kt * 4 + mt) * 32 + lane) * 16);
            #pragma unroll
            for (int j = 0; j < 12; j++) {
                uint2 b = *(const uint2*)(smem + B_OFF + ((ktl * 24 + nh * 12 + j) * 32 + lane) * 8);
                mma16816(c[j], (const uint32_t*)&ah, b.x, b.y);
                mma16816(c[j], (const uint32_t*)&al, b.x, b.y);
            }
        }
    }
    __syncthreads();

    if (mode == 0) {
        const int r0 = mt * 16 + g, r1 = r0 + 8;
        #pragma unroll
        for (int j = 0; j < 12; j++) {
            int col = nh * 96 + j * 8 + 2 * t;
            if (r0 < NPIX) *(float2*)(dst + r0 * QSTRIDE + col) = make_float2(c[j][0], c[j][1]);
            if (r1 < NPIX) *(float2*)(dst + r1 * QSTRIDE + col) = make_float2(c[j][2], c[j][3]);
        }
    } else if (mode == 1) {
        // Q: scale + split -> A-fragment image. accum(16x8) == A-frag sub-block, same lane.
        const float SCALE = 0.17677669529663687f;
        #pragma unroll
        for (int jp = 0; jp < 6; jp++) {
            int h = 3 * nh + (jp >> 1);
            int kb = jp & 1;
            uint32_t hi[4], lo[4];
            split2(make_float2(c[2*jp][0]*SCALE,   c[2*jp][1]*SCALE),   hi[0], lo[0]);
            split2(make_float2(c[2*jp][2]*SCALE,   c[2*jp][3]*SCALE),   hi[1], lo[1]);
            split2(make_float2(c[2*jp+1][0]*SCALE, c[2*jp+1][1]*SCALE), hi[2], lo[2]);
            split2(make_float2(c[2*jp+1][2]*SCALE, c[2*jp+1][3]*SCALE), hi[3], lo[3]);
            int off = (((h * 4 + mt) * 2 + kb) * 32 + lane) * 16;
            *(uint4*)(smem + QF_HI + off) = make_uint4(hi[0], hi[1], hi[2], hi[3]);
            *(uint4*)(smem + QF_LO + off) = make_uint4(lo[0], lo[1], lo[2], lo[3]);
        }
    } else {
        // K: split -> B-fragment image. (c0,c1) = K[m=mt*16+g][kd,kd+1] == b-word, same lane.
        #pragma unroll
        for (int j = 0; j < 12; j++) {
            int h = 3 * nh + (j >> 2), kb = (j >> 1) & 1, khi = j & 1;
            uint32_t h0, l0, h1, l1;
            split2(make_float2(c[j][0], c[j][1]), h0, l0);   // nt = 2mt
            split2(make_float2(c[j][2], c[j][3]), h1, l1);   // nt = 2mt+1
            int base0 = (((h * 2 + kb) * 7 + 2 * mt) * 32 + lane) * 8 + khi * 4;
            *(uint32_t*)(smem + KF_HI + base0) = h0;
            *(uint32_t*)(smem + KF_LO + base0) = l0;
            if (2 * mt + 1 < 7) {
                *(uint32_t*)(smem + KF_HI + base0 + 256) = h1;
                *(uint32_t*)(smem + KF_LO + base0 + 256) = l1;
            }
        }
    }
}

__global__ __launch_bounds__(256, 1)
void fused_winattn(const float* __restrict__ x, const float* __restrict__ y,
                   float* __restrict__ out, float* __restrict__ att_out)
{
    extern __shared__ __align__(16) char smem[];
    float* s_v     = (float*)(smem + V_OFF);
    float* s_att   = (float*)(smem + ATT_OFF);
    float* s_ctx   = (float*)(smem + CTX_OFF);
    float* s_fin   = (float*)(smem + FIN_OFF);
    float* s_logmw = (float*)(smem + LOGMW_O);
    int*   s_goff  = (int*)(smem + GOFF_O);

    const int tx = threadIdx.x;
    const int wid = tx >> 5, lane = tx & 31;
    const int w  = blockIdx.x;
    const int b  = w >> 10;
    const int wr = (w >> 5) & 31;
    const int wc = w & 31;

    // ---- gather x (roll + mask) -> A images; logmw, goff ----
    for (int p = wid; p < NPIX; p += 8) {
        int i = p / 7, j = p - i * 7;
        int hs = wr * 7 + i + 3;  if (hs >= HH) hs -= HH;
        int vs = wc * 7 + j + 3;  if (vs >= HH) vs -= HH;
        int goff = ((b * HH + hs) * HH + vs) * C_;
        float2 xv[3];
        int cnt = 0;
        #pragma unroll
        for (int u = 0; u < 3; u++) {
            xv[u] = *(const float2*)(x + goff + 2 * lane + 64 * u);
            cnt += (xv[u].x > 0.95f ? 0 : 1) + (xv[u].y > 0.95f ? 0 : 1);
        }
        #pragma unroll
        for (int o = 16; o; o >>= 1) cnt += __shfl_xor_sync(0xffffffffu, cnt, o);
        float mask = (float)cnt * (1.0f / 192.0f);
        #pragma unroll
        for (int u = 0; u < 3; u++)
            stage_pair(smem, p, 2 * lane + 64 * u, xv[u].x * mask, xv[u].y * mask);
        if (lane == 0) { s_logmw[p] = logf(mask + 1e-6f); s_goff[p] = goff; }
    }
    __syncthreads();

    // ---- GEMM q -> Q fragment image (scaled, split) ----
    run_gemm(smem, &g_Bimg[0][0][0][0], nullptr, tx, 1);
    __syncthreads();

    // ---- gather y -> A images ----
    for (int p = wid; p < NPIX; p += 8) {
        int goff = s_goff[p];
        #pragma unroll
        for (int u = 0; u < 3; u++) {
            float2 yv = *(const float2*)(y + goff + 2 * lane + 64 * u);
            stage_pair(smem, p, 2 * lane + 64 * u, yv.x, yv.y);
        }
    }
    __syncthreads();

    // ---- GEMM k -> K fragment image; GEMM v -> fp32 (aliases A; A dead after) ----
    run_gemm(smem, &g_Bimg[1][0][0][0], nullptr, tx, 2);
    run_gemm(smem, &g_Bimg[2][0][0][0], s_v, tx, 0);
    __syncthreads();
    for (int e = tx; e < 3 * QSTRIDE; e += 256) s_v[NPIX * QSTRIDE + e] = 0.0f;
    __syncthreads();

    // ---- logits via mma from fragment images (3-pass: QhKh + QlKh + QhKl) ----
    {
        const int g = lane >> 2, t = lane & 3;
        const int mt = wid >> 1, nh = wid & 1;
        #pragma unroll
        for (int hl = 0; hl < 3; hl++) {
            const int h = 3 * nh + hl;
            uint4 qh0 = *(const uint4*)(smem + QF_HI + (((h * 4 + mt) * 2 + 0) * 32 + lane) * 16);
            uint4 qh1 = *(const uint4*)(smem + QF_HI + (((h * 4 + mt) * 2 + 1) * 32 + lane) * 16);
            uint4 ql0 = *(const uint4*)(smem + QF_LO + (((h * 4 + mt) * 2 + 0) * 32 + lane) * 16);
            uint4 ql1 = *(const uint4*)(smem + QF_LO + (((h * 4 + mt) * 2 + 1) * 32 + lane) * 16);
            for (int nt = 0; nt < 7; nt++) {
                uint2 bh0 = *(const uint2*)(smem + KF_HI + (((h * 2 + 0) * 7 + nt) * 32 + lane) * 8);
                uint2 bh1 = *(const uint2*)(smem + KF_HI + (((h * 2 + 1) * 7 + nt) * 32 + lane) * 8);
                uint2 bl0 = *(const uint2*)(smem + KF_LO + (((h * 2 + 0) * 7 + nt) * 32 + lane) * 8);
                uint2 bl1 = *(const uint2*)(smem + KF_LO + (((h * 2 + 1) * 7 + nt) * 32 + lane) * 8);
                float c[4] = {0.f, 0.f, 0.f, 0.f};
                mma16816(c, (const uint32_t*)&qh0, bh0.x, bh0.y);
                mma16816(c, (const uint32_t*)&ql0, bh0.x, bh0.y);
                mma16816(c, (const uint32_t*)&qh0, bl0.x, bl0.y);
                mma16816(c, (const uint32_t*)&qh1, bh1.x, bh1.y);
                mma16816(c, (const uint32_t*)&ql1, bh1.x, bh1.y);
                mma16816(c, (const uint32_t*)&qh1, bl1.x, bl1.y);
                int n0 = mt * 16 + g;
                int m0 = nt * 8 + 2 * t;
                float* hb = s_att + h * (NPIX * 52);
                if (n0 < NPIX) {
                    if (m0     < NPIX) hb[n0 * 52 + m0]     = c[0];
                    if (m0 + 1 < NPIX) hb[n0 * 52 + m0 + 1] = c[1];
                }
                if (n0 + 8 < NPIX) {
                    if (m0     < NPIX) hb[(n0 + 8) * 52 + m0]     = c[2];
                    if (m0 + 1 < NPIX) hb[(n0 + 8) * 52 + m0 + 1] = c[3];
                }
            }
        }
    }
    __syncthreads();

    // ---- softmax rows (add log-mask) ----
    for (int idx = tx; idx < HEADS * NPIX; idx += 256) {
        float* arow = s_att + idx * 52;
        float mx = -1e30f;
        for (int m = 0; m < NPIX; m++) {
            float l = arow[m] + s_logmw[m];
            arow[m] = l;
            mx = fmaxf(mx, l);
        }
        float sum = 0.0f;
        for (int m = 0; m < NPIX; m++) { float e = __expf(arow[m] - mx); arow[m] = e; sum += e; }
        float inv = 1.0f / sum;
        for (int m = 0; m < NPIX; m++) arow[m] *= inv;
        arow[49] = 0.0f; arow[50] = 0.0f; arow[51] = 0.0f;
    }
    __syncthreads();

    // ---- concurrent: warps 0-5 ctx = att @ v (FFMA2); warps 6-7 att -> gmem ----
    if (tx < 192) {
        const int cp  = tx % 96;
        const int seg = tx / 96;
        const int n0  = seg * 25;
        const int nn  = seg ? 24 : 25;
        const int h   = cp >> 4;
        ull acc[25];
        #pragma unroll
        for (int n = 0; n < 25; n++) acc[n] = 0ull;
        for (int m0 = 0; m0 < 52; m0 += 4) {
            ull v2[4];
            #pragma unroll
            for (int i = 0; i < 4; i++)
                v2[i] = *(const ull*)(s_v + (m0 + i) * QSTRIDE + 2 * cp);
            #pragma unroll
            for (int n = 0; n < 25; n++) {
                if (n < nn) {
                    float4 a4 = *(const float4*)(s_att + (h * NPIX + n0 + n) * 52 + m0);
                    fma2(acc[n], pack2(a4.x, a4.x), v2[0]);
                    fma2(acc[n], pack2(a4.y, a4.y), v2[1]);
                    fma2(acc[n], pack2(a4.z, a4.z), v2[2]);
                    fma2(acc[n], pack2(a4.w, a4.w), v2[3]);
                }
            }
        }
        #pragma unroll
        for (int n = 0; n < 25; n++)
            if (n < nn)
                *(float2*)(s_ctx + (n0 + n) * QSTRIDE + 2 * cp) = unpack2(acc[n]);
    } else {
        float* attg = att_out + (size_t)w * ATT_W;
        for (int e = tx - 192; e < ATT_W; e += 64) {
            int t = e / NPIX;
            int m = e - t * NPIX;
            attg[e] = s_att[t * 52 + m];
        }
    }
    __syncthreads();

    // ---- ctx -> A images (v & frag images dead) ----
    for (int e = tx; e < NPIX * 96; e += 256) {
        int p  = e / 96;
        int cp = e - p * 96;
        float2 cv = *(const float2*)(s_ctx + p * QSTRIDE + 2 * cp);
        stage_pair(smem, p, 2 * cp, cv.x, cv.y);
    }
    __syncthreads();

    // ---- GEMM o -> fp32 fin ----
    run_gemm(smem, &g_Bimg[3][0][0][0], s_fin, tx, 0);
    __syncthreads();

    // ---- scatter out (roll-back == same index map) ----
    for (int idx = tx; idx < NPIX * 48; idx += 256) {
        int p  = idx / 48;
        int c4 = idx - p * 48;
        *(float4*)(out + s_goff[p] + 4 * c4) = *(const float4*)(s_fin + p * QSTRIDE + 4 * c4);
    }
}

extern "C" void kernel_launch(void* const* d_in, const int* in_sizes, int n_in,
                              void* d_out, int out_size)
{
    const float* x  = (const float*)d_in[0];
    const float* y  = (const float*)d_in[1];
    const float* Wq = (const float*)d_in[2];
    const float* Wk = (const float*)d_in[3];
    const float* Wv = (const float*)d_in[4];
    const float* Wo = (const float*)d_in[5];

    float* out = (float*)d_out;                       // [8,224,224,192]
    float* att = out + (size_t)8 * 224 * 224 * 192;   // [8192,6,49,49]

    prep_w<<<576, 256>>>(Wq, Wk, Wv, Wo);

    cudaFuncSetAttribute(fused_winattn,
                         cudaFuncAttributeMaxDynamicSharedMemorySize, SMEM_BYTES);
    fused_winattn<<<NWIN, 256, SMEM_BYTES>>>(x, y, out, att);
}

// round 9
// speedup vs baseline: 3.0938x; 1.0383x over previous
#include <cuda_runtime.h>
#include <cuda_fp16.h>
#include <math.h>
#include <stdint.h>

#define HH      224
#define C_      192
#define NPIX    49
#define HEADS   6
#define NWIN    8192
#define QSTRIDE 196
#define ATT_W   14406

// ---- smem byte layout (phase-sequential aliasing) ----
#define A_HI    0          // A frag image hi (24576); s_v aliases 0..40768; ctx frags alias 0..49152
#define A_LO    24576
#define B_OFF   49152      // proj B chunk buffer (24576); VF_HI aliases between v-stage and GEMM o
#define VF_HI   49152
#define QF_HI   73728      // 24576 ; s_fin aliases after unit loop
#define QF_LO   98304      // 24576
#define KF_HI   122880     // 21504
#define KF_LO   144384     // 21504
#define VF_LO   165888     // 24576
#define LOGMW_O 190464
#define GOFF_O  190672
#define SMEM_BYTES 190976
#define V_OFF   0
#define FIN_OFF 73728

typedef unsigned long long ull;

// weight images in mma-B-fragment order
__device__ __align__(16) __half g_Bimg[4][2][3][12288];

// ---------------- helpers ----------------
__device__ __forceinline__ void mma16816(float* c, const uint32_t* a, uint32_t b0, uint32_t b1) {
    asm volatile("mma.sync.aligned.m16n8k16.row.col.f32.f16.f16.f32 "
        "{%0,%1,%2,%3}, {%4,%5,%6,%7}, {%8,%9}, {%0,%1,%2,%3};"
        : "+f"(c[0]), "+f"(c[1]), "+f"(c[2]), "+f"(c[3])
        : "r"(a[0]), "r"(a[1]), "r"(a[2]), "r"(a[3]), "r"(b0), "r"(b1));
}
__device__ __forceinline__ void split2(float2 v, uint32_t& hi, uint32_t& lo) {
    __half2 h2 = __float22half2_rn(v);
    float2 hf = __half22float2(h2);
    __half2 l2 = __float22half2_rn(make_float2(v.x - hf.x, v.y - hf.y));
    hi = *(uint32_t*)&h2;
    lo = *(uint32_t*)&l2;
}

// ---------------- prep: weights -> f16 hi/lo fragment-order images ----------------
__global__ void prep_w(const float* __restrict__ Wq, const float* __restrict__ Wk,
                       const float* __restrict__ Wv, const float* __restrict__ Wo)
{
    int e = blockIdx.x * 256 + threadIdx.x;
    if (e >= 4 * 36864) return;
    int wsel = e / 36864, r = e % 36864;
    int k = r / 192, n = r % 192;
    const float* W = (wsel == 0) ? Wq : (wsel == 1) ? Wk : (wsel == 2) ? Wv : Wo;
    float v = W[k * 192 + n];
    __half h = __float2half_rn(v);
    __half l = __float2half_rn(v - __half2float(h));
    int chunk = k >> 6, kk = k & 63;
    int kt = kk >> 4, kc = kk & 15;
    int khi = kc >> 3, t = (kc & 7) >> 1, half = kc & 1;
    int ntile = n >> 3, g = n & 7;
    int lane = g * 4 + t;
    int off = ((kt * 24 + ntile) * 32 + lane) * 4 + khi * 2 + half;
    g_Bimg[wsel][0][chunk][off] = h;
    g_Bimg[wsel][1][chunk][off] = l;
}

// stage A element pair into fragment-order hi/lo images
__device__ __forceinline__ void stage_pair(char* smem, int p, int c, float a0, float a1)
{
    uint32_t hi, lo;
    split2(make_float2(a0, a1), hi, lo);
    int mt = p >> 4, rr = p & 15;
    int g = rr & 7, hi8 = rr >> 3;
    int kt = c >> 4, cc = c & 15;
    int khi = cc >> 3, t = (cc & 7) >> 1;
    int reg = hi8 + 2 * khi;
    int off = (((kt * 4 + mt) * 32 + g * 4 + t) * 8 + reg * 2) * 2;
    *(uint32_t*)(smem + A_HI + off) = hi;
    *(uint32_t*)(smem + A_LO + off) = lo;
}

// ---- projection GEMM (2-pass Ah*Bh + Al*Bh). mode: 0=fp32 dst, 1=Q frags, 2=K frags
__device__ void run_gemm(char* smem, const __half* img, float* __restrict__ dst,
                         int tx, int mode)
{
    const int wid = tx >> 5, lane = tx & 31;
    const int mt = wid >> 1, nh = wid & 1;
    const int g = lane >> 2, t = lane & 3;

    float c[12][4];
    #pragma unroll
    for (int j = 0; j < 12; j++)
        #pragma unroll
        for (int i = 0; i < 4; i++) c[j][i] = 0.0f;

    uint4 wreg[6];
    const uint4* src0 = (const uint4*)img;
    #pragma unroll
    for (int i = 0; i < 6; i++) wreg[i] = src0[tx + 256 * i];

    for (int s = 0; s < 3; s++) {
        __syncthreads();
        uint4* bb = (uint4*)(smem + B_OFF);
        #pragma unroll
        for (int i = 0; i < 6; i++) bb[tx + 256 * i] = wreg[i];
        __syncthreads();
        if (s < 2) {
            const uint4* nsrc = (const uint4*)(img + (s + 1) * 12288);
            #pragma unroll
            for (int i = 0; i < 6; i++) wreg[i] = nsrc[tx + 256 * i];
        }
        #pragma unroll
        for (int ktl = 0; ktl < 4; ktl++) {
            const int kt = s * 4 + ktl;
            uint4 ah = *(const uint4*)(smem + A_HI + ((kt * 4 + mt) * 32 + lane) * 16);
            uint4 al = *(const uint4*)(smem + A_LO + ((kt * 4 + mt) * 32 + lane) * 16);
            #pragma unroll
            for (int j = 0; j < 12; j++) {
                uint2 b = *(const uint2*)(smem + B_OFF + ((ktl * 24 + nh * 12 + j) * 32 + lane) * 8);
                mma16816(c[j], (const uint32_t*)&ah, b.x, b.y);
                mma16816(c[j], (const uint32_t*)&al, b.x, b.y);
            }
        }
    }
    __syncthreads();

    if (mode == 0) {
        const int r0 = mt * 16 + g, r1 = r0 + 8;
        #pragma unroll
        for (int j = 0; j < 12; j++) {
            int col = nh * 96 + j * 8 + 2 * t;
            if (r0 < NPIX) *(float2*)(dst + r0 * QSTRIDE + col) = make_float2(c[j][0], c[j][1]);
            if (r1 < NPIX) *(float2*)(dst + r1 * QSTRIDE + col) = make_float2(c[j][2], c[j][3]);
        }
    } else if (mode == 1) {
        const float SCALE = 0.17677669529663687f;
        #pragma unroll
        for (int jp = 0; jp < 6; jp++) {
            int h = 3 * nh + (jp >> 1);
            int kb = jp & 1;
            uint32_t hi[4], lo[4];
            split2(make_float2(c[2*jp][0]*SCALE,   c[2*jp][1]*SCALE),   hi[0], lo[0]);
            split2(make_float2(c[2*jp][2]*SCALE,   c[2*jp][3]*SCALE),   hi[1], lo[1]);
            split2(make_float2(c[2*jp+1][0]*SCALE, c[2*jp+1][1]*SCALE), hi[2], lo[2]);
            split2(make_float2(c[2*jp+1][2]*SCALE, c[2*jp+1][3]*SCALE), hi[3], lo[3]);
            int off = (((h * 4 + mt) * 2 + kb) * 32 + lane) * 16;
            *(uint4*)(smem + QF_HI + off) = make_uint4(hi[0], hi[1], hi[2], hi[3]);
            *(uint4*)(smem + QF_LO + off) = make_uint4(lo[0], lo[1], lo[2], lo[3]);
        }
    } else {
        #pragma unroll
        for (int j = 0; j < 12; j++) {
            int h = 3 * nh + (j >> 2), kb = (j >> 1) & 1, khi = j & 1;
            uint32_t h0, l0, h1, l1;
            split2(make_float2(c[j][0], c[j][1]), h0, l0);
            split2(make_float2(c[j][2], c[j][3]), h1, l1);
            int base0 = (((h * 2 + kb) * 7 + 2 * mt) * 32 + lane) * 8 + khi * 4;
            *(uint32_t*)(smem + KF_HI + base0) = h0;
            *(uint32_t*)(smem + KF_LO + base0) = l0;
            if (2 * mt + 1 < 7) {
                *(uint32_t*)(smem + KF_HI + base0 + 256) = h1;
                *(uint32_t*)(smem + KF_LO + base0 + 256) = l1;
            }
        }
    }
}

__global__ __launch_bounds__(256, 1)
void fused_winattn(const float* __restrict__ x, const float* __restrict__ y,
                   float* __restrict__ out, float* __restrict__ att_out)
{
    extern __shared__ __align__(16) char smem[];
    float* s_v     = (float*)(smem + V_OFF);
    float* s_fin   = (float*)(smem + FIN_OFF);
    float* s_logmw = (float*)(smem + LOGMW_O);
    int*   s_goff  = (int*)(smem + GOFF_O);

    const int tx = threadIdx.x;
    const int wid = tx >> 5, lane = tx & 31;
    const int w  = blockIdx.x;
    const int b  = w >> 10;
    const int wr = (w >> 5) & 31;
    const int wc = w & 31;

    // ---- gather x (roll + mask) -> A images; logmw, goff ----
    for (int p = wid; p < NPIX; p += 8) {
        int i = p / 7, j = p - i * 7;
        int hs = wr * 7 + i + 3;  if (hs >= HH) hs -= HH;
        int vs = wc * 7 + j + 3;  if (vs >= HH) vs -= HH;
        int goff = ((b * HH + hs) * HH + vs) * C_;
        float2 xv[3];
        int cnt = 0;
        #pragma unroll
        for (int u = 0; u < 3; u++) {
            xv[u] = *(const float2*)(x + goff + 2 * lane + 64 * u);
            cnt += (xv[u].x > 0.95f ? 0 : 1) + (xv[u].y > 0.95f ? 0 : 1);
        }
        #pragma unroll
        for (int o = 16; o; o >>= 1) cnt += __shfl_xor_sync(0xffffffffu, cnt, o);
        float mask = (float)cnt * (1.0f / 192.0f);
        #pragma unroll
        for (int u = 0; u < 3; u++)
            stage_pair(smem, p, 2 * lane + 64 * u, xv[u].x * mask, xv[u].y * mask);
        if (lane == 0) { s_logmw[p] = logf(mask + 1e-6f); s_goff[p] = goff; }
    }
    __syncthreads();

    // ---- GEMM q -> Q fragment image (scaled, split) ----
    run_gemm(smem, &g_Bimg[0][0][0][0], nullptr, tx, 1);
    __syncthreads();

    // ---- gather y -> A images ----
    for (int p = wid; p < NPIX; p += 8) {
        int goff = s_goff[p];
        #pragma unroll
        for (int u = 0; u < 3; u++) {
            float2 yv = *(const float2*)(y + goff + 2 * lane + 64 * u);
            stage_pair(smem, p, 2 * lane + 64 * u, yv.x, yv.y);
        }
    }
    __syncthreads();

    // ---- GEMM k -> K fragment image; GEMM v -> fp32 s_v (aliases A; A dead after) ----
    run_gemm(smem, &g_Bimg[1][0][0][0], nullptr, tx, 2);
    run_gemm(smem, &g_Bimg[2][0][0][0], s_v, tx, 0);
    __syncthreads();

    // ---- stage V as f16 hi/lo B-fragment image (s_v dead after) ----
    for (int id = tx; id < 3072; id += 256) {
        int li  = id & 31, nt2 = (id >> 5) & 3, kt = (id >> 7) & 3, h = id >> 9;
        int gg = li >> 2, tt = li & 3;
        int ch = 32 * h + 8 * nt2 + gg;
        int m0 = 16 * kt + 2 * tt;
        float v00 = (m0     < NPIX) ? s_v[ m0      * QSTRIDE + ch] : 0.0f;
        float v01 = (m0 + 1 < NPIX) ? s_v[(m0 + 1) * QSTRIDE + ch] : 0.0f;
        float v10 = (m0 + 8 < NPIX) ? s_v[(m0 + 8) * QSTRIDE + ch] : 0.0f;
        float v11 = (m0 + 9 < NPIX) ? s_v[(m0 + 9) * QSTRIDE + ch] : 0.0f;
        uint32_t h0, l0, h1, l1;
        split2(make_float2(v00, v01), h0, l0);
        split2(make_float2(v10, v11), h1, l1);
        *(uint2*)(smem + VF_HI + id * 8) = make_uint2(h0, h1);
        *(uint2*)(smem + VF_LO + id * 8) = make_uint2(l0, l1);
    }
    __syncthreads();

    // ---- fused logits -> register softmax -> att gmem -> att@v -> ctx frags ----
    {
        const int g = lane >> 2, t = lane & 3;
        for (int u = wid; u < 24; u += 8) {
            const int h = u >> 2, mt = u & 3;
            const int n0 = mt * 16 + g;
            uint4 qh0 = *(const uint4*)(smem + QF_HI + (((h * 4 + mt) * 2 + 0) * 32 + lane) * 16);
            uint4 qh1 = *(const uint4*)(smem + QF_HI + (((h * 4 + mt) * 2 + 1) * 32 + lane) * 16);
            uint4 ql0 = *(const uint4*)(smem + QF_LO + (((h * 4 + mt) * 2 + 0) * 32 + lane) * 16);
            uint4 ql1 = *(const uint4*)(smem + QF_LO + (((h * 4 + mt) * 2 + 1) * 32 + lane) * 16);
            float c[7][4];
            #pragma unroll
            for (int nt = 0; nt < 7; nt++) {
                uint2 bh0 = *(const uint2*)(smem + KF_HI + (((h * 2 + 0) * 7 + nt) * 32 + lane) * 8);
                uint2 bh1 = *(const uint2*)(smem + KF_HI + (((h * 2 + 1) * 7 + nt) * 32 + lane) * 8);
                uint2 bl0 = *(const uint2*)(smem + KF_LO + (((h * 2 + 0) * 7 + nt) * 32 + lane) * 8);
                uint2 bl1 = *(const uint2*)(smem + KF_LO + (((h * 2 + 1) * 7 + nt) * 32 + lane) * 8);
                c[nt][0] = c[nt][1] = c[nt][2] = c[nt][3] = 0.0f;
                mma16816(c[nt], (const uint32_t*)&qh0, bh0.x, bh0.y);
                mma16816(c[nt], (const uint32_t*)&ql0, bh0.x, bh0.y);
                mma16816(c[nt], (const uint32_t*)&qh0, bl0.x, bl0.y);
                mma16816(c[nt], (const uint32_t*)&qh1, bh1.x, bh1.y);
                mma16816(c[nt], (const uint32_t*)&ql1, bh1.x, bh1.y);
                mma16816(c[nt], (const uint32_t*)&qh1, bl1.x, bl1.y);
            }
            // log-mask + invalid-column kill (by index — immune to garbage inf/NaN)
            #pragma unroll
            for (int nt = 0; nt < 6; nt++) {
                float2 lm = *(const float2*)(s_logmw + 8 * nt + 2 * t);
                c[nt][0] += lm.x; c[nt][1] += lm.y;
                c[nt][2] += lm.x; c[nt][3] += lm.y;
            }
            {
                float lm48 = s_logmw[48];
                c[6][0] = (t == 0) ? c[6][0] + lm48 : -1e30f;
                c[6][2] = (t == 0) ? c[6][2] + lm48 : -1e30f;
                c[6][1] = -1e30f;  c[6][3] = -1e30f;
            }
            // register softmax over rows n0 (c[.][0,1]) and n0+8 (c[.][2,3])
            float mx0 = -1e30f, mx1 = -1e30f;
            #pragma unroll
            for (int nt = 0; nt < 7; nt++) {
                mx0 = fmaxf(mx0, fmaxf(c[nt][0], c[nt][1]));
                mx1 = fmaxf(mx1, fmaxf(c[nt][2], c[nt][3]));
            }
            mx0 = fmaxf(mx0, __shfl_xor_sync(0xffffffffu, mx0, 1));
            mx0 = fmaxf(mx0, __shfl_xor_sync(0xffffffffu, mx0, 2));
            mx1 = fmaxf(mx1, __shfl_xor_sync(0xffffffffu, mx1, 1));
            mx1 = fmaxf(mx1, __shfl_xor_sync(0xffffffffu, mx1, 2));
            float s0 = 0.0f, s1 = 0.0f;
            #pragma unroll
            for (int nt = 0; nt < 7; nt++) {
                c[nt][0] = __expf(c[nt][0] - mx0); s0 += c[nt][0];
                c[nt][1] = __expf(c[nt][1] - mx0); s0 += c[nt][1];
                c[nt][2] = __expf(c[nt][2] - mx1); s1 += c[nt][2];
                c[nt][3] = __expf(c[nt][3] - mx1); s1 += c[nt][3];
            }
            s0 += __shfl_xor_sync(0xffffffffu, s0, 1);
            s0 += __shfl_xor_sync(0xffffffffu, s0, 2);
            s1 += __shfl_xor_sync(0xffffffffu, s1, 1);
            s1 += __shfl_xor_sync(0xffffffffu, s1, 2);
            float inv0 = 1.0f / s0, inv1 = 1.0f / s1;
            #pragma unroll
            for (int nt = 0; nt < 7; nt++) {
                c[nt][0] *= inv0; c[nt][1] *= inv0;
                c[nt][2] *= inv1; c[nt][3] *= inv1;
            }
            // att -> gmem direct (scalar stores; layout [w][h][n][m])
            {
                float* ab = att_out + (size_t)w * ATT_W + h * 2401;
                #pragma unroll
                for (int nt = 0; nt < 7; nt++) {
                    int m0 = 8 * nt + 2 * t;
                    if (n0 < NPIX) {
                        if (m0     < NPIX) ab[n0 * NPIX + m0]     = c[nt][0];
                        if (m0 + 1 < NPIX) ab[n0 * NPIX + m0 + 1] = c[nt][1];
                    }
                    if (n0 + 8 < NPIX) {
                        if (m0     < NPIX) ab[(n0 + 8) * NPIX + m0]     = c[nt][2];
                        if (m0 + 1 < NPIX) ab[(n0 + 8) * NPIX + m0 + 1] = c[nt][3];
                    }
                }
            }
            // att@v: A-frags from softmaxed accums; B from VF image; 3-pass split
            float d[4][4];
            #pragma unroll
            for (int n2 = 0; n2 < 4; n2++)
                d[n2][0] = d[n2][1] = d[n2][2] = d[n2][3] = 0.0f;
            #pragma unroll
            for (int kt = 0; kt < 4; kt++) {
                uint32_t Ah[4], Al[4];
                split2(make_float2(c[2*kt][0], c[2*kt][1]), Ah[0], Al[0]);
                split2(make_float2(c[2*kt][2], c[2*kt][3]), Ah[1], Al[1]);
                if (2 * kt + 1 < 7) {
                    split2(make_float2(c[2*kt+1][0], c[2*kt+1][1]), Ah[2], Al[2]);
                    split2(make_float2(c[2*kt+1][2], c[2*kt+1][3]), Ah[3], Al[3]);
                } else {
                    Ah[2] = Ah[3] = Al[2] = Al[3] = 0u;
                }
                #pragma unroll
                for (int n2 = 0; n2 < 4; n2++) {
                    uint2 bh = *(const uint2*)(smem + VF_HI + (((h * 4 + kt) * 4 + n2) * 32 + lane) * 8);
                    uint2 bl = *(const uint2*)(smem + VF_LO + (((h * 4 + kt) * 4 + n2) * 32 + lane) * 8);
                    mma16816(d[n2], Ah, bh.x, bh.y);
                    mma16816(d[n2], Al, bh.x, bh.y);
                    mma16816(d[n2], Ah, bl.x, bl.y);
                }
            }
            // ctx -> A-fragment image for GEMM o (lands at standard A image offsets)
            #pragma unroll
            for (int n2 = 0; n2 < 4; n2++) {
                uint32_t h0, l0, h1, l1;
                split2(make_float2(d[n2][0], d[n2][1]), h0, l0);
                split2(make_float2(d[n2][2], d[n2][3]), h1, l1);
                int kt_o = 2 * h + (n2 >> 1);
                int khi  = n2 & 1;
                int off  = ((kt_o * 4 + mt) * 32 + lane) * 16 + khi * 8;
                *(uint2*)(smem + A_HI + off) = make_uint2(h0, h1);
                *(uint2*)(smem + A_LO + off) = make_uint2(l0, l1);
            }
        }
    }
    __syncthreads();

    // ---- GEMM o (A = ctx frags at standard offsets) -> fp32 s_fin ----
    run_gemm(smem, &g_Bimg[3][0][0][0], s_fin, tx, 0);
    __syncthreads();

    // ---- scatter out (roll-back == same index map) ----
    for (int idx = tx; idx < NPIX * 48; idx += 256) {
        int p  = idx / 48;
        int c4 = idx - p * 48;
        *(float4*)(out + s_goff[p] + 4 * c4) = *(const float4*)(s_fin + p * QSTRIDE + 4 * c4);
    }
}

extern "C" void kernel_launch(void* const* d_in, const int* in_sizes, int n_in,
                              void* d_out, int out_size)
{
    const float* x  = (const float*)d_in[0];
    const float* y  = (const float*)d_in[1];
    const float* Wq = (const float*)d_in[2];
    const float* Wk = (const float*)d_in[3];
    const float* Wv = (const float*)d_in[4];
    const float* Wo = (const float*)d_in[5];

    float* out = (float*)d_out;                       // [8,224,224,192]
    float* att = out + (size_t)8 * 224 * 224 * 192;   // [8192,6,49,49]

    prep_w<<<576, 256>>>(Wq, Wk, Wv, Wo);

    cudaFuncSetAttribute(fused_winattn,
                         cudaFuncAttributeMaxDynamicSharedMemorySize, SMEM_BYTES);
    fused_winattn<<<NWIN, 256, SMEM_BYTES>>>(x, y, out, att);
}

// round 10
// speedup vs baseline: 3.4981x; 1.1307x over previous
#include <cuda_runtime.h>
#include <cuda_fp16.h>
#include <math.h>
#include <stdint.h>

#define HH      224
#define C_      192
#define NPIX    49
#define HEADS   6
#define NWIN    8192
#define QSTRIDE 196
#define ATT_W   14406
#define NTHR    512

// ---- smem byte layout (phase-sequential aliasing) ----
#define A_HI    0          // A frag image hi (24576); s_v aliases 0..40768; ctx frags alias
#define A_LO    24576
#define B_OFF   49152      // proj B chunk buffer (24576); VF_HI aliases
#define VF_HI   49152
#define QF_HI   73728      // 24576 ; s_fin aliases after attention
#define QF_LO   98304
#define KF_HI   122880     // 21504
#define KF_LO   144384
#define VF_LO   165888     // 24576
#define LOGMW_O 190464
#define GOFF_O  190672
#define SMEM_BYTES 190976
#define V_OFF   0
#define FIN_OFF 73728

typedef unsigned long long ull;

// weight images in mma-B-fragment order
__device__ __align__(16) __half g_Bimg[4][2][3][12288];

// ---------------- helpers ----------------
__device__ __forceinline__ void mma16816(float* c, const uint32_t* a, uint32_t b0, uint32_t b1) {
    asm volatile("mma.sync.aligned.m16n8k16.row.col.f32.f16.f16.f32 "
        "{%0,%1,%2,%3}, {%4,%5,%6,%7}, {%8,%9}, {%0,%1,%2,%3};"
        : "+f"(c[0]), "+f"(c[1]), "+f"(c[2]), "+f"(c[3])
        : "r"(a[0]), "r"(a[1]), "r"(a[2]), "r"(a[3]), "r"(b0), "r"(b1));
}
__device__ __forceinline__ void split2(float2 v, uint32_t& hi, uint32_t& lo) {
    __half2 h2 = __float22half2_rn(v);
    float2 hf = __half22float2(h2);
    __half2 l2 = __float22half2_rn(make_float2(v.x - hf.x, v.y - hf.y));
    hi = *(uint32_t*)&h2;
    lo = *(uint32_t*)&l2;
}

// ---------------- prep: weights -> f16 hi/lo fragment-order images ----------------
__global__ void prep_w(const float* __restrict__ Wq, const float* __restrict__ Wk,
                       const float* __restrict__ Wv, const float* __restrict__ Wo)
{
    int e = blockIdx.x * 256 + threadIdx.x;
    if (e >= 4 * 36864) return;
    int wsel = e / 36864, r = e % 36864;
    int k = r / 192, n = r % 192;
    const float* W = (wsel == 0) ? Wq : (wsel == 1) ? Wk : (wsel == 2) ? Wv : Wo;
    float v = W[k * 192 + n];
    __half h = __float2half_rn(v);
    __half l = __float2half_rn(v - __half2float(h));
    int chunk = k >> 6, kk = k & 63;
    int kt = kk >> 4, kc = kk & 15;
    int khi = kc >> 3, t = (kc & 7) >> 1, half = kc & 1;
    int ntile = n >> 3, g = n & 7;
    int lane = g * 4 + t;
    int off = ((kt * 24 + ntile) * 32 + lane) * 4 + khi * 2 + half;
    g_Bimg[wsel][0][chunk][off] = h;
    g_Bimg[wsel][1][chunk][off] = l;
}

// stage A element pair into fragment-order hi/lo images
__device__ __forceinline__ void stage_pair(char* smem, int p, int c, float a0, float a1)
{
    uint32_t hi, lo;
    split2(make_float2(a0, a1), hi, lo);
    int mt = p >> 4, rr = p & 15;
    int g = rr & 7, hi8 = rr >> 3;
    int kt = c >> 4, cc = c & 15;
    int khi = cc >> 3, t = (cc & 7) >> 1;
    int reg = hi8 + 2 * khi;
    int off = (((kt * 4 + mt) * 32 + g * 4 + t) * 8 + reg * 2) * 2;
    *(uint32_t*)(smem + A_HI + off) = hi;
    *(uint32_t*)(smem + A_LO + off) = lo;
}

// ---- projection GEMM, 16 warps (2-pass Ah*Bh + Al*Bh). mode: 0=fp32, 1=Q frags, 2=K frags
// warp = (mt, nh, jh): mt = wid>>2, nh = (wid>>1)&1, jh = wid&1; 6 j's per warp.
__device__ void run_gemm(char* smem, const __half* img, float* __restrict__ dst,
                         int tx, int mode)
{
    const int wid = tx >> 5, lane = tx & 31;
    const int mt = wid >> 2, nh = (wid >> 1) & 1, jh = wid & 1;
    const int g = lane >> 2, t = lane & 3;

    float c[6][4];
    #pragma unroll
    for (int jj = 0; jj < 6; jj++)
        #pragma unroll
        for (int i = 0; i < 4; i++) c[jj][i] = 0.0f;

    uint4 wreg[3];
    const uint4* src0 = (const uint4*)img;
    #pragma unroll
    for (int i = 0; i < 3; i++) wreg[i] = src0[tx + NTHR * i];

    for (int s = 0; s < 3; s++) {
        __syncthreads();
        uint4* bb = (uint4*)(smem + B_OFF);
        #pragma unroll
        for (int i = 0; i < 3; i++) bb[tx + NTHR * i] = wreg[i];
        __syncthreads();
        if (s < 2) {
            const uint4* nsrc = (const uint4*)(img + (s + 1) * 12288);
            #pragma unroll
            for (int i = 0; i < 3; i++) wreg[i] = nsrc[tx + NTHR * i];
        }
        #pragma unroll
        for (int ktl = 0; ktl < 4; ktl++) {
            const int kt = s * 4 + ktl;
            uint4 ah = *(const uint4*)(smem + A_HI + ((kt * 4 + mt) * 32 + lane) * 16);
            uint4 al = *(const uint4*)(smem + A_LO + ((kt * 4 + mt) * 32 + lane) * 16);
            #pragma unroll
            for (int jj = 0; jj < 6; jj++) {
                const int j = jh * 6 + jj;
                uint2 b = *(const uint2*)(smem + B_OFF + ((ktl * 24 + nh * 12 + j) * 32 + lane) * 8);
                mma16816(c[jj], (const uint32_t*)&ah, b.x, b.y);
                mma16816(c[jj], (const uint32_t*)&al, b.x, b.y);
            }
        }
    }
    __syncthreads();

    if (mode == 0) {
        const int r0 = mt * 16 + g, r1 = r0 + 8;
        #pragma unroll
        for (int jj = 0; jj < 6; jj++) {
            int col = nh * 96 + (jh * 6 + jj) * 8 + 2 * t;
            if (r0 < NPIX) *(float2*)(dst + r0 * QSTRIDE + col) = make_float2(c[jj][0], c[jj][1]);
            if (r1 < NPIX) *(float2*)(dst + r1 * QSTRIDE + col) = make_float2(c[jj][2], c[jj][3]);
        }
    } else if (mode == 1) {
        // Q: scale + split -> A-fragment image. warp covers jp = jh*3 .. jh*3+2.
        const float SCALE = 0.17677669529663687f;
        #pragma unroll
        for (int jp3 = 0; jp3 < 3; jp3++) {
            int jp = jh * 3 + jp3;
            int h = 3 * nh + (jp >> 1);
            int kb = jp & 1;
            uint32_t hi[4], lo[4];
            split2(make_float2(c[2*jp3][0]*SCALE,   c[2*jp3][1]*SCALE),   hi[0], lo[0]);
            split2(make_float2(c[2*jp3][2]*SCALE,   c[2*jp3][3]*SCALE),   hi[1], lo[1]);
            split2(make_float2(c[2*jp3+1][0]*SCALE, c[2*jp3+1][1]*SCALE), hi[2], lo[2]);
            split2(make_float2(c[2*jp3+1][2]*SCALE, c[2*jp3+1][3]*SCALE), hi[3], lo[3]);
            int off = (((h * 4 + mt) * 2 + kb) * 32 + lane) * 16;
            *(uint4*)(smem + QF_HI + off) = make_uint4(hi[0], hi[1], hi[2], hi[3]);
            *(uint4*)(smem + QF_LO + off) = make_uint4(lo[0], lo[1], lo[2], lo[3]);
        }
    } else {
        // K: split -> B-fragment image, per global j.
        #pragma unroll
        for (int jj = 0; jj < 6; jj++) {
            int j = jh * 6 + jj;
            int h = 3 * nh + (j >> 2), kb = (j >> 1) & 1, khi = j & 1;
            uint32_t h0, l0, h1, l1;
            split2(make_float2(c[jj][0], c[jj][1]), h0, l0);
            split2(make_float2(c[jj][2], c[jj][3]), h1, l1);
            int base0 = (((h * 2 + kb) * 7 + 2 * mt) * 32 + lane) * 8 + khi * 4;
            *(uint32_t*)(smem + KF_HI + base0) = h0;
            *(uint32_t*)(smem + KF_LO + base0) = l0;
            if (2 * mt + 1 < 7) {
                *(uint32_t*)(smem + KF_HI + base0 + 256) = h1;
                *(uint32_t*)(smem + KF_LO + base0 + 256) = l1;
            }
        }
    }
}

__global__ __launch_bounds__(NTHR, 1)
void fused_winattn(const float* __restrict__ x, const float* __restrict__ y,
                   float* __restrict__ out, float* __restrict__ att_out)
{
    extern __shared__ __align__(16) char smem[];
    float* s_v     = (float*)(smem + V_OFF);
    float* s_fin   = (float*)(smem + FIN_OFF);
    float* s_logmw = (float*)(smem + LOGMW_O);
    int*   s_goff  = (int*)(smem + GOFF_O);

    const int tx = threadIdx.x;
    const int wid = tx >> 5, lane = tx & 31;
    const int w  = blockIdx.x;
    const int b  = w >> 10;
    const int wr = (w >> 5) & 31;
    const int wc = w & 31;

    // ---- gather x (roll + mask) -> A images; logmw, goff ----
    for (int p = wid; p < NPIX; p += 16) {
        int i = p / 7, j = p - i * 7;
        int hs = wr * 7 + i + 3;  if (hs >= HH) hs -= HH;
        int vs = wc * 7 + j + 3;  if (vs >= HH) vs -= HH;
        int goff = ((b * HH + hs) * HH + vs) * C_;
        float2 xv[3];
        int cnt = 0;
        #pragma unroll
        for (int u = 0; u < 3; u++) {
            xv[u] = *(const float2*)(x + goff + 2 * lane + 64 * u);
            cnt += (xv[u].x > 0.95f ? 0 : 1) + (xv[u].y > 0.95f ? 0 : 1);
        }
        #pragma unroll
        for (int o = 16; o; o >>= 1) cnt += __shfl_xor_sync(0xffffffffu, cnt, o);
        float mask = (float)cnt * (1.0f / 192.0f);
        #pragma unroll
        for (int u = 0; u < 3; u++)
            stage_pair(smem, p, 2 * lane + 64 * u, xv[u].x * mask, xv[u].y * mask);
        if (lane == 0) { s_logmw[p] = logf(mask + 1e-6f); s_goff[p] = goff; }
    }
    __syncthreads();

    // ---- GEMM q -> Q fragment image (scaled, split) ----
    run_gemm(smem, &g_Bimg[0][0][0][0], nullptr, tx, 1);
    __syncthreads();

    // ---- gather y -> A images ----
    for (int p = wid; p < NPIX; p += 16) {
        int goff = s_goff[p];
        #pragma unroll
        for (int u = 0; u < 3; u++) {
            float2 yv = *(const float2*)(y + goff + 2 * lane + 64 * u);
            stage_pair(smem, p, 2 * lane + 64 * u, yv.x, yv.y);
        }
    }
    __syncthreads();

    // ---- GEMM k -> K fragment image; GEMM v -> fp32 s_v (aliases A; A dead after) ----
    run_gemm(smem, &g_Bimg[1][0][0][0], nullptr, tx, 2);
    run_gemm(smem, &g_Bimg[2][0][0][0], s_v, tx, 0);
    __syncthreads();

    // ---- stage V as f16 hi/lo B-fragment image (s_v dead after) ----
    for (int id = tx; id < 3072; id += NTHR) {
        int li  = id & 31, nt2 = (id >> 5) & 3, kt = (id >> 7) & 3, h = id >> 9;
        int gg = li >> 2, tt = li & 3;
        int ch = 32 * h + 8 * nt2 + gg;
        int m0 = 16 * kt + 2 * tt;
        float v00 = (m0     < NPIX) ? s_v[ m0      * QSTRIDE + ch] : 0.0f;
        float v01 = (m0 + 1 < NPIX) ? s_v[(m0 + 1) * QSTRIDE + ch] : 0.0f;
        float v10 = (m0 + 8 < NPIX) ? s_v[(m0 + 8) * QSTRIDE + ch] : 0.0f;
        float v11 = (m0 + 9 < NPIX) ? s_v[(m0 + 9) * QSTRIDE + ch] : 0.0f;
        uint32_t h0, l0, h1, l1;
        split2(make_float2(v00, v01), h0, l0);
        split2(make_float2(v10, v11), h1, l1);
        *(uint2*)(smem + VF_HI + id * 8) = make_uint2(h0, h1);
        *(uint2*)(smem + VF_LO + id * 8) = make_uint2(l0, l1);
    }
    __syncthreads();

    // ---- fused logits -> register softmax -> att gmem -> att@v -> ctx frags ----
    {
        const int g = lane >> 2, t = lane & 3;
        for (int u = wid; u < 24; u += 16) {
            const int h = u >> 2, mt = u & 3;
            const int n0 = mt * 16 + g;
            uint4 qh0 = *(const uint4*)(smem + QF_HI + (((h * 4 + mt) * 2 + 0) * 32 + lane) * 16);
            uint4 qh1 = *(const uint4*)(smem + QF_HI + (((h * 4 + mt) * 2 + 1) * 32 + lane) * 16);
            uint4 ql0 = *(const uint4*)(smem + QF_LO + (((h * 4 + mt) * 2 + 0) * 32 + lane) * 16);
            uint4 ql1 = *(const uint4*)(smem + QF_LO + (((h * 4 + mt) * 2 + 1) * 32 + lane) * 16);
            float c[7][4];
            #pragma unroll
            for (int nt = 0; nt < 7; nt++) {
                uint2 bh0 = *(const uint2*)(smem + KF_HI + (((h * 2 + 0) * 7 + nt) * 32 + lane) * 8);
                uint2 bh1 = *(const uint2*)(smem + KF_HI + (((h * 2 + 1) * 7 + nt) * 32 + lane) * 8);
                uint2 bl0 = *(const uint2*)(smem + KF_LO + (((h * 2 + 0) * 7 + nt) * 32 + lane) * 8);
                uint2 bl1 = *(const uint2*)(smem + KF_LO + (((h * 2 + 1) * 7 + nt) * 32 + lane) * 8);
                c[nt][0] = c[nt][1] = c[nt][2] = c[nt][3] = 0.0f;
                mma16816(c[nt], (const uint32_t*)&qh0, bh0.x, bh0.y);
                mma16816(c[nt], (const uint32_t*)&ql0, bh0.x, bh0.y);
                mma16816(c[nt], (const uint32_t*)&qh0, bl0.x, bl0.y);
                mma16816(c[nt], (const uint32_t*)&qh1, bh1.x, bh1.y);
                mma16816(c[nt], (const uint32_t*)&ql1, bh1.x, bh1.y);
                mma16816(c[nt], (const uint32_t*)&qh1, bl1.x, bl1.y);
            }
            // log-mask + invalid-column kill (by index)
            #pragma unroll
            for (int nt = 0; nt < 6; nt++) {
                float2 lm = *(const float2*)(s_logmw + 8 * nt + 2 * t);
                c[nt][0] += lm.x; c[nt][1] += lm.y;
                c[nt][2] += lm.x; c[nt][3] += lm.y;
            }
            {
                float lm48 = s_logmw[48];
                c[6][0] = (t == 0) ? c[6][0] + lm48 : -1e30f;
                c[6][2] = (t == 0) ? c[6][2] + lm48 : -1e30f;
                c[6][1] = -1e30f;  c[6][3] = -1e30f;
            }
            // register softmax over rows n0 and n0+8
            float mx0 = -1e30f, mx1 = -1e30f;
            #pragma unroll
            for (int nt = 0; nt < 7; nt++) {
                mx0 = fmaxf(mx0, fmaxf(c[nt][0], c[nt][1]));
                mx1 = fmaxf(mx1, fmaxf(c[nt][2], c[nt][3]));
            }
            mx0 = fmaxf(mx0, __shfl_xor_sync(0xffffffffu, mx0, 1));
            mx0 = fmaxf(mx0, __shfl_xor_sync(0xffffffffu, mx0, 2));
            mx1 = fmaxf(mx1, __shfl_xor_sync(0xffffffffu, mx1, 1));
            mx1 = fmaxf(mx1, __shfl_xor_sync(0xffffffffu, mx1, 2));
            float s0 = 0.0f, s1 = 0.0f;
            #pragma unroll
            for (int nt = 0; nt < 7; nt++) {
                c[nt][0] = __expf(c[nt][0] - mx0); s0 += c[nt][0];
                c[nt][1] = __expf(c[nt][1] - mx0); s0 += c[nt][1];
                c[nt][2] = __expf(c[nt][2] - mx1); s1 += c[nt][2];
                c[nt][3] = __expf(c[nt][3] - mx1); s1 += c[nt][3];
            }
            s0 += __shfl_xor_sync(0xffffffffu, s0, 1);
            s0 += __shfl_xor_sync(0xffffffffu, s0, 2);
            s1 += __shfl_xor_sync(0xffffffffu, s1, 1);
            s1 += __shfl_xor_sync(0xffffffffu, s1, 2);
            float inv0 = 1.0f / s0, inv1 = 1.0f / s1;
            #pragma unroll
            for (int nt = 0; nt < 7; nt++) {
                c[nt][0] *= inv0; c[nt][1] *= inv0;
                c[nt][2] *= inv1; c[nt][3] *= inv1;
            }
            // att -> gmem direct
            {
                float* ab = att_out + (size_t)w * ATT_W + h * 2401;
                #pragma unroll
                for (int nt = 0; nt < 7; nt++) {
                    int m0 = 8 * nt + 2 * t;
                    if (n0 < NPIX) {
                        if (m0     < NPIX) ab[n0 * NPIX + m0]     = c[nt][0];
                        if (m0 + 1 < NPIX) ab[n0 * NPIX + m0 + 1] = c[nt][1];
                    }
                    if (n0 + 8 < NPIX) {
                        if (m0     < NPIX) ab[(n0 + 8) * NPIX + m0]     = c[nt][2];
                        if (m0 + 1 < NPIX) ab[(n0 + 8) * NPIX + m0 + 1] = c[nt][3];
                    }
                }
            }
            // att@v via mma (A-frags from softmaxed accums, 3-pass split)
            float d[4][4];
            #pragma unroll
            for (int n2 = 0; n2 < 4; n2++)
                d[n2][0] = d[n2][1] = d[n2][2] = d[n2][3] = 0.0f;
            #pragma unroll
            for (int kt = 0; kt < 4; kt++) {
                uint32_t Ah[4], Al[4];
                split2(make_float2(c[2*kt][0], c[2*kt][1]), Ah[0], Al[0]);
                split2(make_float2(c[2*kt][2], c[2*kt][3]), Ah[1], Al[1]);
                if (2 * kt + 1 < 7) {
                    split2(make_float2(c[2*kt+1][0], c[2*kt+1][1]), Ah[2], Al[2]);
                    split2(make_float2(c[2*kt+1][2], c[2*kt+1][3]), Ah[3], Al[3]);
                } else {
                    Ah[2] = Ah[3] = Al[2] = Al[3] = 0u;
                }
                #pragma unroll
                for (int n2 = 0; n2 < 4; n2++) {
                    uint2 bh = *(const uint2*)(smem + VF_HI + (((h * 4 + kt) * 4 + n2) * 32 + lane) * 8);
                    uint2 bl = *(const uint2*)(smem + VF_LO + (((h * 4 + kt) * 4 + n2) * 32 + lane) * 8);
                    mma16816(d[n2], Ah, bh.x, bh.y);
                    mma16816(d[n2], Al, bh.x, bh.y);
                    mma16816(d[n2], Ah, bl.x, bl.y);
                }
            }
            // ctx -> A-fragment image for GEMM o
            #pragma unroll
            for (int n2 = 0; n2 < 4; n2++) {
                uint32_t h0, l0, h1, l1;
                split2(make_float2(d[n2][0], d[n2][1]), h0, l0);
                split2(make_float2(d[n2][2], d[n2][3]), h1, l1);
                int kt_o = 2 * h + (n2 >> 1);
                int khi  = n2 & 1;
                int off  = ((kt_o * 4 + mt) * 32 + lane) * 16 + khi * 8;
                *(uint2*)(smem + A_HI + off) = make_uint2(h0, h1);
                *(uint2*)(smem + A_LO + off) = make_uint2(l0, l1);
            }
        }
    }
    __syncthreads();

    // ---- GEMM o (A = ctx frags) -> fp32 s_fin ----
    run_gemm(smem, &g_Bimg[3][0][0][0], s_fin, tx, 0);
    __syncthreads();

    // ---- scatter out (roll-back == same index map) ----
    for (int idx = tx; idx < NPIX * 48; idx += NTHR) {
        int p  = idx / 48;
        int c4 = idx - p * 48;
        *(float4*)(out + s_goff[p] + 4 * c4) = *(const float4*)(s_fin + p * QSTRIDE + 4 * c4);
    }
}

extern "C" void kernel_launch(void* const* d_in, const int* in_sizes, int n_in,
                              void* d_out, int out_size)
{
    const float* x  = (const float*)d_in[0];
    const float* y  = (const float*)d_in[1];
    const float* Wq = (const float*)d_in[2];
    const float* Wk = (const float*)d_in[3];
    const float* Wv = (const float*)d_in[4];
    const float* Wo = (const float*)d_in[5];

    float* out = (float*)d_out;                       // [8,224,224,192]
    float* att = out + (size_t)8 * 224 * 224 * 192;   // [8192,6,49,49]

    prep_w<<<576, 256>>>(Wq, Wk, Wv, Wo);

    cudaFuncSetAttribute(fused_winattn,
                         cudaFuncAttributeMaxDynamicSharedMemorySize, SMEM_BYTES);
    fused_winattn<<<NWIN, NTHR, SMEM_BYTES>>>(x, y, out, att);
}

// round 12
// speedup vs baseline: 4.3773x; 1.2513x over previous
#include <cuda_runtime.h>
#include <cuda_fp16.h>
#include <math.h>
#include <stdint.h>

#define HH      224
#define C_      192
#define NPIX    49
#define HEADS   6
#define NWIN    8192
#define QSTRIDE 196
#define ATT_W   14406
#define NTHR    512

// ---- smem byte layout (phase-sequential aliasing) ----
#define IMG_X   0          // x A-image hi (24576); s_v + ctx frags alias later
#define IMG_Y   24576      // y A-image hi (24576)
#define B_OFF   49152      // proj B staging (24576); VF_HI aliases during attention
#define VF_HI   49152
#define QF_HI   73728      // 24576 ; s_fin aliases after attention
#define QF_LO   98304      // 24576
#define KF_HI   122880     // 21504
#define KF_LO   144384     // 21504
#define VF_LO   165888     // 24576
#define LOGMW_O 190464
#define GOFF_O  190672
#define SMEM_BYTES 190976
#define SV_OFF  0          // fp32 v (38416) — aliases IMG_X+IMG_Y after kv compute
#define CTX_OFF 0          // ctx frags -> IMG_X region
#define FIN_OFF 73728

// weight images (f16 hi only) in mma-B-fragment order: [w][chunk][12288]
__device__ __align__(16) __half g_Bimg[4][3][12288];

// ---------------- helpers ----------------
__device__ __forceinline__ void mma16816(float* c, const uint32_t* a, uint32_t b0, uint32_t b1) {
    asm volatile("mma.sync.aligned.m16n8k16.row.col.f32.f16.f16.f32 "
        "{%0,%1,%2,%3}, {%4,%5,%6,%7}, {%8,%9}, {%0,%1,%2,%3};"
        : "+f"(c[0]), "+f"(c[1]), "+f"(c[2]), "+f"(c[3])
        : "r"(a[0]), "r"(a[1]), "r"(a[2]), "r"(a[3]), "r"(b0), "r"(b1));
}
__device__ __forceinline__ uint32_t cvt2(float a, float b) {
    __half2 h2 = __float22half2_rn(make_float2(a, b));
    return *(uint32_t*)&h2;
}
__device__ __forceinline__ void split2(float2 v, uint32_t& hi, uint32_t& lo) {
    __half2 h2 = __float22half2_rn(v);
    float2 hf = __half22float2(h2);
    __half2 l2 = __float22half2_rn(make_float2(v.x - hf.x, v.y - hf.y));
    hi = *(uint32_t*)&h2;
    lo = *(uint32_t*)&l2;
}

// ---------------- prep: weights -> f16 fragment-order images (hi only) ----------------
__global__ void prep_w(const float* __restrict__ Wq, const float* __restrict__ Wk,
                       const float* __restrict__ Wv, const float* __restrict__ Wo)
{
    int e = blockIdx.x * 256 + threadIdx.x;
    if (e >= 4 * 36864) return;
    int wsel = e / 36864, r = e % 36864;
    int k = r / 192, n = r % 192;
    const float* W = (wsel == 0) ? Wq : (wsel == 1) ? Wk : (wsel == 2) ? Wv : Wo;
    __half h = __float2half_rn(W[k * 192 + n]);
    int chunk = k >> 6, kk = k & 63;
    int kt = kk >> 4, kc = kk & 15;
    int khi = kc >> 3, t = (kc & 7) >> 1, half = kc & 1;
    int ntile = n >> 3, g = n & 7;
    int lane = g * 4 + t;
    int off = ((kt * 24 + ntile) * 32 + lane) * 4 + khi * 2 + half;
    g_Bimg[wsel][chunk][off] = h;
}

// stage A element pair (hi only) into fragment-order image at base
__device__ __forceinline__ void stage_hi(char* smem, int base, int p, int c, float a0, float a1)
{
    uint32_t hi = cvt2(a0, a1);
    int mt = p >> 4, rr = p & 15;
    int g = rr & 7, hi8 = rr >> 3;
    int kt = c >> 4, cc = c & 15;
    int khi = cc >> 3, t = (cc & 7) >> 1;
    int reg = hi8 + 2 * khi;
    int off = (((kt * 4 + mt) * 32 + g * 4 + t) * 8 + reg * 2) * 2;
    *(uint32_t*)(smem + base + off) = hi;
}

// ---- projection GEMM, 1-pass. mode: 0 = fp32 dst, 1 = Q frags (scaled+split) ----
__device__ void run_gemm(char* smem, const __half* img, int a_base,
                         float* __restrict__ dst, int tx, int mode)
{
    const int wid = tx >> 5, lane = tx & 31;
    const int mt = wid >> 2, nh = (wid >> 1) & 1, jh = wid & 1;
    const int g = lane >> 2, t = lane & 3;

    float c[6][4];
    #pragma unroll
    for (int jj = 0; jj < 6; jj++)
        #pragma unroll
        for (int i = 0; i < 4; i++) c[jj][i] = 0.0f;

    uint4 wreg[3];
    const uint4* src0 = (const uint4*)img;
    #pragma unroll
    for (int i = 0; i < 3; i++) wreg[i] = src0[tx + NTHR * i];

    for (int s = 0; s < 3; s++) {
        __syncthreads();
        uint4* bb = (uint4*)(smem + B_OFF);
        #pragma unroll
        for (int i = 0; i < 3; i++) bb[tx + NTHR * i] = wreg[i];
        __syncthreads();
        if (s < 2) {
            const uint4* nsrc = (const uint4*)(img + (s + 1) * 12288);
            #pragma unroll
            for (int i = 0; i < 3; i++) wreg[i] = nsrc[tx + NTHR * i];
        }
        #pragma unroll
        for (int ktl = 0; ktl < 4; ktl++) {
            const int kt = s * 4 + ktl;
            uint4 ah = *(const uint4*)(smem + a_base + ((kt * 4 + mt) * 32 + lane) * 16);
            #pragma unroll
            for (int jj = 0; jj < 6; jj++) {
                const int j = jh * 6 + jj;
                uint2 b = *(const uint2*)(smem + B_OFF + ((ktl * 24 + nh * 12 + j) * 32 + lane) * 8);
                mma16816(c[jj], (const uint32_t*)&ah, b.x, b.y);
            }
        }
    }
    __syncthreads();

    if (mode == 0) {
        const int r0 = mt * 16 + g, r1 = r0 + 8;
        #pragma unroll
        for (int jj = 0; jj < 6; jj++) {
            int col = nh * 96 + (jh * 6 + jj) * 8 + 2 * t;
            if (r0 < NPIX) *(float2*)(dst + r0 * QSTRIDE + col) = make_float2(c[jj][0], c[jj][1]);
            if (r1 < NPIX) *(float2*)(dst + r1 * QSTRIDE + col) = make_float2(c[jj][2], c[jj][3]);
        }
    } else {
        const float SCALE = 0.17677669529663687f;
        #pragma unroll
        for (int jp3 = 0; jp3 < 3; jp3++) {
            int jp = jh * 3 + jp3;
            int h = 3 * nh + (jp >> 1);
            int kb = jp & 1;
            uint32_t hi[4], lo[4];
            split2(make_float2(c[2*jp3][0]*SCALE,   c[2*jp3][1]*SCALE),   hi[0], lo[0]);
            split2(make_float2(c[2*jp3][2]*SCALE,   c[2*jp3][3]*SCALE),   hi[1], lo[1]);
            split2(make_float2(c[2*jp3+1][0]*SCALE, c[2*jp3+1][1]*SCALE), hi[2], lo[2]);
            split2(make_float2(c[2*jp3+1][2]*SCALE, c[2*jp3+1][3]*SCALE), hi[3], lo[3]);
            int off = (((h * 4 + mt) * 2 + kb) * 32 + lane) * 16;
            *(uint4*)(smem + QF_HI + off) = make_uint4(hi[0], hi[1], hi[2], hi[3]);
            *(uint4*)(smem + QF_LO + off) = make_uint4(lo[0], lo[1], lo[2], lo[3]);
        }
    }
}

// ---- fused k+v GEMM (shared A reads; half-chunk interleaved B staging) ----
__device__ void run_gemm_kv(char* smem, const __half* imgk, const __half* imgv,
                            float* __restrict__ s_v, int tx)
{
    const int wid = tx >> 5, lane = tx & 31;
    const int mt = wid >> 2, nh = (wid >> 1) & 1, jh = wid & 1;
    const int g = lane >> 2, t = lane & 3;

    float ck[6][4], cv[6][4];
    #pragma unroll
    for (int jj = 0; jj < 6; jj++)
        #pragma unroll
        for (int i = 0; i < 4; i++) { ck[jj][i] = 0.0f; cv[jj][i] = 0.0f; }

    uint4 wreg[3];
    {
        const uint4* sk = (const uint4*)imgk;
        const uint4* sv = (const uint4*)imgv;
        #pragma unroll
        for (int i = 0; i < 3; i++) {
            int gi = tx + NTHR * i;
            wreg[i] = (gi < 768) ? sk[gi] : sv[gi - 768];
        }
    }
    for (int hs = 0; hs < 6; hs++) {
        __syncthreads();
        uint4* bb = (uint4*)(smem + B_OFF);
        #pragma unroll
        for (int i = 0; i < 3; i++) bb[tx + NTHR * i] = wreg[i];
        __syncthreads();
        if (hs < 5) {
            int h2 = hs + 1, ch = h2 >> 1, hf = h2 & 1;
            const uint4* sk = (const uint4*)(imgk + ch * 12288 + hf * 6144);
            const uint4* sv = (const uint4*)(imgv + ch * 12288 + hf * 6144);
            #pragma unroll
            for (int i = 0; i < 3; i++) {
                int gi = tx + NTHR * i;
                wreg[i] = (gi < 768) ? sk[gi] : sv[gi - 768];
            }
        }
        const int chunk = hs >> 1, half = hs & 1;
        #pragma unroll
        for (int kl = 0; kl < 2; kl++) {
            int kt = chunk * 4 + half * 2 + kl;
            uint4 ah = *(const uint4*)(smem + IMG_Y + ((kt * 4 + mt) * 32 + lane) * 16);
            #pragma unroll
            for (int jj = 0; jj < 6; jj++) {
                int j = jh * 6 + jj;
                uint2 bk = *(const uint2*)(smem + B_OFF +         ((kl * 24 + nh * 12 + j) * 32 + lane) * 8);
                uint2 bv = *(const uint2*)(smem + B_OFF + 12288 + ((kl * 24 + nh * 12 + j) * 32 + lane) * 8);
                mma16816(ck[jj], (const uint32_t*)&ah, bk.x, bk.y);
                mma16816(cv[jj], (const uint32_t*)&ah, bv.x, bv.y);
            }
        }
    }
    __syncthreads();   // A (IMG_Y) fully consumed; s_v may now alias it

    // K epilogue -> B-fragment image (hi+lo). NOTE: nt=2*mt+1 == 7 is out of range
    // for mt==3 — the guard below is load-bearing (R11 NaN root cause).
    #pragma unroll
    for (int jj = 0; jj < 6; jj++) {
        int j = jh * 6 + jj;
        int h = 3 * nh + (j >> 2), kb = (j >> 1) & 1, khi = j & 1;
        uint32_t h0, l0, h1, l1;
        split2(make_float2(ck[jj][0], ck[jj][1]), h0, l0);
        split2(make_float2(ck[jj][2], ck[jj][3]), h1, l1);
        int base0 = (((h * 2 + kb) * 7 + 2 * mt) * 32 + lane) * 8 + khi * 4;
        *(uint32_t*)(smem + KF_HI + base0) = h0;
        *(uint32_t*)(smem + KF_LO + base0) = l0;
        if (2 * mt + 1 < 7) {
            *(uint32_t*)(smem + KF_HI + base0 + 256) = h1;
            *(uint32_t*)(smem + KF_LO + base0 + 256) = l1;
        }
    }
    // V epilogue -> fp32 rows
    const int r0 = mt * 16 + g, r1 = r0 + 8;
    #pragma unroll
    for (int jj = 0; jj < 6; jj++) {
        int col = nh * 96 + (jh * 6 + jj) * 8 + 2 * t;
        if (r0 < NPIX) *(float2*)(s_v + r0 * QSTRIDE + col) = make_float2(cv[jj][0], cv[jj][1]);
        if (r1 < NPIX) *(float2*)(s_v + r1 * QSTRIDE + col) = make_float2(cv[jj][2], cv[jj][3]);
    }
}

__global__ __launch_bounds__(NTHR, 1)
void fused_winattn(const float* __restrict__ x, const float* __restrict__ y,
                   float* __restrict__ out, float* __restrict__ att_out)
{
    extern __shared__ __align__(16) char smem[];
    float* s_v     = (float*)(smem + SV_OFF);
    float* s_fin   = (float*)(smem + FIN_OFF);
    float* s_logmw = (float*)(smem + LOGMW_O);
    int*   s_goff  = (int*)(smem + GOFF_O);

    const int tx = threadIdx.x;
    const int wid = tx >> 5, lane = tx & 31;
    const int w  = blockIdx.x;
    const int b  = w >> 10;
    const int wr = (w >> 5) & 31;
    const int wc = w & 31;

    // ---- gather x (roll + mask) AND y -> A-images; logmw, goff ----
    for (int p = wid; p < NPIX; p += 16) {
        int i = p / 7, j = p - i * 7;
        int hs = wr * 7 + i + 3;  if (hs >= HH) hs -= HH;
        int vs = wc * 7 + j + 3;  if (vs >= HH) vs -= HH;
        int goff = ((b * HH + hs) * HH + vs) * C_;
        float2 xv[3], yv[3];
        int cnt = 0;
        #pragma unroll
        for (int u = 0; u < 3; u++) {
            xv[u] = *(const float2*)(x + goff + 2 * lane + 64 * u);
            yv[u] = *(const float2*)(y + goff + 2 * lane + 64 * u);
            cnt += (xv[u].x > 0.95f ? 0 : 1) + (xv[u].y > 0.95f ? 0 : 1);
        }
        #pragma unroll
        for (int o = 16; o; o >>= 1) cnt += __shfl_xor_sync(0xffffffffu, cnt, o);
        float mask = (float)cnt * (1.0f / 192.0f);
        #pragma unroll
        for (int u = 0; u < 3; u++) {
            stage_hi(smem, IMG_X, p, 2 * lane + 64 * u, xv[u].x * mask, xv[u].y * mask);
            stage_hi(smem, IMG_Y, p, 2 * lane + 64 * u, yv[u].x, yv[u].y);
        }
        if (lane == 0) { s_logmw[p] = logf(mask + 1e-6f); s_goff[p] = goff; }
    }
    __syncthreads();

    // ---- GEMM q (A = x image) -> Q fragment image ----
    run_gemm(smem, &g_Bimg[0][0][0], IMG_X, nullptr, tx, 1);

    // ---- fused GEMM k+v (A = y image) -> K frags + fp32 s_v ----
    run_gemm_kv(smem, &g_Bimg[1][0][0], &g_Bimg[2][0][0], s_v, tx);
    __syncthreads();

    // ---- stage V as f16 hi/lo B-fragment image (s_v dead after) ----
    for (int id = tx; id < 3072; id += NTHR) {
        int li  = id & 31, nt2 = (id >> 5) & 3, kt = (id >> 7) & 3, h = id >> 9;
        int gg = li >> 2, tt = li & 3;
        int ch = 32 * h + 8 * nt2 + gg;
        int m0 = 16 * kt + 2 * tt;
        float v00 = (m0     < NPIX) ? s_v[ m0      * QSTRIDE + ch] : 0.0f;
        float v01 = (m0 + 1 < NPIX) ? s_v[(m0 + 1) * QSTRIDE + ch] : 0.0f;
        float v10 = (m0 + 8 < NPIX) ? s_v[(m0 + 8) * QSTRIDE + ch] : 0.0f;
        float v11 = (m0 + 9 < NPIX) ? s_v[(m0 + 9) * QSTRIDE + ch] : 0.0f;
        uint32_t h0, l0, h1, l1;
        split2(make_float2(v00, v01), h0, l0);
        split2(make_float2(v10, v11), h1, l1);
        *(uint2*)(smem + VF_HI + id * 8) = make_uint2(h0, h1);
        *(uint2*)(smem + VF_LO + id * 8) = make_uint2(l0, l1);
    }
    __syncthreads();

    // ---- fused logits -> register softmax -> att gmem -> att@v -> ctx frags ----
    {
        const int g = lane >> 2, t = lane & 3;
        for (int u = wid; u < 24; u += 16) {
            const int h = u >> 2, mt = u & 3;
            const int n0 = mt * 16 + g;
            uint4 qh0 = *(const uint4*)(smem + QF_HI + (((h * 4 + mt) * 2 + 0) * 32 + lane) * 16);
            uint4 qh1 = *(const uint4*)(smem + QF_HI + (((h * 4 + mt) * 2 + 1) * 32 + lane) * 16);
            uint4 ql0 = *(const uint4*)(smem + QF_LO + (((h * 4 + mt) * 2 + 0) * 32 + lane) * 16);
            uint4 ql1 = *(const uint4*)(smem + QF_LO + (((h * 4 + mt) * 2 + 1) * 32 + lane) * 16);
            float c[7][4];
            #pragma unroll
            for (int nt = 0; nt < 7; nt++) {
                uint2 bh0 = *(const uint2*)(smem + KF_HI + (((h * 2 + 0) * 7 + nt) * 32 + lane) * 8);
                uint2 bh1 = *(const uint2*)(smem + KF_HI + (((h * 2 + 1) * 7 + nt) * 32 + lane) * 8);
                uint2 bl0 = *(const uint2*)(smem + KF_LO + (((h * 2 + 0) * 7 + nt) * 32 + lane) * 8);
                uint2 bl1 = *(const uint2*)(smem + KF_LO + (((h * 2 + 1) * 7 + nt) * 32 + lane) * 8);
                c[nt][0] = c[nt][1] = c[nt][2] = c[nt][3] = 0.0f;
                mma16816(c[nt], (const uint32_t*)&qh0, bh0.x, bh0.y);
                mma16816(c[nt], (const uint32_t*)&ql0, bh0.x, bh0.y);
                mma16816(c[nt], (const uint32_t*)&qh0, bl0.x, bl0.y);
                mma16816(c[nt], (const uint32_t*)&qh1, bh1.x, bh1.y);
                mma16816(c[nt], (const uint32_t*)&ql1, bh1.x, bh1.y);
                mma16816(c[nt], (const uint32_t*)&qh1, bl1.x, bl1.y);
            }
            #pragma unroll
            for (int nt = 0; nt < 6; nt++) {
                float2 lm = *(const float2*)(s_logmw + 8 * nt + 2 * t);
                c[nt][0] += lm.x; c[nt][1] += lm.y;
                c[nt][2] += lm.x; c[nt][3] += lm.y;
            }
            {
                float lm48 = s_logmw[48];
                c[6][0] = (t == 0) ? c[6][0] + lm48 : -1e30f;
                c[6][2] = (t == 0) ? c[6][2] + lm48 : -1e30f;
                c[6][1] = -1e30f;  c[6][3] = -1e30f;
            }
            float mx0 = -1e30f, mx1 = -1e30f;
            #pragma unroll
            for (int nt = 0; nt < 7; nt++) {
                mx0 = fmaxf(mx0, fmaxf(c[nt][0], c[nt][1]));
                mx1 = fmaxf(mx1, fmaxf(c[nt][2], c[nt][3]));
            }
            mx0 = fmaxf(mx0, __shfl_xor_sync(0xffffffffu, mx0, 1));
            mx0 = fmaxf(mx0, __shfl_xor_sync(0xffffffffu, mx0, 2));
            mx1 = fmaxf(mx1, __shfl_xor_sync(0xffffffffu, mx1, 1));
            mx1 = fmaxf(mx1, __shfl_xor_sync(0xffffffffu, mx1, 2));
            float s0 = 0.0f, s1 = 0.0f;
            #pragma unroll
            for (int nt = 0; nt < 7; nt++) {
                c[nt][0] = __expf(c[nt][0] - mx0); s0 += c[nt][0];
                c[nt][1] = __expf(c[nt][1] - mx0); s0 += c[nt][1];
                c[nt][2] = __expf(c[nt][2] - mx1); s1 += c[nt][2];
                c[nt][3] = __expf(c[nt][3] - mx1); s1 += c[nt][3];
            }
            s0 += __shfl_xor_sync(0xffffffffu, s0, 1);
            s0 += __shfl_xor_sync(0xffffffffu, s0, 2);
            s1 += __shfl_xor_sync(0xffffffffu, s1, 1);
            s1 += __shfl_xor_sync(0xffffffffu, s1, 2);
            float inv0 = 1.0f / s0, inv1 = 1.0f / s1;
            #pragma unroll
            for (int nt = 0; nt < 7; nt++) {
                c[nt][0] *= inv0; c[nt][1] *= inv0;
                c[nt][2] *= inv1; c[nt][3] *= inv1;
            }
            {
                float* ab = att_out + (size_t)w * ATT_W + h * 2401;
                #pragma unroll
                for (int nt = 0; nt < 7; nt++) {
                    int m0 = 8 * nt + 2 * t;
                    if (n0 < NPIX) {
                        if (m0     < NPIX) ab[n0 * NPIX + m0]     = c[nt][0];
                        if (m0 + 1 < NPIX) ab[n0 * NPIX + m0 + 1] = c[nt][1];
                    }
                    if (n0 + 8 < NPIX) {
                        if (m0     < NPIX) ab[(n0 + 8) * NPIX + m0]     = c[nt][2];
                        if (m0 + 1 < NPIX) ab[(n0 + 8) * NPIX + m0 + 1] = c[nt][3];
                    }
                }
            }
            // att@v via mma (3-pass split)
            float d[4][4];
            #pragma unroll
            for (int n2 = 0; n2 < 4; n2++)
                d[n2][0] = d[n2][1] = d[n2][2] = d[n2][3] = 0.0f;
            #pragma unroll
            for (int kt = 0; kt < 4; kt++) {
                uint32_t Ah[4], Al[4];
                split2(make_float2(c[2*kt][0], c[2*kt][1]), Ah[0], Al[0]);
                split2(make_float2(c[2*kt][2], c[2*kt][3]), Ah[1], Al[1]);
                if (2 * kt + 1 < 7) {
                    split2(make_float2(c[2*kt+1][0], c[2*kt+1][1]), Ah[2], Al[2]);
                    split2(make_float2(c[2*kt+1][2], c[2*kt+1][3]), Ah[3], Al[3]);
                } else {
                    Ah[2] = Ah[3] = Al[2] = Al[3] = 0u;
                }
                #pragma unroll
                for (int n2 = 0; n2 < 4; n2++) {
                    uint2 bh = *(const uint2*)(smem + VF_HI + (((h * 4 + kt) * 4 + n2) * 32 + lane) * 8);
                    uint2 bl = *(const uint2*)(smem + VF_LO + (((h * 4 + kt) * 4 + n2) * 32 + lane) * 8);
                    mma16816(d[n2], Ah, bh.x, bh.y);
                    mma16816(d[n2], Al, bh.x, bh.y);
                    mma16816(d[n2], Ah, bl.x, bl.y);
                }
            }
            // ctx -> A-fragment image (hi only) for GEMM o
            #pragma unroll
            for (int n2 = 0; n2 < 4; n2++) {
                uint32_t h0 = cvt2(d[n2][0], d[n2][1]);
                uint32_t h1 = cvt2(d[n2][2], d[n2][3]);
                int kt_o = 2 * h + (n2 >> 1);
                int khi  = n2 & 1;
                int off  = ((kt_o * 4 + mt) * 32 + lane) * 16 + khi * 8;
                *(uint2*)(smem + CTX_OFF + off) = make_uint2(h0, h1);
            }
        }
    }
    __syncthreads();

    // ---- GEMM o (A = ctx frags) -> fp32 s_fin ----
    run_gemm(smem, &g_Bimg[3][0][0], CTX_OFF, s_fin, tx, 0);
    __syncthreads();

    // ---- scatter out (roll-back == same index map) ----
    for (int idx = tx; idx < NPIX * 48; idx += NTHR) {
        int p  = idx / 48;
        int c4 = idx - p * 48;
        *(float4*)(out + s_goff[p] + 4 * c4) = *(const float4*)(s_fin + p * QSTRIDE + 4 * c4);
    }
}

extern "C" void kernel_launch(void* const* d_in, const int* in_sizes, int n_in,
                              void* d_out, int out_size)
{
    const float* x  = (const float*)d_in[0];
    const float* y  = (const float*)d_in[1];
    const float* Wq = (const float*)d_in[2];
    const float* Wk = (const float*)d_in[3];
    const float* Wv = (const float*)d_in[4];
    const float* Wo = (const float*)d_in[5];

    float* out = (float*)d_out;                       // [8,224,224,192]
    float* att = out + (size_t)8 * 224 * 224 * 192;   // [8192,6,49,49]

    prep_w<<<576, 256>>>(Wq, Wk, Wv, Wo);

    cudaFuncSetAttribute(fused_winattn,
                         cudaFuncAttributeMaxDynamicSharedMemorySize, SMEM_BYTES);
    fused_winattn<<<NWIN, NTHR, SMEM_BYTES>>>(x, y, out, att);
}

// round 13
// speedup vs baseline: 4.4430x; 1.0150x over previous
#include <cuda_runtime.h>
#include <cuda_fp16.h>
#include <math.h>
#include <stdint.h>

#define HH      224
#define C_      192
#define NPIX    49
#define HEADS   6
#define NWIN    8192
#define QSTRIDE 196
#define ATT_W   14406
#define NTHR    512

// ---- smem byte layout (phase-sequential aliasing) ----
#define IMG_X   0          // x A-image (24576); CTX frags alias during attention
#define IMG_Y   24576      // y A-image (24576)
#define B_OFF   49152      // B staging (24576); VF_HI aliases after V-GEMM
#define VF_HI   49152
#define QF_HI   73728      // 24576 ; s_fin aliases after attention
#define QF_LO   98304      // 24576
#define KF_HI   122880     // 21504
#define KF_LO   144384     // 21504
#define VF_LO   165888     // 24576 ; ALSO K's B staging buffer (before V epilogue)
#define LOGMW_O 190464
#define GOFF_O  190672
#define SMEM_BYTES 190976
#define CTX_OFF 0
#define FIN_OFF 73728

// weight images (f16 hi only) in mma-B-fragment order: [w][chunk][12288]
__device__ __align__(16) __half g_Bimg[4][3][12288];

// ---------------- helpers ----------------
__device__ __forceinline__ void mma16816(float* c, const uint32_t* a, uint32_t b0, uint32_t b1) {
    asm volatile("mma.sync.aligned.m16n8k16.row.col.f32.f16.f16.f32 "
        "{%0,%1,%2,%3}, {%4,%5,%6,%7}, {%8,%9}, {%0,%1,%2,%3};"
        : "+f"(c[0]), "+f"(c[1]), "+f"(c[2]), "+f"(c[3])
        : "r"(a[0]), "r"(a[1]), "r"(a[2]), "r"(a[3]), "r"(b0), "r"(b1));
}
__device__ __forceinline__ uint32_t cvt2(float a, float b) {
    __half2 h2 = __float22half2_rn(make_float2(a, b));
    return *(uint32_t*)&h2;
}
__device__ __forceinline__ void split2(float2 v, uint32_t& hi, uint32_t& lo) {
    __half2 h2 = __float22half2_rn(v);
    float2 hf = __half22float2(h2);
    __half2 l2 = __float22half2_rn(make_float2(v.x - hf.x, v.y - hf.y));
    hi = *(uint32_t*)&h2;
    lo = *(uint32_t*)&l2;
}
__device__ __forceinline__ void barx(int id) {
    asm volatile("bar.sync %0, 256;" :: "r"(id) : "memory");
}

// ---------------- prep: weights -> f16 fragment-order images (hi only) ----------------
__global__ void prep_w(const float* __restrict__ Wq, const float* __restrict__ Wk,
                       const float* __restrict__ Wv, const float* __restrict__ Wo)
{
    int e = blockIdx.x * 256 + threadIdx.x;
    if (e >= 4 * 36864) return;
    int wsel = e / 36864, r = e % 36864;
    int k = r / 192, n = r % 192;
    const float* W = (wsel == 0) ? Wq : (wsel == 1) ? Wk : (wsel == 2) ? Wv : Wo;
    __half h = __float2half_rn(W[k * 192 + n]);
    int chunk = k >> 6, kk = k & 63;
    int kt = kk >> 4, kc = kk & 15;
    int khi = kc >> 3, t = (kc & 7) >> 1, half = kc & 1;
    int ntile = n >> 3, g = n & 7;
    int lane = g * 4 + t;
    int off = ((kt * 24 + ntile) * 32 + lane) * 4 + khi * 2 + half;
    g_Bimg[wsel][chunk][off] = h;
}

// stage A element pair (hi only) into fragment-order image at base
__device__ __forceinline__ void stage_hi(char* smem, int base, int p, int c, float a0, float a1)
{
    uint32_t hi = cvt2(a0, a1);
    int mt = p >> 4, rr = p & 15;
    int g = rr & 7, hi8 = rr >> 3;
    int kt = c >> 4, cc = c & 15;
    int khi = cc >> 3, t = (cc & 7) >> 1;
    int reg = hi8 + 2 * khi;
    int off = (((kt * 4 + mt) * 32 + g * 4 + t) * 8 + reg * 2) * 2;
    *(uint32_t*)(smem + base + off) = hi;
}

// ---- 8-warp GEMM (group-private named barrier). mode 1 = Q frags, 2 = K frags ----
__device__ void run_gemm8(char* smem, const __half* img, int a_base, int b_off,
                          int gtx, int bid, int mode, uint4* wreg)
{
    const int wid8 = gtx >> 5, lane = gtx & 31;
    const int mt = wid8 >> 1, nh = wid8 & 1;

    float c[12][4];
    #pragma unroll
    for (int j = 0; j < 12; j++)
        #pragma unroll
        for (int i = 0; i < 4; i++) c[j][i] = 0.0f;

    for (int s = 0; s < 3; s++) {
        barx(bid);
        uint4* bb = (uint4*)(smem + b_off);
        #pragma unroll
        for (int i = 0; i < 6; i++) bb[gtx + 256 * i] = wreg[i];
        barx(bid);
        if (s < 2) {
            const uint4* nsrc = (const uint4*)(img + (s + 1) * 12288);
            #pragma unroll
            for (int i = 0; i < 6; i++) wreg[i] = nsrc[gtx + 256 * i];
        }
        #pragma unroll
        for (int ktl = 0; ktl < 4; ktl++) {
            const int kt = s * 4 + ktl;
            uint4 ah = *(const uint4*)(smem + a_base + ((kt * 4 + mt) * 32 + lane) * 16);
            #pragma unroll
            for (int j = 0; j < 12; j++) {
                uint2 b = *(const uint2*)(smem + b_off + ((ktl * 24 + nh * 12 + j) * 32 + lane) * 8);
                mma16816(c[j], (const uint32_t*)&ah, b.x, b.y);
            }
        }
    }

    if (mode == 1) {
        // Q: scale + split -> A-fragment image
        const float SCALE = 0.17677669529663687f;
        #pragma unroll
        for (int jp = 0; jp < 6; jp++) {
            int h = 3 * nh + (jp >> 1);
            int kb = jp & 1;
            uint32_t hi[4], lo[4];
            split2(make_float2(c[2*jp][0]*SCALE,   c[2*jp][1]*SCALE),   hi[0], lo[0]);
            split2(make_float2(c[2*jp][2]*SCALE,   c[2*jp][3]*SCALE),   hi[1], lo[1]);
            split2(make_float2(c[2*jp+1][0]*SCALE, c[2*jp+1][1]*SCALE), hi[2], lo[2]);
            split2(make_float2(c[2*jp+1][2]*SCALE, c[2*jp+1][3]*SCALE), hi[3], lo[3]);
            int off = (((h * 4 + mt) * 2 + kb) * 32 + lane) * 16;
            *(uint4*)(smem + QF_HI + off) = make_uint4(hi[0], hi[1], hi[2], hi[3]);
            *(uint4*)(smem + QF_LO + off) = make_uint4(lo[0], lo[1], lo[2], lo[3]);
        }
    } else {
        // K: split -> B-fragment image (guard: nt=2mt+1==7 out of range for mt==3)
        #pragma unroll
        for (int j = 0; j < 12; j++) {
            int h = 3 * nh + (j >> 2), kb = (j >> 1) & 1, khi = j & 1;
            uint32_t h0, l0, h1, l1;
            split2(make_float2(c[j][0], c[j][1]), h0, l0);
            split2(make_float2(c[j][2], c[j][3]), h1, l1);
            int base0 = (((h * 2 + kb) * 7 + 2 * mt) * 32 + lane) * 8 + khi * 4;
            *(uint32_t*)(smem + KF_HI + base0) = h0;
            *(uint32_t*)(smem + KF_LO + base0) = l0;
            if (2 * mt + 1 < 7) {
                *(uint32_t*)(smem + KF_HI + base0 + 256) = h1;
                *(uint32_t*)(smem + KF_LO + base0 + 256) = l1;
            }
        }
    }
}

// ---- 16-warp GEMM. mode 0 = fp32 dst (O), mode 3 = direct VF-fragment epilogue (V) ----
__device__ void run_gemm16(char* smem, const __half* img, int a_base,
                           float* __restrict__ dst, int tx, int mode)
{
    const int wid = tx >> 5, lane = tx & 31;
    const int mt = wid >> 2, nh = (wid >> 1) & 1, jh = wid & 1;
    const int g = lane >> 2, t = lane & 3;

    float c[6][4];
    #pragma unroll
    for (int jj = 0; jj < 6; jj++)
        #pragma unroll
        for (int i = 0; i < 4; i++) c[jj][i] = 0.0f;

    uint4 wreg[3];
    const uint4* src0 = (const uint4*)img;
    #pragma unroll
    for (int i = 0; i < 3; i++) wreg[i] = src0[tx + NTHR * i];

    for (int s = 0; s < 3; s++) {
        __syncthreads();
        uint4* bb = (uint4*)(smem + B_OFF);
        #pragma unroll
        for (int i = 0; i < 3; i++) bb[tx + NTHR * i] = wreg[i];
        __syncthreads();
        if (s < 2) {
            const uint4* nsrc = (const uint4*)(img + (s + 1) * 12288);
            #pragma unroll
            for (int i = 0; i < 3; i++) wreg[i] = nsrc[tx + NTHR * i];
        }
        #pragma unroll
        for (int ktl = 0; ktl < 4; ktl++) {
            const int kt = s * 4 + ktl;
            uint4 ah = *(const uint4*)(smem + a_base + ((kt * 4 + mt) * 32 + lane) * 16);
            #pragma unroll
            for (int jj = 0; jj < 6; jj++) {
                const int j = jh * 6 + jj;
                uint2 b = *(const uint2*)(smem + B_OFF + ((ktl * 24 + nh * 12 + j) * 32 + lane) * 8);
                mma16816(c[jj], (const uint32_t*)&ah, b.x, b.y);
            }
        }
    }
    __syncthreads();

    if (mode == 0) {
        const int r0 = mt * 16 + g, r1 = r0 + 8;
        #pragma unroll
        for (int jj = 0; jj < 6; jj++) {
            int col = nh * 96 + (jh * 6 + jj) * 8 + 2 * t;
            if (r0 < NPIX) *(float2*)(dst + r0 * QSTRIDE + col) = make_float2(c[jj][0], c[jj][1]);
            if (r1 < NPIX) *(float2*)(dst + r1 * QSTRIDE + col) = make_float2(c[jj][2], c[jj][3]);
        }
    } else {
        // V: direct B-fragment store. Lane pairing rows (g, g^1) via shfl_xor lane^4.
        const int even = !(g & 1);
        const int tt = g >> 1;
        #pragma unroll
        for (int jj = 0; jj < 6; jj++) {
            int col = nh * 96 + (jh * 6 + jj) * 8 + 2 * t;
            float p0 = __shfl_xor_sync(0xffffffffu, c[jj][0], 4);
            float p1 = __shfl_xor_sync(0xffffffffu, c[jj][1], 4);
            float p2 = __shfl_xor_sync(0xffffffffu, c[jj][2], 4);
            float p3 = __shfl_xor_sync(0xffffffffu, c[jj][3], 4);
            int m0 = 16 * mt + (even ? g : g - 1);   // even word base row
            float va0 = even ? c[jj][0] : p1;        // V[m0][ch]
            float vb0 = even ? p0 : c[jj][1];        // V[m0+1][ch]
            float va1 = even ? c[jj][2] : p3;        // V[m0+8][ch]
            float vb1 = even ? p2 : c[jj][3];        // V[m0+9][ch]
            va0 = (m0     < NPIX) ? va0 : 0.0f;
            vb0 = (m0 + 1 < NPIX) ? vb0 : 0.0f;
            va1 = (m0 + 8 < NPIX) ? va1 : 0.0f;
            vb1 = (m0 + 9 < NPIX) ? vb1 : 0.0f;
            int ch = col + (even ? 0 : 1);
            uint32_t h0, l0, h1, l1;
            split2(make_float2(va0, vb0), h0, l0);
            split2(make_float2(va1, vb1), h1, l1);
            int hh = ch >> 5, nt2 = (ch >> 3) & 3, gg = ch & 7;
            int id = ((hh * 4 + mt) * 4 + nt2) * 32 + gg * 4 + tt;
            *(uint2*)(smem + VF_HI + id * 8) = make_uint2(h0, h1);
            *(uint2*)(smem + VF_LO + id * 8) = make_uint2(l0, l1);
        }
    }
}

__global__ __launch_bounds__(NTHR, 1)
void fused_winattn(const float* __restrict__ x, const float* __restrict__ y,
                   float* __restrict__ out, float* __restrict__ att_out)
{
    extern __shared__ __align__(16) char smem[];
    float* s_fin   = (float*)(smem + FIN_OFF);
    float* s_logmw = (float*)(smem + LOGMW_O);
    int*   s_goff  = (int*)(smem + GOFF_O);

    const int tx = threadIdx.x;
    const int wid = tx >> 5, lane = tx & 31;
    const int w  = blockIdx.x;
    const int b  = w >> 10;
    const int wr = (w >> 5) & 31;
    const int wc = w & 31;

    // ---- prefetch B chunk-0 for this warp's GEMM group (hidden under gather) ----
    const int grp = (tx < 256) ? 0 : 1;
    const int gtx = tx & 255;
    uint4 wreg[6];
    {
        const uint4* s0 = (const uint4*)(grp == 0 ? &g_Bimg[0][0][0] : &g_Bimg[1][0][0]);
        #pragma unroll
        for (int i = 0; i < 6; i++) wreg[i] = s0[gtx + 256 * i];
    }

    // ---- gather x (roll + mask) AND y -> A-images; logmw, goff ----
    for (int p = wid; p < NPIX; p += 16) {
        int i = p / 7, j = p - i * 7;
        int hs = wr * 7 + i + 3;  if (hs >= HH) hs -= HH;
        int vs = wc * 7 + j + 3;  if (vs >= HH) vs -= HH;
        int goff = ((b * HH + hs) * HH + vs) * C_;
        float2 xv[3], yv[3];
        int cnt = 0;
        #pragma unroll
        for (int u = 0; u < 3; u++) {
            xv[u] = *(const float2*)(x + goff + 2 * lane + 64 * u);
            yv[u] = *(const float2*)(y + goff + 2 * lane + 64 * u);
            cnt += (xv[u].x > 0.95f ? 0 : 1) + (xv[u].y > 0.95f ? 0 : 1);
        }
        #pragma unroll
        for (int o = 16; o; o >>= 1) cnt += __shfl_xor_sync(0xffffffffu, cnt, o);
        float mask = (float)cnt * (1.0f / 192.0f);
        #pragma unroll
        for (int u = 0; u < 3; u++) {
            stage_hi(smem, IMG_X, p, 2 * lane + 64 * u, xv[u].x * mask, xv[u].y * mask);
            stage_hi(smem, IMG_Y, p, 2 * lane + 64 * u, yv[u].x, yv[u].y);
        }
        if (lane == 0) { s_logmw[p] = logf(mask + 1e-6f); s_goff[p] = goff; }
    }
    __syncthreads();

    // ---- CONCURRENT: warps 0-7 GEMM q -> Q frags | warps 8-15 GEMM k -> K frags ----
    if (grp == 0)
        run_gemm8(smem, &g_Bimg[0][0][0], IMG_X, B_OFF,  gtx, 1, 1, wreg);
    else
        run_gemm8(smem, &g_Bimg[1][0][0], IMG_Y, VF_LO, gtx, 2, 2, wreg);
    __syncthreads();

    // ---- GEMM v (16 warps) -> direct VF fragment image ----
    run_gemm16(smem, &g_Bimg[2][0][0], IMG_Y, nullptr, tx, 3);
    __syncthreads();

    // ---- fused logits -> register softmax -> att gmem -> att@v -> ctx frags ----
    {
        const int g = lane >> 2, t = lane & 3;
        for (int u = wid; u < 24; u += 16) {
            const int h = u >> 2, mt = u & 3;
            const int n0 = mt * 16 + g;
            uint4 qh0 = *(const uint4*)(smem + QF_HI + (((h * 4 + mt) * 2 + 0) * 32 + lane) * 16);
            uint4 qh1 = *(const uint4*)(smem + QF_HI + (((h * 4 + mt) * 2 + 1) * 32 + lane) * 16);
            uint4 ql0 = *(const uint4*)(smem + QF_LO + (((h * 4 + mt) * 2 + 0) * 32 + lane) * 16);
            uint4 ql1 = *(const uint4*)(smem + QF_LO + (((h * 4 + mt) * 2 + 1) * 32 + lane) * 16);
            float c[7][4];
            #pragma unroll
            for (int nt = 0; nt < 7; nt++) {
                uint2 bh0 = *(const uint2*)(smem + KF_HI + (((h * 2 + 0) * 7 + nt) * 32 + lane) * 8);
                uint2 bh1 = *(const uint2*)(smem + KF_HI + (((h * 2 + 1) * 7 + nt) * 32 + lane) * 8);
                uint2 bl0 = *(const uint2*)(smem + KF_LO + (((h * 2 + 0) * 7 + nt) * 32 + lane) * 8);
                uint2 bl1 = *(const uint2*)(smem + KF_LO + (((h * 2 + 1) * 7 + nt) * 32 + lane) * 8);
                c[nt][0] = c[nt][1] = c[nt][2] = c[nt][3] = 0.0f;
                mma16816(c[nt], (const uint32_t*)&qh0, bh0.x, bh0.y);
                mma16816(c[nt], (const uint32_t*)&ql0, bh0.x, bh0.y);
                mma16816(c[nt], (const uint32_t*)&qh0, bl0.x, bl0.y);
                mma16816(c[nt], (const uint32_t*)&qh1, bh1.x, bh1.y);
                mma16816(c[nt], (const uint32_t*)&ql1, bh1.x, bh1.y);
                mma16816(c[nt], (const uint32_t*)&qh1, bl1.x, bl1.y);
            }
            #pragma unroll
            for (int nt = 0; nt < 6; nt++) {
                float2 lm = *(const float2*)(s_logmw + 8 * nt + 2 * t);
                c[nt][0] += lm.x; c[nt][1] += lm.y;
                c[nt][2] += lm.x; c[nt][3] += lm.y;
            }
            {
                float lm48 = s_logmw[48];
                c[6][0] = (t == 0) ? c[6][0] + lm48 : -1e30f;
                c[6][2] = (t == 0) ? c[6][2] + lm48 : -1e30f;
                c[6][1] = -1e30f;  c[6][3] = -1e30f;
            }
            float mx0 = -1e30f, mx1 = -1e30f;
            #pragma unroll
            for (int nt = 0; nt < 7; nt++) {
                mx0 = fmaxf(mx0, fmaxf(c[nt][0], c[nt][1]));
                mx1 = fmaxf(mx1, fmaxf(c[nt][2], c[nt][3]));
            }
            mx0 = fmaxf(mx0, __shfl_xor_sync(0xffffffffu, mx0, 1));
            mx0 = fmaxf(mx0, __shfl_xor_sync(0xffffffffu, mx0, 2));
            mx1 = fmaxf(mx1, __shfl_xor_sync(0xffffffffu, mx1, 1));
            mx1 = fmaxf(mx1, __shfl_xor_sync(0xffffffffu, mx1, 2));
            float s0 = 0.0f, s1 = 0.0f;
            #pragma unroll
            for (int nt = 0; nt < 7; nt++) {
                c[nt][0] = __expf(c[nt][0] - mx0); s0 += c[nt][0];
                c[nt][1] = __expf(c[nt][1] - mx0); s0 += c[nt][1];
                c[nt][2] = __expf(c[nt][2] - mx1); s1 += c[nt][2];
                c[nt][3] = __expf(c[nt][3] - mx1); s1 += c[nt][3];
            }
            s0 += __shfl_xor_sync(0xffffffffu, s0, 1);
            s0 += __shfl_xor_sync(0xffffffffu, s0, 2);
            s1 += __shfl_xor_sync(0xffffffffu, s1, 1);
            s1 += __shfl_xor_sync(0xffffffffu, s1, 2);
            float inv0 = 1.0f / s0, inv1 = 1.0f / s1;
            #pragma unroll
            for (int nt = 0; nt < 7; nt++) {
                c[nt][0] *= inv0; c[nt][1] *= inv0;
                c[nt][2] *= inv1; c[nt][3] *= inv1;
            }
            {
                float* ab = att_out + (size_t)w * ATT_W + h * 2401;
                #pragma unroll
                for (int nt = 0; nt < 7; nt++) {
                    int m0 = 8 * nt + 2 * t;
                    if (n0 < NPIX) {
                        if (m0     < NPIX) ab[n0 * NPIX + m0]     = c[nt][0];
                        if (m0 + 1 < NPIX) ab[n0 * NPIX + m0 + 1] = c[nt][1];
                    }
                    if (n0 + 8 < NPIX) {
                        if (m0     < NPIX) ab[(n0 + 8) * NPIX + m0]     = c[nt][2];
                        if (m0 + 1 < NPIX) ab[(n0 + 8) * NPIX + m0 + 1] = c[nt][3];
                    }
                }
            }
            // att@v via mma (3-pass split)
            float d[4][4];
            #pragma unroll
            for (int n2 = 0; n2 < 4; n2++)
                d[n2][0] = d[n2][1] = d[n2][2] = d[n2][3] = 0.0f;
            #pragma unroll
            for (int kt = 0; kt < 4; kt++) {
                uint32_t Ah[4], Al[4];
                split2(make_float2(c[2*kt][0], c[2*kt][1]), Ah[0], Al[0]);
                split2(make_float2(c[2*kt][2], c[2*kt][3]), Ah[1], Al[1]);
                if (2 * kt + 1 < 7) {
                    split2(make_float2(c[2*kt+1][0], c[2*kt+1][1]), Ah[2], Al[2]);
                    split2(make_float2(c[2*kt+1][2], c[2*kt+1][3]), Ah[3], Al[3]);
                } else {
                    Ah[2] = Ah[3] = Al[2] = Al[3] = 0u;
                }
                #pragma unroll
                for (int n2 = 0; n2 < 4; n2++) {
                    uint2 bh = *(const uint2*)(smem + VF_HI + (((h * 4 + kt) * 4 + n2) * 32 + lane) * 8);
                    uint2 bl = *(const uint2*)(smem + VF_LO + (((h * 4 + kt) * 4 + n2) * 32 + lane) * 8);
                    mma16816(d[n2], Ah, bh.x, bh.y);
                    mma16816(d[n2], Al, bh.x, bh.y);
                    mma16816(d[n2], Ah, bl.x, bl.y);
                }
            }
            // ctx -> A-fragment image (hi only) for GEMM o
            #pragma unroll
            for (int n2 = 0; n2 < 4; n2++) {
                uint32_t h0 = cvt2(d[n2][0], d[n2][1]);
                uint32_t h1 = cvt2(d[n2][2], d[n2][3]);
                int kt_o = 2 * h + (n2 >> 1);
                int khi  = n2 & 1;
                int off  = ((kt_o * 4 + mt) * 32 + lane) * 16 + khi * 8;
                *(uint2*)(smem + CTX_OFF + off) = make_uint2(h0, h1);
            }
        }
    }
    __syncthreads();

    // ---- GEMM o (A = ctx frags) -> fp32 s_fin ----
    run_gemm16(smem, &g_Bimg[3][0][0], CTX_OFF, s_fin, tx, 0);
    __syncthreads();

    // ---- scatter out (roll-back == same index map) ----
    for (int idx = tx; idx < NPIX * 48; idx += NTHR) {
        int p  = idx / 48;
        int c4 = idx - p * 48;
        *(float4*)(out + s_goff[p] + 4 * c4) = *(const float4*)(s_fin + p * QSTRIDE + 4 * c4);
    }
}

extern "C" void kernel_launch(void* const* d_in, const int* in_sizes, int n_in,
                              void* d_out, int out_size)
{
    const float* x  = (const float*)d_in[0];
    const float* y  = (const float*)d_in[1];
    const float* Wq = (const float*)d_in[2];
    const float* Wk = (const float*)d_in[3];
    const float* Wv = (const float*)d_in[4];
    const float* Wo = (const float*)d_in[5];

    float* out = (float*)d_out;                       // [8,224,224,192]
    float* att = out + (size_t)8 * 224 * 224 * 192;   // [8192,6,49,49]

    prep_w<<<576, 256>>>(Wq, Wk, Wv, Wo);

    cudaFuncSetAttribute(fused_winattn,
                         cudaFuncAttributeMaxDynamicSharedMemorySize, SMEM_BYTES);
    fused_winattn<<<NWIN, NTHR, SMEM_BYTES>>>(x, y, out, att);
}

// round 14
// speedup vs baseline: 6.5132x; 1.4659x over previous
#include <cuda_runtime.h>
#include <cuda_fp16.h>
#include <math.h>
#include <stdint.h>

#define HH      224
#define C_      192
#define NPIX    49
#define HEADS   6
#define NWIN    8192
#define QSTRIDE 196
#define ATT_W   14406
#define NTHR    384

// ---- smem byte layout (105.4 KB -> 2 CTAs/SM) ----
#define IMG_X   0          // x A-image (24576); VF_HI aliases after V-GEMM
#define IMG_Y   24576      // y A-image (24576); CTX frags alias during attention
#define B_OFF   49152      // B half-chunk staging (12288)
#define QF_HI   61440      // 24576 ; fin aliases after attention
#define KF_HI   86016      // 21504
#define LOGMW_O 107520
#define GOFF_O  107728
#define SMEM_BYTES 107936
#define VF_HI   0
#define CTX_OFF 24576
#define FIN_OFF 61440

// weight images (f16 hi only) in mma-B-fragment order: [w][chunk][12288]
__device__ __align__(16) __half g_Bimg[4][3][12288];

// ---------------- helpers ----------------
__device__ __forceinline__ void mma16816(float* c, const uint32_t* a, uint32_t b0, uint32_t b1) {
    asm volatile("mma.sync.aligned.m16n8k16.row.col.f32.f16.f16.f32 "
        "{%0,%1,%2,%3}, {%4,%5,%6,%7}, {%8,%9}, {%0,%1,%2,%3};"
        : "+f"(c[0]), "+f"(c[1]), "+f"(c[2]), "+f"(c[3])
        : "r"(a[0]), "r"(a[1]), "r"(a[2]), "r"(a[3]), "r"(b0), "r"(b1));
}
__device__ __forceinline__ uint32_t cvt2(float a, float b) {
    __half2 h2 = __float22half2_rn(make_float2(a, b));
    return *(uint32_t*)&h2;
}

// ---------------- prep: weights -> f16 fragment-order images (hi only) ----------------
__global__ void prep_w(const float* __restrict__ Wq, const float* __restrict__ Wk,
                       const float* __restrict__ Wv, const float* __restrict__ Wo)
{
    int e = blockIdx.x * 256 + threadIdx.x;
    if (e >= 4 * 36864) return;
    int wsel = e / 36864, r = e % 36864;
    int k = r / 192, n = r % 192;
    const float* W = (wsel == 0) ? Wq : (wsel == 1) ? Wk : (wsel == 2) ? Wv : Wo;
    __half h = __float2half_rn(W[k * 192 + n]);
    int chunk = k >> 6, kk = k & 63;
    int kt = kk >> 4, kc = kk & 15;
    int khi = kc >> 3, t = (kc & 7) >> 1, half = kc & 1;
    int ntile = n >> 3, g = n & 7;
    int lane = g * 4 + t;
    int off = ((kt * 24 + ntile) * 32 + lane) * 4 + khi * 2 + half;
    g_Bimg[wsel][chunk][off] = h;
}

// stage A element pair (hi only) into fragment-order image at base
__device__ __forceinline__ void stage_hi(char* smem, int base, int p, int c, float a0, float a1)
{
    uint32_t hi = cvt2(a0, a1);
    int mt = p >> 4, rr = p & 15;
    int g = rr & 7, hi8 = rr >> 3;
    int kt = c >> 4, cc = c & 15;
    int khi = cc >> 3, t = (cc & 7) >> 1;
    int reg = hi8 + 2 * khi;
    int off = (((kt * 4 + mt) * 32 + g * 4 + t) * 8 + reg * 2) * 2;
    *(uint32_t*)(smem + base + off) = hi;
}

// ---- 12-warp GEMM, 1-pass, 2mt x 4j per warp, 6 half-chunk stages.
// mode: 0 = fp32 dst (O), 1 = Q frags (scaled), 2 = K frags, 3 = VF frags (V)
__device__ void run_gemm(char* smem, const __half* img, int a_base,
                         float* __restrict__ dst, int tx, int mode, uint4* wreg)
{
    const int wid = tx >> 5, lane = tx & 31;
    const int mp = wid >= 6, jg = wid - 6 * mp;   // mp in {0,1}, jg in {0..5}
    const int g = lane >> 2, t = lane & 3;

    float c[2][4][4];
    #pragma unroll
    for (int m2 = 0; m2 < 2; m2++)
        #pragma unroll
        for (int jj = 0; jj < 4; jj++)
            #pragma unroll
            for (int i = 0; i < 4; i++) c[m2][jj][i] = 0.0f;

    for (int hs = 0; hs < 6; hs++) {
        __syncthreads();
        uint4* bb = (uint4*)(smem + B_OFF);
        #pragma unroll
        for (int i = 0; i < 2; i++) bb[tx + NTHR * i] = wreg[i];
        __syncthreads();
        if (hs < 5) {
            const uint4* nsrc = (const uint4*)(img + (hs + 1) * 6144);
            #pragma unroll
            for (int i = 0; i < 2; i++) wreg[i] = nsrc[tx + NTHR * i];
        }
        #pragma unroll
        for (int ktl = 0; ktl < 2; ktl++) {
            const int kt = hs * 2 + ktl;
            uint4 ah[2];
            #pragma unroll
            for (int m2 = 0; m2 < 2; m2++)
                ah[m2] = *(const uint4*)(smem + a_base + ((kt * 4 + 2 * mp + m2) * 32 + lane) * 16);
            #pragma unroll
            for (int jj = 0; jj < 4; jj++) {
                const int j = jg * 4 + jj;
                uint2 b = *(const uint2*)(smem + B_OFF + ((ktl * 24 + j) * 32 + lane) * 8);
                mma16816(c[0][jj], (const uint32_t*)&ah[0], b.x, b.y);
                mma16816(c[1][jj], (const uint32_t*)&ah[1], b.x, b.y);
            }
        }
    }
    __syncthreads();

    if (mode == 0) {
        #pragma unroll
        for (int m2 = 0; m2 < 2; m2++) {
            const int mt = 2 * mp + m2;
            const int r0 = mt * 16 + g, r1 = r0 + 8;
            #pragma unroll
            for (int jj = 0; jj < 4; jj++) {
                int col = (jg * 4 + jj) * 8 + 2 * t;
                if (r0 < NPIX) *(float2*)(dst + r0 * QSTRIDE + col) = make_float2(c[m2][jj][0], c[m2][jj][1]);
                if (r1 < NPIX) *(float2*)(dst + r1 * QSTRIDE + col) = make_float2(c[m2][jj][2], c[m2][jj][3]);
            }
        }
    } else if (mode == 1) {
        // Q: scale -> A-fragment image. h = jg; warp covers kb in {0,1}, khi = jj&1.
        const float SCALE = 0.17677669529663687f;
        #pragma unroll
        for (int m2 = 0; m2 < 2; m2++) {
            const int mt = 2 * mp + m2;
            #pragma unroll
            for (int kb = 0; kb < 2; kb++) {
                uint32_t w0 = cvt2(c[m2][2*kb][0]*SCALE,   c[m2][2*kb][1]*SCALE);
                uint32_t w1 = cvt2(c[m2][2*kb][2]*SCALE,   c[m2][2*kb][3]*SCALE);
                uint32_t w2 = cvt2(c[m2][2*kb+1][0]*SCALE, c[m2][2*kb+1][1]*SCALE);
                uint32_t w3 = cvt2(c[m2][2*kb+1][2]*SCALE, c[m2][2*kb+1][3]*SCALE);
                int off = (((jg * 4 + mt) * 2 + kb) * 32 + lane) * 16;
                *(uint4*)(smem + QF_HI + off) = make_uint4(w0, w1, w2, w3);
            }
        }
    } else if (mode == 2) {
        // K -> B-fragment image. h = jg, kb = jj>>1, khi = jj&1. Guard nt=2mt+1<7.
        #pragma unroll
        for (int m2 = 0; m2 < 2; m2++) {
            const int mt = 2 * mp + m2;
            #pragma unroll
            for (int jj = 0; jj < 4; jj++) {
                int kb = jj >> 1, khi = jj & 1;
                uint32_t h0 = cvt2(c[m2][jj][0], c[m2][jj][1]);
                uint32_t h1 = cvt2(c[m2][jj][2], c[m2][jj][3]);
                int base0 = (((jg * 2 + kb) * 7 + 2 * mt) * 32 + lane) * 8 + khi * 4;
                *(uint32_t*)(smem + KF_HI + base0) = h0;
                if (2 * mt + 1 < 7)
                    *(uint32_t*)(smem + KF_HI + base0 + 256) = h1;
            }
        }
    } else {
        // V: direct B-fragment store. Lane pairing rows (g, g^1) via shfl_xor lane^4.
        const int even = !(g & 1);
        const int tt = g >> 1;
        #pragma unroll
        for (int m2 = 0; m2 < 2; m2++) {
            const int mt = 2 * mp + m2;
            #pragma unroll
            for (int jj = 0; jj < 4; jj++) {
                int col = (jg * 4 + jj) * 8 + 2 * t;
                float p0 = __shfl_xor_sync(0xffffffffu, c[m2][jj][0], 4);
                float p1 = __shfl_xor_sync(0xffffffffu, c[m2][jj][1], 4);
                float p2 = __shfl_xor_sync(0xffffffffu, c[m2][jj][2], 4);
                float p3 = __shfl_xor_sync(0xffffffffu, c[m2][jj][3], 4);
                int m0 = 16 * mt + (even ? g : g - 1);
                float va0 = even ? c[m2][jj][0] : p1;
                float vb0 = even ? p0 : c[m2][jj][1];
                float va1 = even ? c[m2][jj][2] : p3;
                float vb1 = even ? p2 : c[m2][jj][3];
                va0 = (m0     < NPIX) ? va0 : 0.0f;
                vb0 = (m0 + 1 < NPIX) ? vb0 : 0.0f;
                va1 = (m0 + 8 < NPIX) ? va1 : 0.0f;
                vb1 = (m0 + 9 < NPIX) ? vb1 : 0.0f;
                int ch = col + (even ? 0 : 1);
                uint32_t h0 = cvt2(va0, vb0);
                uint32_t h1 = cvt2(va1, vb1);
                int hh = ch >> 5, nt2 = (ch >> 3) & 3, gg = ch & 7;
                int id = ((hh * 4 + mt) * 4 + nt2) * 32 + gg * 4 + tt;
                *(uint2*)(smem + VF_HI + id * 8) = make_uint2(h0, h1);
            }
        }
    }
}

__global__ __launch_bounds__(NTHR, 2)
void fused_winattn(const float* __restrict__ x, const float* __restrict__ y,
                   float* __restrict__ out, float* __restrict__ att_out)
{
    extern __shared__ __align__(16) char smem[];
    float* s_fin   = (float*)(smem + FIN_OFF);
    float* s_logmw = (float*)(smem + LOGMW_O);
    int*   s_goff  = (int*)(smem + GOFF_O);

    const int tx = threadIdx.x;
    const int wid = tx >> 5, lane = tx & 31;
    const int w  = blockIdx.x;
    const int b  = w >> 10;
    const int wr = (w >> 5) & 31;
    const int wc = w & 31;

    // ---- prefetch Q's B half-chunk 0 (hidden under gather) ----
    uint4 wreg[2];
    {
        const uint4* s0 = (const uint4*)&g_Bimg[0][0][0];
        wreg[0] = s0[tx];
        wreg[1] = s0[tx + NTHR];
    }

    // ---- gather x (roll + mask) AND y -> A-images; logmw, goff ----
    for (int p = wid; p < NPIX; p += 12) {
        int i = p / 7, j = p - i * 7;
        int hs = wr * 7 + i + 3;  if (hs >= HH) hs -= HH;
        int vs = wc * 7 + j + 3;  if (vs >= HH) vs -= HH;
        int goff = ((b * HH + hs) * HH + vs) * C_;
        float2 xv[3], yv[3];
        int cnt = 0;
        #pragma unroll
        for (int u = 0; u < 3; u++) {
            xv[u] = *(const float2*)(x + goff + 2 * lane + 64 * u);
            yv[u] = *(const float2*)(y + goff + 2 * lane + 64 * u);
            cnt += (xv[u].x > 0.95f ? 0 : 1) + (xv[u].y > 0.95f ? 0 : 1);
        }
        #pragma unroll
        for (int o = 16; o; o >>= 1) cnt += __shfl_xor_sync(0xffffffffu, cnt, o);
        float mask = (float)cnt * (1.0f / 192.0f);
        #pragma unroll
        for (int u = 0; u < 3; u++) {
            stage_hi(smem, IMG_X, p, 2 * lane + 64 * u, xv[u].x * mask, xv[u].y * mask);
            stage_hi(smem, IMG_Y, p, 2 * lane + 64 * u, yv[u].x, yv[u].y);
        }
        if (lane == 0) { s_logmw[p] = logf(mask + 1e-6f); s_goff[p] = goff; }
    }
    __syncthreads();

    // ---- GEMM q -> Q frags ----
    run_gemm(smem, &g_Bimg[0][0][0], IMG_X, nullptr, tx, 1, wreg);
    wreg[0] = ((const uint4*)&g_Bimg[1][0][0])[tx];
    wreg[1] = ((const uint4*)&g_Bimg[1][0][0])[tx + NTHR];

    // ---- GEMM k -> K frags ----
    run_gemm(smem, &g_Bimg[1][0][0], IMG_Y, nullptr, tx, 2, wreg);
    wreg[0] = ((const uint4*)&g_Bimg[2][0][0])[tx];
    wreg[1] = ((const uint4*)&g_Bimg[2][0][0])[tx + NTHR];

    // ---- GEMM v -> VF frags (into IMG_X region; x-image dead) ----
    run_gemm(smem, &g_Bimg[2][0][0], IMG_Y, nullptr, tx, 3, wreg);
    __syncthreads();

    // ---- fused logits (1-pass) -> register softmax -> att gmem -> att@v (1-pass) -> ctx frags ----
    {
        const int g = lane >> 2, t = lane & 3;
        for (int u = wid; u < 24; u += 12) {
            const int h = u >> 2, mt = u & 3;
            const int n0 = mt * 16 + g;
            uint4 qh0 = *(const uint4*)(smem + QF_HI + (((h * 4 + mt) * 2 + 0) * 32 + lane) * 16);
            uint4 qh1 = *(const uint4*)(smem + QF_HI + (((h * 4 + mt) * 2 + 1) * 32 + lane) * 16);
            float c[7][4];
            #pragma unroll
            for (int nt = 0; nt < 7; nt++) {
                uint2 bh0 = *(const uint2*)(smem + KF_HI + (((h * 2 + 0) * 7 + nt) * 32 + lane) * 8);
                uint2 bh1 = *(const uint2*)(smem + KF_HI + (((h * 2 + 1) * 7 + nt) * 32 + lane) * 8);
                c[nt][0] = c[nt][1] = c[nt][2] = c[nt][3] = 0.0f;
                mma16816(c[nt], (const uint32_t*)&qh0, bh0.x, bh0.y);
                mma16816(c[nt], (const uint32_t*)&qh1, bh1.x, bh1.y);
            }
            #pragma unroll
            for (int nt = 0; nt < 6; nt++) {
                float2 lm = *(const float2*)(s_logmw + 8 * nt + 2 * t);
                c[nt][0] += lm.x; c[nt][1] += lm.y;
                c[nt][2] += lm.x; c[nt][3] += lm.y;
            }
            {
                float lm48 = s_logmw[48];
                c[6][0] = (t == 0) ? c[6][0] + lm48 : -1e30f;
                c[6][2] = (t == 0) ? c[6][2] + lm48 : -1e30f;
                c[6][1] = -1e30f;  c[6][3] = -1e30f;
            }
            float mx0 = -1e30f, mx1 = -1e30f;
            #pragma unroll
            for (int nt = 0; nt < 7; nt++) {
                mx0 = fmaxf(mx0, fmaxf(c[nt][0], c[nt][1]));
                mx1 = fmaxf(mx1, fmaxf(c[nt][2], c[nt][3]));
            }
            mx0 = fmaxf(mx0, __shfl_xor_sync(0xffffffffu, mx0, 1));
            mx0 = fmaxf(mx0, __shfl_xor_sync(0xffffffffu, mx0, 2));
            mx1 = fmaxf(mx1, __shfl_xor_sync(0xffffffffu, mx1, 1));
            mx1 = fmaxf(mx1, __shfl_xor_sync(0xffffffffu, mx1, 2));
            float s0 = 0.0f, s1 = 0.0f;
            #pragma unroll
            for (int nt = 0; nt < 7; nt++) {
                c[nt][0] = __expf(c[nt][0] - mx0); s0 += c[nt][0];
                c[nt][1] = __expf(c[nt][1] - mx0); s0 += c[nt][1];
                c[nt][2] = __expf(c[nt][2] - mx1); s1 += c[nt][2];
                c[nt][3] = __expf(c[nt][3] - mx1); s1 += c[nt][3];
            }
            s0 += __shfl_xor_sync(0xffffffffu, s0, 1);
            s0 += __shfl_xor_sync(0xffffffffu, s0, 2);
            s1 += __shfl_xor_sync(0xffffffffu, s1, 1);
            s1 += __shfl_xor_sync(0xffffffffu, s1, 2);
            float inv0 = 1.0f / s0, inv1 = 1.0f / s1;
            #pragma unroll
            for (int nt = 0; nt < 7; nt++) {
                c[nt][0] *= inv0; c[nt][1] *= inv0;
                c[nt][2] *= inv1; c[nt][3] *= inv1;
            }
            {
                float* ab = att_out + (size_t)w * ATT_W + h * 2401;
                #pragma unroll
                for (int nt = 0; nt < 7; nt++) {
                    int m0 = 8 * nt + 2 * t;
                    if (n0 < NPIX) {
                        if (m0     < NPIX) ab[n0 * NPIX + m0]     = c[nt][0];
                        if (m0 + 1 < NPIX) ab[n0 * NPIX + m0 + 1] = c[nt][1];
                    }
                    if (n0 + 8 < NPIX) {
                        if (m0     < NPIX) ab[(n0 + 8) * NPIX + m0]     = c[nt][2];
                        if (m0 + 1 < NPIX) ab[(n0 + 8) * NPIX + m0 + 1] = c[nt][3];
                    }
                }
            }
            // att@v via mma (1-pass)
            float d[4][4];
            #pragma unroll
            for (int n2 = 0; n2 < 4; n2++)
                d[n2][0] = d[n2][1] = d[n2][2] = d[n2][3] = 0.0f;
            #pragma unroll
            for (int kt = 0; kt < 4; kt++) {
                uint32_t Ah[4];
                Ah[0] = cvt2(c[2*kt][0], c[2*kt][1]);
                Ah[1] = cvt2(c[2*kt][2], c[2*kt][3]);
                if (2 * kt + 1 < 7) {
                    Ah[2] = cvt2(c[2*kt+1][0], c[2*kt+1][1]);
                    Ah[3] = cvt2(c[2*kt+1][2], c[2*kt+1][3]);
                } else {
                    Ah[2] = Ah[3] = 0u;
                }
                #pragma unroll
                for (int n2 = 0; n2 < 4; n2++) {
                    uint2 bh = *(const uint2*)(smem + VF_HI + (((h * 4 + kt) * 4 + n2) * 32 + lane) * 8);
                    mma16816(d[n2], Ah, bh.x, bh.y);
                }
            }
            // ctx -> A-fragment image (hi only) for GEMM o
            #pragma unroll
            for (int n2 = 0; n2 < 4; n2++) {
                uint32_t h0 = cvt2(d[n2][0], d[n2][1]);
                uint32_t h1 = cvt2(d[n2][2], d[n2][3]);
                int kt_o = 2 * h + (n2 >> 1);
                int khi  = n2 & 1;
                int off  = ((kt_o * 4 + mt) * 32 + lane) * 16 + khi * 8;
                *(uint2*)(smem + CTX_OFF + off) = make_uint2(h0, h1);
            }
        }
    }
    __syncthreads();

    // ---- GEMM o (A = ctx frags) -> fp32 s_fin ----
    wreg[0] = ((const uint4*)&g_Bimg[3][0][0])[tx];
    wreg[1] = ((const uint4*)&g_Bimg[3][0][0])[tx + NTHR];
    run_gemm(smem, &g_Bimg[3][0][0], CTX_OFF, s_fin, tx, 0, wreg);
    __syncthreads();

    // ---- scatter out (roll-back == same index map) ----
    for (int idx = tx; idx < NPIX * 48; idx += NTHR) {
        int p  = idx / 48;
        int c4 = idx - p * 48;
        *(float4*)(out + s_goff[p] + 4 * c4) = *(const float4*)(s_fin + p * QSTRIDE + 4 * c4);
    }
}

extern "C" void kernel_launch(void* const* d_in, const int* in_sizes, int n_in,
                              void* d_out, int out_size)
{
    const float* x  = (const float*)d_in[0];
    const float* y  = (const float*)d_in[1];
    const float* Wq = (const float*)d_in[2];
    const float* Wk = (const float*)d_in[3];
    const float* Wv = (const float*)d_in[4];
    const float* Wo = (const float*)d_in[5];

    float* out = (float*)d_out;                       // [8,224,224,192]
    float* att = out + (size_t)8 * 224 * 224 * 192;   // [8192,6,49,49]

    prep_w<<<576, 256>>>(Wq, Wk, Wv, Wo);

    cudaFuncSetAttribute(fused_winattn,
                         cudaFuncAttributeMaxDynamicSharedMemorySize, SMEM_BYTES);
    fused_winattn<<<NWIN, NTHR, SMEM_BYTES>>>(x, y, out, att);
}